// round 1
// baseline (speedup 1.0000x reference)
#include <cuda_runtime.h>
#include <math.h>

#define BB   2
#define TTOK 2048
#define DDIM 1024
#define NH   16
#define HDIM 64
#define BT   (BB*TTOK)   // 4096

// ---------------- scratch (static device allocations; no cudaMalloc) ----------
__device__ float g_ln1[BT * DDIM];
__device__ float g_qkv[BT * 3 * DDIM];
__device__ float g_att[BT * DDIM];
__device__ float g_x1 [BT * DDIM];
__device__ float g_ln2[BT * DDIM];
__device__ float g_h  [BT * 4 * DDIM];

// ---------------- LayerNorm: one block per row, 256 threads, float4 -----------
__global__ void ln_kernel(const float* __restrict__ x, const float* __restrict__ g,
                          const float* __restrict__ b, float* __restrict__ o) {
    int row = blockIdx.x;
    int tid = threadIdx.x;
    const float4* xr = (const float4*)(x + (size_t)row * DDIM);
    float4 v = xr[tid];
    float s  = v.x + v.y + v.z + v.w;
    float ss = v.x*v.x + v.y*v.y + v.z*v.z + v.w*v.w;
    #pragma unroll
    for (int off = 16; off > 0; off >>= 1) {
        s  += __shfl_xor_sync(0xffffffffu, s,  off);
        ss += __shfl_xor_sync(0xffffffffu, ss, off);
    }
    __shared__ float rs[8], rss[8];
    int w = tid >> 5, ln = tid & 31;
    if (ln == 0) { rs[w] = s; rss[w] = ss; }
    __syncthreads();
    float tot = 0.f, tots = 0.f;
    #pragma unroll
    for (int i = 0; i < 8; i++) { tot += rs[i]; tots += rss[i]; }
    float mu  = tot * (1.0f / DDIM);
    float var = tots * (1.0f / DDIM) - mu * mu;
    float inv = rsqrtf(var + 1e-5f);
    float4 gg = ((const float4*)g)[tid];
    float4 bb = ((const float4*)b)[tid];
    float4 r;
    r.x = (v.x - mu) * inv * gg.x + bb.x;
    r.y = (v.y - mu) * inv * gg.y + bb.y;
    r.z = (v.z - mu) * inv * gg.z + bb.z;
    r.w = (v.w - mu) * inv * gg.w + bb.w;
    ((float4*)(o + (size_t)row * DDIM))[tid] = r;
}

// ---------------- GELU (tanh approximation, matches jax.nn.gelu default) ------
__device__ __forceinline__ float gelu_f(float x) {
    float x3 = x * x * x;
    return 0.5f * x * (1.0f + tanhf(0.7978845608028654f * (x + 0.044715f * x3)));
}

// ---------------- SGEMM: C = A[M,K] @ B[K,N] + bias, EPI: 0 none / 1 gelu / 2 +res
template<int EPI>
__global__ void __launch_bounds__(256) gemm_kernel(
    const float* __restrict__ A, const float* __restrict__ B,
    const float* __restrict__ bias, const float* __restrict__ res,
    float* __restrict__ C, int M, int N, int K)
{
    __shared__ float As[16 * 128];
    __shared__ float Bs[16 * 128];
    int tid = threadIdx.x;
    int bm = blockIdx.y << 7;
    int bn = blockIdx.x << 7;
    int rm = (tid >> 4) << 3;
    int rn = (tid & 15) << 3;

    float acc[8][8];
    #pragma unroll
    for (int i = 0; i < 8; i++)
        #pragma unroll
        for (int j = 0; j < 8; j++) acc[i][j] = 0.f;

    for (int k0 = 0; k0 < K; k0 += 16) {
        #pragma unroll
        for (int i = 0; i < 2; i++) {
            int f = tid + (i << 8);
            int ra = f >> 2, ca = (f & 3) << 2;
            float4 av = *(const float4*)(A + (size_t)(bm + ra) * K + k0 + ca);
            As[(ca + 0) * 128 + ra] = av.x;
            As[(ca + 1) * 128 + ra] = av.y;
            As[(ca + 2) * 128 + ra] = av.z;
            As[(ca + 3) * 128 + ra] = av.w;
            int rb = f >> 5, cb = (f & 31) << 2;
            *(float4*)&Bs[rb * 128 + cb] =
                *(const float4*)(B + (size_t)(k0 + rb) * N + bn + cb);
        }
        __syncthreads();
        #pragma unroll
        for (int k = 0; k < 16; k++) {
            float a[8], b[8];
            *(float4*)&a[0] = *(float4*)&As[k * 128 + rm];
            *(float4*)&a[4] = *(float4*)&As[k * 128 + rm + 4];
            *(float4*)&b[0] = *(float4*)&Bs[k * 128 + rn];
            *(float4*)&b[4] = *(float4*)&Bs[k * 128 + rn + 4];
            #pragma unroll
            for (int i = 0; i < 8; i++)
                #pragma unroll
                for (int j = 0; j < 8; j++)
                    acc[i][j] += a[i] * b[j];
        }
        __syncthreads();
    }

    #pragma unroll
    for (int i = 0; i < 8; i++) {
        size_t crow = (size_t)(bm + rm + i);
        #pragma unroll
        for (int j4 = 0; j4 < 8; j4 += 4) {
            float4 bv = *(const float4*)(bias + bn + rn + j4);
            float4 cv;
            cv.x = acc[i][j4 + 0] + bv.x;
            cv.y = acc[i][j4 + 1] + bv.y;
            cv.z = acc[i][j4 + 2] + bv.z;
            cv.w = acc[i][j4 + 3] + bv.w;
            if (EPI == 1) {
                cv.x = gelu_f(cv.x); cv.y = gelu_f(cv.y);
                cv.z = gelu_f(cv.z); cv.w = gelu_f(cv.w);
            }
            if (EPI == 2) {
                float4 rv = *(const float4*)(res + crow * N + bn + rn + j4);
                cv.x += rv.x; cv.y += rv.y; cv.z += rv.z; cv.w += rv.w;
            }
            *(float4*)(C + crow * N + bn + rn + j4) = cv;
        }
    }
}

// ---------------- Flash attention (fp32), BQ=BK=64, hd=64, causal -------------
// qkv: [BT, 3*D] rows; q at col h*64, k at D+h*64, v at 2D+h*64.
// smem: Qt[kk][qr] (64x68), Kt[kk][kr] (64x68), Pt[kv][qr] (64x68), Vs[kv][c] (64x64)
__global__ void __launch_bounds__(256) attn_kernel(const float* __restrict__ qkv,
                                                   float* __restrict__ out) {
    extern __shared__ float sm[];
    float* Qt = sm;                    // 64*68
    float* Kt = Qt + 64 * 68;
    float* Pt = Kt + 64 * 68;
    float* Vs = Pt + 64 * 68;          // 64*64

    int qt = (int)gridDim.x - 1 - (int)blockIdx.x;   // heavy tiles first
    int b  = blockIdx.y >> 4;
    int h  = blockIdx.y & 15;
    int tid = threadIdx.x;
    int tr = tid >> 4;      // 0..15 -> q rows tr*4..tr*4+3
    int tc = tid & 15;      // 0..15 -> cols   tc*4..tc*4+3

    const size_t TD3 = 3 * DDIM;
    size_t rowbase = (size_t)b * TTOK + (size_t)qt * 64;

    // load Q transposed: Qt[c][r]
    #pragma unroll
    for (int i = 0; i < 4; i++) {
        int f = tid + (i << 8);
        int r = f >> 4;
        int c4 = (f & 15) << 2;
        float4 v = *(const float4*)(qkv + (rowbase + r) * TD3 + h * HDIM + c4);
        Qt[(c4 + 0) * 68 + r] = v.x;
        Qt[(c4 + 1) * 68 + r] = v.y;
        Qt[(c4 + 2) * 68 + r] = v.z;
        Qt[(c4 + 3) * 68 + r] = v.w;
    }

    float m_[4], l_[4], O_[4][4];
    #pragma unroll
    for (int a = 0; a < 4; a++) {
        m_[a] = -1e30f; l_[a] = 0.f;
        #pragma unroll
        for (int c = 0; c < 4; c++) O_[a][c] = 0.f;
    }

    for (int jt = 0; jt <= qt; jt++) {
        // load K (transposed) and V
        #pragma unroll
        for (int i = 0; i < 4; i++) {
            int f = tid + (i << 8);
            int r = f >> 4;
            int c4 = (f & 15) << 2;
            size_t kvrow = ((size_t)b * TTOK + (size_t)jt * 64 + r) * TD3 + h * HDIM + c4;
            float4 kv = *(const float4*)(qkv + kvrow + DDIM);
            Kt[(c4 + 0) * 68 + r] = kv.x;
            Kt[(c4 + 1) * 68 + r] = kv.y;
            Kt[(c4 + 2) * 68 + r] = kv.z;
            Kt[(c4 + 3) * 68 + r] = kv.w;
            *(float4*)&Vs[r * 64 + c4] = *(const float4*)(qkv + kvrow + 2 * DDIM);
        }
        __syncthreads();

        // S = Q K^T (scaled later)
        float s[4][4];
        #pragma unroll
        for (int a = 0; a < 4; a++)
            #pragma unroll
            for (int c = 0; c < 4; c++) s[a][c] = 0.f;
        #pragma unroll 16
        for (int kk = 0; kk < 64; kk++) {
            float4 q4 = *(const float4*)&Qt[kk * 68 + (tr << 2)];
            float4 k4 = *(const float4*)&Kt[kk * 68 + (tc << 2)];
            float qa[4] = {q4.x, q4.y, q4.z, q4.w};
            float ka[4] = {k4.x, k4.y, k4.z, k4.w};
            #pragma unroll
            for (int a = 0; a < 4; a++)
                #pragma unroll
                for (int c = 0; c < 4; c++)
                    s[a][c] += qa[a] * ka[c];
        }

        // online softmax (rows shared by 16 threads with same tr; lanes aligned)
        #pragma unroll
        for (int a = 0; a < 4; a++) {
            #pragma unroll
            for (int c = 0; c < 4; c++) {
                s[a][c] *= 0.125f;  // 1/sqrt(64)
                if (jt == qt && ((tc << 2) + c) > ((tr << 2) + a)) s[a][c] = -1e30f;
            }
            float mi = fmaxf(fmaxf(s[a][0], s[a][1]), fmaxf(s[a][2], s[a][3]));
            #pragma unroll
            for (int off = 8; off > 0; off >>= 1)
                mi = fmaxf(mi, __shfl_xor_sync(0xffffffffu, mi, off, 16));
            float mn = fmaxf(m_[a], mi);
            float alpha = __expf(m_[a] - mn);
            float p[4], rsum = 0.f;
            #pragma unroll
            for (int c = 0; c < 4; c++) { p[c] = __expf(s[a][c] - mn); rsum += p[c]; }
            #pragma unroll
            for (int off = 8; off > 0; off >>= 1)
                rsum += __shfl_xor_sync(0xffffffffu, rsum, off, 16);
            l_[a] = l_[a] * alpha + rsum;
            m_[a] = mn;
            #pragma unroll
            for (int c = 0; c < 4; c++) {
                O_[a][c] *= alpha;
                Pt[((tc << 2) + c) * 68 + (tr << 2) + a] = p[c];
            }
        }
        __syncthreads();

        // O += P V
        #pragma unroll 16
        for (int kv = 0; kv < 64; kv++) {
            float4 p4 = *(const float4*)&Pt[kv * 68 + (tr << 2)];
            float4 v4 = *(const float4*)&Vs[kv * 64 + (tc << 2)];
            float pa[4] = {p4.x, p4.y, p4.z, p4.w};
            float va[4] = {v4.x, v4.y, v4.z, v4.w};
            #pragma unroll
            for (int a = 0; a < 4; a++)
                #pragma unroll
                for (int c = 0; c < 4; c++)
                    O_[a][c] += pa[a] * va[c];
        }
        __syncthreads();
    }

    #pragma unroll
    for (int a = 0; a < 4; a++) {
        float inv = 1.0f / l_[a];
        float4 r;
        r.x = O_[a][0] * inv; r.y = O_[a][1] * inv;
        r.z = O_[a][2] * inv; r.w = O_[a][3] * inv;
        *(float4*)(out + (rowbase + (tr << 2) + a) * DDIM + h * HDIM + (tc << 2)) = r;
    }
}

// ---------------- launch ------------------------------------------------------
extern "C" void kernel_launch(void* const* d_in, const int* in_sizes, int n_in,
                              void* d_out, int out_size) {
    const float* x      = (const float*)d_in[0];
    const float* ln1_g  = (const float*)d_in[1];
    const float* ln1_b  = (const float*)d_in[2];
    const float* ln2_g  = (const float*)d_in[3];
    const float* ln2_b  = (const float*)d_in[4];
    const float* w_qkv  = (const float*)d_in[5];
    const float* b_qkv  = (const float*)d_in[6];
    const float* w_o    = (const float*)d_in[7];
    const float* b_o    = (const float*)d_in[8];
    const float* w_fc1  = (const float*)d_in[9];
    const float* b_fc1  = (const float*)d_in[10];
    const float* w_fc2  = (const float*)d_in[11];
    const float* b_fc2  = (const float*)d_in[12];
    float* out = (float*)d_out;

    float *p_ln1, *p_qkv, *p_att, *p_x1, *p_ln2, *p_h;
    cudaGetSymbolAddress((void**)&p_ln1, g_ln1);
    cudaGetSymbolAddress((void**)&p_qkv, g_qkv);
    cudaGetSymbolAddress((void**)&p_att, g_att);
    cudaGetSymbolAddress((void**)&p_x1,  g_x1);
    cudaGetSymbolAddress((void**)&p_ln2, g_ln2);
    cudaGetSymbolAddress((void**)&p_h,   g_h);

    const int attn_smem = (3 * 64 * 68 + 64 * 64) * (int)sizeof(float);  // 68608
    cudaFuncSetAttribute(attn_kernel, cudaFuncAttributeMaxDynamicSharedMemorySize, attn_smem);

    // 1) LN1
    ln_kernel<<<BT, 256>>>(x, ln1_g, ln1_b, p_ln1);
    // 2) QKV GEMM: [4096,1024] @ [1024,3072]
    gemm_kernel<0><<<dim3(3 * DDIM / 128, BT / 128), 256>>>(
        p_ln1, w_qkv, b_qkv, nullptr, p_qkv, BT, 3 * DDIM, DDIM);
    // 3) attention
    attn_kernel<<<dim3(TTOK / 64, BB * NH), 256, attn_smem>>>(p_qkv, p_att);
    // 4) output proj + residual(x)
    gemm_kernel<2><<<dim3(DDIM / 128, BT / 128), 256>>>(
        p_att, w_o, b_o, x, p_x1, BT, DDIM, DDIM);
    // 5) LN2
    ln_kernel<<<BT, 256>>>(p_x1, ln2_g, ln2_b, p_ln2);
    // 6) fc1 + GELU: [4096,1024] @ [1024,4096]
    gemm_kernel<1><<<dim3(4 * DDIM / 128, BT / 128), 256>>>(
        p_ln2, w_fc1, b_fc1, nullptr, p_h, BT, 4 * DDIM, DDIM);
    // 7) fc2 + residual(x1) -> out: [4096,4096] @ [4096,1024]
    gemm_kernel<2><<<dim3(DDIM / 128, BT / 128), 256>>>(
        p_h, w_fc2, b_fc2, p_x1, out, BT, DDIM, 4 * DDIM);
}

// round 3
// speedup vs baseline: 1.7540x; 1.7540x over previous
#include <cuda_runtime.h>
#include <cuda_bf16.h>
#include <math.h>
#include <stdint.h>

#define BB   2
#define TTOK 2048
#define DDIM 1024
#define NH   16
#define HDIM 64
#define BT   (BB*TTOK)   // 4096

// ------------------------- scratch (static device arrays) --------------------
__device__ float g_qkv[BT * 3 * DDIM];            // fp32 qkv for attention
__device__ float g_x1 [BT * DDIM];                // fp32 residual stream after attn
__device__ __nv_bfloat16 g_ah[BT * DDIM];         // activation split hi
__device__ __nv_bfloat16 g_al[BT * DDIM];         // activation split lo
__device__ __nv_bfloat16 g_hh[BT * 4 * DDIM];     // gelu(h) split hi
__device__ __nv_bfloat16 g_hl[BT * 4 * DDIM];     // gelu(h) split lo
__device__ __nv_bfloat16 g_wq_h[3 * DDIM * DDIM], g_wq_l[3 * DDIM * DDIM];
__device__ __nv_bfloat16 g_wo_h[DDIM * DDIM],     g_wo_l[DDIM * DDIM];
__device__ __nv_bfloat16 g_w1_h[4 * DDIM * DDIM], g_w1_l[4 * DDIM * DDIM];
__device__ __nv_bfloat16 g_w2_h[4 * DDIM * DDIM], g_w2_l[4 * DDIM * DDIM];

// ------------------------- PTX helpers ---------------------------------------
__device__ __forceinline__ uint32_t s2u(const void* p) {
    uint32_t a;
    asm("{ .reg .u64 t; cvta.to.shared.u64 t, %1; cvt.u32.u64 %0, t; }" : "=r"(a) : "l"(p));
    return a;
}
__device__ __forceinline__ void cp16(uint32_t dst, const void* src) {
    asm volatile("cp.async.cg.shared.global [%0], [%1], 16;" :: "r"(dst), "l"(src));
}
#define CP_COMMIT() asm volatile("cp.async.commit_group;" ::: "memory")
#define CP_WAIT2()  asm volatile("cp.async.wait_group 2;" ::: "memory")

__device__ __forceinline__ void ldsm4(uint32_t* r, uint32_t addr) {
    asm volatile("ldmatrix.sync.aligned.m8n8.x4.shared.b16 {%0,%1,%2,%3}, [%4];"
                 : "=r"(r[0]), "=r"(r[1]), "=r"(r[2]), "=r"(r[3]) : "r"(addr));
}
__device__ __forceinline__ void mma_bf16(float* c, const uint32_t* a,
                                         uint32_t b0, uint32_t b1) {
    asm volatile(
        "mma.sync.aligned.m16n8k16.row.col.f32.bf16.bf16.f32 "
        "{%0,%1,%2,%3}, {%4,%5,%6,%7}, {%8,%9}, {%0,%1,%2,%3};"
        : "+f"(c[0]), "+f"(c[1]), "+f"(c[2]), "+f"(c[3])
        : "r"(a[0]), "r"(a[1]), "r"(a[2]), "r"(a[3]), "r"(b0), "r"(b1));
}

__device__ __forceinline__ float gelu_f(float x) {
    float x3 = x * x * x;
    return 0.5f * x * (1.0f + tanhf(0.7978845608028654f * (x + 0.044715f * x3)));
}
__device__ __forceinline__ void split_bf16(float v, __nv_bfloat16& h, __nv_bfloat16& l) {
    h = __float2bfloat16(v);
    l = __float2bfloat16(v - __bfloat162float(h));
}

// ------------------------- weight transpose + bf16 split ---------------------
__global__ void wsplit_t(const float* __restrict__ W,
                         __nv_bfloat16* __restrict__ Oh, __nv_bfloat16* __restrict__ Ol,
                         int K, int N) {
    __shared__ float t[32][33];
    int nx = blockIdx.x * 32, kx = blockIdx.y * 32;
    int tx = threadIdx.x, ty = threadIdx.y;  // 32 x 8
    #pragma unroll
    for (int i = 0; i < 32; i += 8)
        t[ty + i][tx] = W[(size_t)(kx + ty + i) * N + nx + tx];
    __syncthreads();
    #pragma unroll
    for (int i = 0; i < 32; i += 8) {
        float v = t[tx][ty + i];
        __nv_bfloat16 h, l; split_bf16(v, h, l);
        size_t oi = (size_t)(nx + ty + i) * K + kx + tx;
        Oh[oi] = h; Ol[oi] = l;
    }
}

// ------------------------- LayerNorm -> split bf16 ---------------------------
__global__ void ln_split(const float* __restrict__ x, const float* __restrict__ g,
                         const float* __restrict__ b,
                         __nv_bfloat16* __restrict__ oh, __nv_bfloat16* __restrict__ ol) {
    int row = blockIdx.x;
    int tid = threadIdx.x;
    float4 v = ((const float4*)(x + (size_t)row * DDIM))[tid];
    float s  = v.x + v.y + v.z + v.w;
    float ss = v.x*v.x + v.y*v.y + v.z*v.z + v.w*v.w;
    #pragma unroll
    for (int off = 16; off > 0; off >>= 1) {
        s  += __shfl_xor_sync(0xffffffffu, s,  off);
        ss += __shfl_xor_sync(0xffffffffu, ss, off);
    }
    __shared__ float rs[8], rss[8];
    int w = tid >> 5, ln = tid & 31;
    if (ln == 0) { rs[w] = s; rss[w] = ss; }
    __syncthreads();
    float tot = 0.f, tots = 0.f;
    #pragma unroll
    for (int i = 0; i < 8; i++) { tot += rs[i]; tots += rss[i]; }
    float mu  = tot * (1.0f / DDIM);
    float var = tots * (1.0f / DDIM) - mu * mu;
    float inv = rsqrtf(var + 1e-5f);
    float4 gg = ((const float4*)g)[tid];
    float4 bb = ((const float4*)b)[tid];
    float r0 = (v.x - mu) * inv * gg.x + bb.x;
    float r1 = (v.y - mu) * inv * gg.y + bb.y;
    float r2 = (v.z - mu) * inv * gg.z + bb.z;
    float r3 = (v.w - mu) * inv * gg.w + bb.w;
    __nv_bfloat16 h0,h1,h2,h3,l0,l1,l2,l3;
    split_bf16(r0,h0,l0); split_bf16(r1,h1,l1); split_bf16(r2,h2,l2); split_bf16(r3,h3,l3);
    size_t base = (size_t)row * DDIM + tid * 4;
    __nv_bfloat162 a01; a01.x = h0; a01.y = h1;
    __nv_bfloat162 a23; a23.x = h2; a23.y = h3;
    __nv_bfloat162 b01; b01.x = l0; b01.y = l1;
    __nv_bfloat162 b23; b23.x = l2; b23.y = l3;
    *(__nv_bfloat162*)(oh + base)     = a01;
    *(__nv_bfloat162*)(oh + base + 2) = a23;
    *(__nv_bfloat162*)(ol + base)     = b01;
    *(__nv_bfloat162*)(ol + base + 2) = b23;
}

// ------------------------- HMMA split-bf16 GEMM ------------------------------
// C[M,N] = (Ah+Al)[M,K] @ (Bh+Bl)[N,K]^T + bias. EPI: 0 plain / 1 gelu-split / 2 +res
// Block 128x128, 8 warps (2x4), warp tile 64x32, K-chunk 32, 3-stage cp.async.
#define ROWB   80                    // 40 bf16 per smem row (32 data + 8 pad)
#define OFF_AH 0
#define OFF_AL 10240
#define OFF_BH 20480
#define OFF_BL 30720
#define STG    40960
#define GEMM_SMEM (3 * STG)

__device__ __forceinline__ void load_stage(
    uint32_t st,
    const __nv_bfloat16* __restrict__ Ah, const __nv_bfloat16* __restrict__ Al,
    const __nv_bfloat16* __restrict__ Bh, const __nv_bfloat16* __restrict__ Bl,
    int K, int bm, int bn, int k0, int tid)
{
    #pragma unroll
    for (int j = 0; j < 2; j++) {
        int o = tid + (j << 8);        // 0..511
        int r = o >> 2, c = o & 3;     // 128 rows x 4 chunks of 16B
        size_t ga = (size_t)(bm + r) * K + k0 + (c << 3);
        size_t gb = (size_t)(bn + r) * K + k0 + (c << 3);
        uint32_t so = (uint32_t)(r * ROWB + (c << 4));
        cp16(st + OFF_AH + so, Ah + ga);
        cp16(st + OFF_AL + so, Al + ga);
        cp16(st + OFF_BH + so, Bh + gb);
        cp16(st + OFF_BL + so, Bl + gb);
    }
}

template<int EPI>
__global__ void __launch_bounds__(256, 1) hmma_gemm(
    const __nv_bfloat16* __restrict__ Ah, const __nv_bfloat16* __restrict__ Al,
    const __nv_bfloat16* __restrict__ Bh, const __nv_bfloat16* __restrict__ Bl,
    const float* __restrict__ bias, const float* __restrict__ res,
    float* __restrict__ Cf, __nv_bfloat16* __restrict__ Ch, __nv_bfloat16* __restrict__ Cl,
    int N, int K)
{
    extern __shared__ __align__(1024) char smem[];
    uint32_t sb = s2u(smem);
    int tid = threadIdx.x, wid = tid >> 5, lane = tid & 31;
    int wm = wid & 1, wn = wid >> 1;            // warp grid 2(M) x 4(N)
    int bm = blockIdx.y << 7, bn = blockIdx.x << 7;

    float acc[4][4][4];
    #pragma unroll
    for (int mi = 0; mi < 4; mi++)
        #pragma unroll
        for (int ni = 0; ni < 4; ni++)
            #pragma unroll
            for (int e = 0; e < 4; e++) acc[mi][ni][e] = 0.f;

    int nch = K >> 5;
    load_stage(sb, Ah, Al, Bh, Bl, K, bm, bn, 0, tid);
    CP_COMMIT();
    load_stage(sb + STG, Ah, Al, Bh, Bl, K, bm, bn, 32, tid);
    CP_COMMIT();

    // per-lane ldmatrix address components
    int arow = lane & 15;
    int acol = (lane >> 4) << 3;                 // 0 or 8
    int bg   = lane >> 3;                        // 0..3 (matrix select)
    int brow = lane & 7;

    for (int i = 0; i < nch; i++) {
        if (i + 2 < nch) {
            load_stage(sb + (uint32_t)((i + 2) % 3) * STG,
                       Ah, Al, Bh, Bl, K, bm, bn, (i + 2) << 5, tid);
        }
        CP_COMMIT();
        CP_WAIT2();
        __syncthreads();

        uint32_t st = sb + (uint32_t)(i % 3) * STG;
        #pragma unroll
        for (int ks = 0; ks < 2; ks++) {
            uint32_t aH[4][4], aL[4][4];
            #pragma unroll
            for (int mi = 0; mi < 4; mi++) {
                uint32_t off = (uint32_t)(((wm << 6) + (mi << 4) + arow) * ROWB
                                          + ((ks << 4) + acol) * 2);
                ldsm4(aH[mi], st + OFF_AH + off);
                ldsm4(aL[mi], st + OFF_AL + off);
            }
            uint32_t bH[4][2], bL[4][2];
            #pragma unroll
            for (int np = 0; np < 2; np++) {
                uint32_t off = (uint32_t)(((wn << 5) + (np << 4) + ((bg >> 1) << 3) + brow) * ROWB
                                          + ((ks << 4) + ((bg & 1) << 3)) * 2);
                uint32_t r[4];
                ldsm4(r, st + OFF_BH + off);
                bH[2*np][0] = r[0]; bH[2*np][1] = r[1];
                bH[2*np+1][0] = r[2]; bH[2*np+1][1] = r[3];
                ldsm4(r, st + OFF_BL + off);
                bL[2*np][0] = r[0]; bL[2*np][1] = r[1];
                bL[2*np+1][0] = r[2]; bL[2*np+1][1] = r[3];
            }
            #pragma unroll
            for (int mi = 0; mi < 4; mi++)
                #pragma unroll
                for (int ni = 0; ni < 4; ni++) {
                    mma_bf16(acc[mi][ni], aH[mi], bH[ni][0], bH[ni][1]);
                    mma_bf16(acc[mi][ni], aH[mi], bL[ni][0], bL[ni][1]);
                    mma_bf16(acc[mi][ni], aL[mi], bH[ni][0], bH[ni][1]);
                }
        }
        __syncthreads();
    }

    // ---- epilogue ----
    #pragma unroll
    for (int mi = 0; mi < 4; mi++) {
        #pragma unroll
        for (int ni = 0; ni < 4; ni++) {
            int row0 = bm + (wm << 6) + (mi << 4) + (lane >> 2);
            int col  = bn + (wn << 5) + (ni << 3) + ((lane & 3) << 1);
            float b0 = __ldg(bias + col), b1 = __ldg(bias + col + 1);
            #pragma unroll
            for (int half = 0; half < 2; half++) {
                int row = row0 + half * 8;
                float v0 = acc[mi][ni][half * 2 + 0] + b0;
                float v1 = acc[mi][ni][half * 2 + 1] + b1;
                size_t oi = (size_t)row * N + col;
                if (EPI == 0) {
                    float2 ov; ov.x = v0; ov.y = v1;
                    *(float2*)(Cf + oi) = ov;
                } else if (EPI == 2) {
                    float2 rv = *(const float2*)(res + oi);
                    float2 ov; ov.x = v0 + rv.x; ov.y = v1 + rv.y;
                    *(float2*)(Cf + oi) = ov;
                } else {
                    float a0 = gelu_f(v0), a1 = gelu_f(v1);
                    __nv_bfloat16 h0, h1, l0, l1;
                    split_bf16(a0, h0, l0); split_bf16(a1, h1, l1);
                    __nv_bfloat162 hh; hh.x = h0; hh.y = h1;
                    __nv_bfloat162 ll; ll.x = l0; ll.y = l1;
                    *(__nv_bfloat162*)(Ch + oi) = hh;
                    *(__nv_bfloat162*)(Cl + oi) = ll;
                }
            }
        }
    }
}

// ------------------------- Flash attention (fp32) -> split bf16 out ----------
__global__ void __launch_bounds__(256) attn_kernel(const float* __restrict__ qkv,
                                                   __nv_bfloat16* __restrict__ out_h,
                                                   __nv_bfloat16* __restrict__ out_l) {
    extern __shared__ float sm[];
    float* Qt = sm;
    float* Kt = Qt + 64 * 68;
    float* Pt = Kt + 64 * 68;
    float* Vs = Pt + 64 * 68;

    int qt = (int)gridDim.x - 1 - (int)blockIdx.x;
    int b  = blockIdx.y >> 4;
    int h  = blockIdx.y & 15;
    int tid = threadIdx.x;
    int tr = tid >> 4;
    int tc = tid & 15;

    const size_t TD3 = 3 * DDIM;
    size_t rowbase = (size_t)b * TTOK + (size_t)qt * 64;

    #pragma unroll
    for (int i = 0; i < 4; i++) {
        int f = tid + (i << 8);
        int r = f >> 4;
        int c4 = (f & 15) << 2;
        float4 v = *(const float4*)(qkv + (rowbase + r) * TD3 + h * HDIM + c4);
        Qt[(c4 + 0) * 68 + r] = v.x;
        Qt[(c4 + 1) * 68 + r] = v.y;
        Qt[(c4 + 2) * 68 + r] = v.z;
        Qt[(c4 + 3) * 68 + r] = v.w;
    }

    float m_[4], l_[4], O_[4][4];
    #pragma unroll
    for (int a = 0; a < 4; a++) {
        m_[a] = -1e30f; l_[a] = 0.f;
        #pragma unroll
        for (int c = 0; c < 4; c++) O_[a][c] = 0.f;
    }

    for (int jt = 0; jt <= qt; jt++) {
        #pragma unroll
        for (int i = 0; i < 4; i++) {
            int f = tid + (i << 8);
            int r = f >> 4;
            int c4 = (f & 15) << 2;
            size_t kvrow = ((size_t)b * TTOK + (size_t)jt * 64 + r) * TD3 + h * HDIM + c4;
            float4 kv = *(const float4*)(qkv + kvrow + DDIM);
            Kt[(c4 + 0) * 68 + r] = kv.x;
            Kt[(c4 + 1) * 68 + r] = kv.y;
            Kt[(c4 + 2) * 68 + r] = kv.z;
            Kt[(c4 + 3) * 68 + r] = kv.w;
            *(float4*)&Vs[r * 64 + c4] = *(const float4*)(qkv + kvrow + 2 * DDIM);
        }
        __syncthreads();

        float s[4][4];
        #pragma unroll
        for (int a = 0; a < 4; a++)
            #pragma unroll
            for (int c = 0; c < 4; c++) s[a][c] = 0.f;
        #pragma unroll 16
        for (int kk = 0; kk < 64; kk++) {
            float4 q4 = *(const float4*)&Qt[kk * 68 + (tr << 2)];
            float4 k4 = *(const float4*)&Kt[kk * 68 + (tc << 2)];
            float qa[4] = {q4.x, q4.y, q4.z, q4.w};
            float ka[4] = {k4.x, k4.y, k4.z, k4.w};
            #pragma unroll
            for (int a = 0; a < 4; a++)
                #pragma unroll
                for (int c = 0; c < 4; c++)
                    s[a][c] += qa[a] * ka[c];
        }

        #pragma unroll
        for (int a = 0; a < 4; a++) {
            #pragma unroll
            for (int c = 0; c < 4; c++) {
                s[a][c] *= 0.125f;
                if (jt == qt && ((tc << 2) + c) > ((tr << 2) + a)) s[a][c] = -1e30f;
            }
            float mi = fmaxf(fmaxf(s[a][0], s[a][1]), fmaxf(s[a][2], s[a][3]));
            #pragma unroll
            for (int off = 8; off > 0; off >>= 1)
                mi = fmaxf(mi, __shfl_xor_sync(0xffffffffu, mi, off, 16));
            float mn = fmaxf(m_[a], mi);
            float alpha = __expf(m_[a] - mn);
            float p[4], rsum = 0.f;
            #pragma unroll
            for (int c = 0; c < 4; c++) { p[c] = __expf(s[a][c] - mn); rsum += p[c]; }
            #pragma unroll
            for (int off = 8; off > 0; off >>= 1)
                rsum += __shfl_xor_sync(0xffffffffu, rsum, off, 16);
            l_[a] = l_[a] * alpha + rsum;
            m_[a] = mn;
            #pragma unroll
            for (int c = 0; c < 4; c++) {
                O_[a][c] *= alpha;
                Pt[((tc << 2) + c) * 68 + (tr << 2) + a] = p[c];
            }
        }
        __syncthreads();

        #pragma unroll 16
        for (int kv = 0; kv < 64; kv++) {
            float4 p4 = *(const float4*)&Pt[kv * 68 + (tr << 2)];
            float4 v4 = *(const float4*)&Vs[kv * 64 + (tc << 2)];
            float pa[4] = {p4.x, p4.y, p4.z, p4.w};
            float va[4] = {v4.x, v4.y, v4.z, v4.w};
            #pragma unroll
            for (int a = 0; a < 4; a++)
                #pragma unroll
                for (int c = 0; c < 4; c++)
                    O_[a][c] += pa[a] * va[c];
        }
        __syncthreads();
    }

    #pragma unroll
    for (int a = 0; a < 4; a++) {
        float inv = 1.0f / l_[a];
        float o0 = O_[a][0] * inv, o1 = O_[a][1] * inv;
        float o2 = O_[a][2] * inv, o3 = O_[a][3] * inv;
        __nv_bfloat16 h0,h1,h2,h3,l0,l1,l2,l3;
        split_bf16(o0,h0,l0); split_bf16(o1,h1,l1);
        split_bf16(o2,h2,l2); split_bf16(o3,h3,l3);
        size_t idx = (rowbase + (tr << 2) + a) * DDIM + h * HDIM + (tc << 2);
        __nv_bfloat162 hh0; hh0.x = h0; hh0.y = h1;
        __nv_bfloat162 hh1; hh1.x = h2; hh1.y = h3;
        __nv_bfloat162 ll0; ll0.x = l0; ll0.y = l1;
        __nv_bfloat162 ll1; ll1.x = l2; ll1.y = l3;
        *(__nv_bfloat162*)(out_h + idx)     = hh0;
        *(__nv_bfloat162*)(out_h + idx + 2) = hh1;
        *(__nv_bfloat162*)(out_l + idx)     = ll0;
        *(__nv_bfloat162*)(out_l + idx + 2) = ll1;
    }
}

// ------------------------- launch --------------------------------------------
extern "C" void kernel_launch(void* const* d_in, const int* in_sizes, int n_in,
                              void* d_out, int out_size) {
    const float* x      = (const float*)d_in[0];
    const float* ln1_g  = (const float*)d_in[1];
    const float* ln1_b  = (const float*)d_in[2];
    const float* ln2_g  = (const float*)d_in[3];
    const float* ln2_b  = (const float*)d_in[4];
    const float* w_qkv  = (const float*)d_in[5];
    const float* b_qkv  = (const float*)d_in[6];
    const float* w_o    = (const float*)d_in[7];
    const float* b_o    = (const float*)d_in[8];
    const float* w_fc1  = (const float*)d_in[9];
    const float* b_fc1  = (const float*)d_in[10];
    const float* w_fc2  = (const float*)d_in[11];
    const float* b_fc2  = (const float*)d_in[12];
    float* out = (float*)d_out;

    float *p_qkv, *p_x1;
    __nv_bfloat16 *p_ah, *p_al, *p_hh, *p_hl;
    __nv_bfloat16 *p_wqh, *p_wql, *p_woh, *p_wol, *p_w1h, *p_w1l, *p_w2h, *p_w2l;
    cudaGetSymbolAddress((void**)&p_qkv, g_qkv);
    cudaGetSymbolAddress((void**)&p_x1,  g_x1);
    cudaGetSymbolAddress((void**)&p_ah,  g_ah);
    cudaGetSymbolAddress((void**)&p_al,  g_al);
    cudaGetSymbolAddress((void**)&p_hh,  g_hh);
    cudaGetSymbolAddress((void**)&p_hl,  g_hl);
    cudaGetSymbolAddress((void**)&p_wqh, g_wq_h);
    cudaGetSymbolAddress((void**)&p_wql, g_wq_l);
    cudaGetSymbolAddress((void**)&p_woh, g_wo_h);
    cudaGetSymbolAddress((void**)&p_wol, g_wo_l);
    cudaGetSymbolAddress((void**)&p_w1h, g_w1_h);
    cudaGetSymbolAddress((void**)&p_w1l, g_w1_l);
    cudaGetSymbolAddress((void**)&p_w2h, g_w2_h);
    cudaGetSymbolAddress((void**)&p_w2l, g_w2_l);

    const int attn_smem = (3 * 64 * 68 + 64 * 64) * (int)sizeof(float);
    cudaFuncSetAttribute(attn_kernel, cudaFuncAttributeMaxDynamicSharedMemorySize, attn_smem);
    cudaFuncSetAttribute(hmma_gemm<0>, cudaFuncAttributeMaxDynamicSharedMemorySize, GEMM_SMEM);
    cudaFuncSetAttribute(hmma_gemm<1>, cudaFuncAttributeMaxDynamicSharedMemorySize, GEMM_SMEM);
    cudaFuncSetAttribute(hmma_gemm<2>, cudaFuncAttributeMaxDynamicSharedMemorySize, GEMM_SMEM);

    dim3 wblk(32, 8);
    wsplit_t<<<dim3(3 * DDIM / 32, DDIM / 32), wblk>>>(w_qkv, p_wqh, p_wql, DDIM, 3 * DDIM);
    wsplit_t<<<dim3(DDIM / 32, DDIM / 32), wblk>>>(w_o, p_woh, p_wol, DDIM, DDIM);
    wsplit_t<<<dim3(4 * DDIM / 32, DDIM / 32), wblk>>>(w_fc1, p_w1h, p_w1l, DDIM, 4 * DDIM);
    wsplit_t<<<dim3(DDIM / 32, 4 * DDIM / 32), wblk>>>(w_fc2, p_w2h, p_w2l, 4 * DDIM, DDIM);

    // 1) LN1 -> split
    ln_split<<<BT, 256>>>(x, ln1_g, ln1_b, p_ah, p_al);
    // 2) QKV GEMM -> fp32 qkv
    hmma_gemm<0><<<dim3(3 * DDIM / 128, BT / 128), 256, GEMM_SMEM>>>(
        p_ah, p_al, p_wqh, p_wql, b_qkv, nullptr, p_qkv, nullptr, nullptr, 3 * DDIM, DDIM);
    // 3) attention -> split att
    attn_kernel<<<dim3(TTOK / 64, BB * NH), 256, attn_smem>>>(p_qkv, p_ah, p_al);
    // 4) O-proj + residual(x) -> x1 fp32
    hmma_gemm<2><<<dim3(DDIM / 128, BT / 128), 256, GEMM_SMEM>>>(
        p_ah, p_al, p_woh, p_wol, b_o, x, p_x1, nullptr, nullptr, DDIM, DDIM);
    // 5) LN2 -> split
    ln_split<<<BT, 256>>>(p_x1, ln2_g, ln2_b, p_ah, p_al);
    // 6) FC1 + GELU -> split h
    hmma_gemm<1><<<dim3(4 * DDIM / 128, BT / 128), 256, GEMM_SMEM>>>(
        p_ah, p_al, p_w1h, p_w1l, b_fc1, nullptr, nullptr, p_hh, p_hl, 4 * DDIM, DDIM);
    // 7) FC2 + residual(x1) -> out fp32
    hmma_gemm<2><<<dim3(DDIM / 128, BT / 128), 256, GEMM_SMEM>>>(
        p_hh, p_hl, p_w2h, p_w2l, b_fc2, p_x1, out, nullptr, nullptr, DDIM, 4 * DDIM);
}

// round 4
// speedup vs baseline: 2.3872x; 1.3610x over previous
#include <cuda_runtime.h>
#include <cuda_bf16.h>
#include <math.h>
#include <stdint.h>

#define BB   2
#define TTOK 2048
#define DDIM 1024
#define NH   16
#define HDIM 64
#define BT   (BB*TTOK)   // 4096

// ------------------------- scratch (static device arrays) --------------------
__device__ float g_x1 [BT * DDIM];                // fp32 residual stream after attn
__device__ __nv_bfloat16 g_ah[BT * DDIM];         // activation split hi
__device__ __nv_bfloat16 g_al[BT * DDIM];         // activation split lo
__device__ __nv_bfloat16 g_qvh[BT * 3 * DDIM];    // qkv split hi
__device__ __nv_bfloat16 g_qvl[BT * 3 * DDIM];    // qkv split lo
__device__ __nv_bfloat16 g_hh[BT * 4 * DDIM];     // gelu(h) split hi
__device__ __nv_bfloat16 g_hl[BT * 4 * DDIM];     // gelu(h) split lo
__device__ __nv_bfloat16 g_wq_h[3 * DDIM * DDIM], g_wq_l[3 * DDIM * DDIM];
__device__ __nv_bfloat16 g_wo_h[DDIM * DDIM],     g_wo_l[DDIM * DDIM];
__device__ __nv_bfloat16 g_w1_h[4 * DDIM * DDIM], g_w1_l[4 * DDIM * DDIM];
__device__ __nv_bfloat16 g_w2_h[4 * DDIM * DDIM], g_w2_l[4 * DDIM * DDIM];

// ------------------------- PTX helpers ---------------------------------------
__device__ __forceinline__ uint32_t s2u(const void* p) {
    uint32_t a;
    asm("{ .reg .u64 t; cvta.to.shared.u64 t, %1; cvt.u32.u64 %0, t; }" : "=r"(a) : "l"(p));
    return a;
}
__device__ __forceinline__ void cp16(uint32_t dst, const void* src) {
    asm volatile("cp.async.cg.shared.global [%0], [%1], 16;" :: "r"(dst), "l"(src));
}
#define CP_COMMIT() asm volatile("cp.async.commit_group;" ::: "memory")
#define CP_WAIT0()  asm volatile("cp.async.wait_group 0;" ::: "memory")
#define CP_WAIT1()  asm volatile("cp.async.wait_group 1;" ::: "memory")
#define CP_WAIT2()  asm volatile("cp.async.wait_group 2;" ::: "memory")

__device__ __forceinline__ void ldsm4(uint32_t* r, uint32_t addr) {
    asm volatile("ldmatrix.sync.aligned.m8n8.x4.shared.b16 {%0,%1,%2,%3}, [%4];"
                 : "=r"(r[0]), "=r"(r[1]), "=r"(r[2]), "=r"(r[3]) : "r"(addr));
}
__device__ __forceinline__ void ldsm4t(uint32_t* r, uint32_t addr) {
    asm volatile("ldmatrix.sync.aligned.m8n8.x4.trans.shared.b16 {%0,%1,%2,%3}, [%4];"
                 : "=r"(r[0]), "=r"(r[1]), "=r"(r[2]), "=r"(r[3]) : "r"(addr));
}
__device__ __forceinline__ void mma_bf16(float* c, const uint32_t* a,
                                         uint32_t b0, uint32_t b1) {
    asm volatile(
        "mma.sync.aligned.m16n8k16.row.col.f32.bf16.bf16.f32 "
        "{%0,%1,%2,%3}, {%4,%5,%6,%7}, {%8,%9}, {%0,%1,%2,%3};"
        : "+f"(c[0]), "+f"(c[1]), "+f"(c[2]), "+f"(c[3])
        : "r"(a[0]), "r"(a[1]), "r"(a[2]), "r"(a[3]), "r"(b0), "r"(b1));
}

__device__ __forceinline__ float gelu_f(float x) {
    float x3 = x * x * x;
    return 0.5f * x * (1.0f + tanhf(0.7978845608028654f * (x + 0.044715f * x3)));
}
__device__ __forceinline__ void split_bf16(float v, __nv_bfloat16& h, __nv_bfloat16& l) {
    h = __float2bfloat16(v);
    l = __float2bfloat16(v - __bfloat162float(h));
}

// ------------------------- weight transpose + bf16 split ---------------------
__global__ void wsplit_t(const float* __restrict__ W,
                         __nv_bfloat16* __restrict__ Oh, __nv_bfloat16* __restrict__ Ol,
                         int K, int N) {
    __shared__ float t[32][33];
    int nx = blockIdx.x * 32, kx = blockIdx.y * 32;
    int tx = threadIdx.x, ty = threadIdx.y;  // 32 x 8
    #pragma unroll
    for (int i = 0; i < 32; i += 8)
        t[ty + i][tx] = W[(size_t)(kx + ty + i) * N + nx + tx];
    __syncthreads();
    #pragma unroll
    for (int i = 0; i < 32; i += 8) {
        float v = t[tx][ty + i];
        __nv_bfloat16 h, l; split_bf16(v, h, l);
        size_t oi = (size_t)(nx + ty + i) * K + kx + tx;
        Oh[oi] = h; Ol[oi] = l;
    }
}

// ------------------------- LayerNorm -> split bf16 ---------------------------
__global__ void ln_split(const float* __restrict__ x, const float* __restrict__ g,
                         const float* __restrict__ b,
                         __nv_bfloat16* __restrict__ oh, __nv_bfloat16* __restrict__ ol) {
    int row = blockIdx.x;
    int tid = threadIdx.x;
    float4 v = ((const float4*)(x + (size_t)row * DDIM))[tid];
    float s  = v.x + v.y + v.z + v.w;
    float ss = v.x*v.x + v.y*v.y + v.z*v.z + v.w*v.w;
    #pragma unroll
    for (int off = 16; off > 0; off >>= 1) {
        s  += __shfl_xor_sync(0xffffffffu, s,  off);
        ss += __shfl_xor_sync(0xffffffffu, ss, off);
    }
    __shared__ float rs[8], rss[8];
    int w = tid >> 5, ln = tid & 31;
    if (ln == 0) { rs[w] = s; rss[w] = ss; }
    __syncthreads();
    float tot = 0.f, tots = 0.f;
    #pragma unroll
    for (int i = 0; i < 8; i++) { tot += rs[i]; tots += rss[i]; }
    float mu  = tot * (1.0f / DDIM);
    float var = tots * (1.0f / DDIM) - mu * mu;
    float inv = rsqrtf(var + 1e-5f);
    float4 gg = ((const float4*)g)[tid];
    float4 bb = ((const float4*)b)[tid];
    float r0 = (v.x - mu) * inv * gg.x + bb.x;
    float r1 = (v.y - mu) * inv * gg.y + bb.y;
    float r2 = (v.z - mu) * inv * gg.z + bb.z;
    float r3 = (v.w - mu) * inv * gg.w + bb.w;
    __nv_bfloat16 h0,h1,h2,h3,l0,l1,l2,l3;
    split_bf16(r0,h0,l0); split_bf16(r1,h1,l1); split_bf16(r2,h2,l2); split_bf16(r3,h3,l3);
    size_t base = (size_t)row * DDIM + tid * 4;
    __nv_bfloat162 a01; a01.x = h0; a01.y = h1;
    __nv_bfloat162 a23; a23.x = h2; a23.y = h3;
    __nv_bfloat162 b01; b01.x = l0; b01.y = l1;
    __nv_bfloat162 b23; b23.x = l2; b23.y = l3;
    *(__nv_bfloat162*)(oh + base)     = a01;
    *(__nv_bfloat162*)(oh + base + 2) = a23;
    *(__nv_bfloat162*)(ol + base)     = b01;
    *(__nv_bfloat162*)(ol + base + 2) = b23;
}

// ------------------------- HMMA split-bf16 GEMM ------------------------------
// EPI: 0 plain fp32 / 1 gelu->split / 2 +res fp32 / 3 split (no gelu)
#define ROWB   80
#define OFF_AH 0
#define OFF_AL 10240
#define OFF_BH 20480
#define OFF_BL 30720
#define STG    40960
#define GEMM_SMEM (3 * STG)

__device__ __forceinline__ void load_stage(
    uint32_t st,
    const __nv_bfloat16* __restrict__ Ah, const __nv_bfloat16* __restrict__ Al,
    const __nv_bfloat16* __restrict__ Bh, const __nv_bfloat16* __restrict__ Bl,
    int K, int bm, int bn, int k0, int tid)
{
    #pragma unroll
    for (int j = 0; j < 2; j++) {
        int o = tid + (j << 8);
        int r = o >> 2, c = o & 3;
        size_t ga = (size_t)(bm + r) * K + k0 + (c << 3);
        size_t gb = (size_t)(bn + r) * K + k0 + (c << 3);
        uint32_t so = (uint32_t)(r * ROWB + (c << 4));
        cp16(st + OFF_AH + so, Ah + ga);
        cp16(st + OFF_AL + so, Al + ga);
        cp16(st + OFF_BH + so, Bh + gb);
        cp16(st + OFF_BL + so, Bl + gb);
    }
}

template<int EPI>
__global__ void __launch_bounds__(256, 1) hmma_gemm(
    const __nv_bfloat16* __restrict__ Ah, const __nv_bfloat16* __restrict__ Al,
    const __nv_bfloat16* __restrict__ Bh, const __nv_bfloat16* __restrict__ Bl,
    const float* __restrict__ bias, const float* __restrict__ res,
    float* __restrict__ Cf, __nv_bfloat16* __restrict__ Ch, __nv_bfloat16* __restrict__ Cl,
    int N, int K)
{
    extern __shared__ __align__(1024) char smem[];
    uint32_t sb = s2u(smem);
    int tid = threadIdx.x, wid = tid >> 5, lane = tid & 31;
    int wm = wid & 1, wn = wid >> 1;
    int bm = blockIdx.y << 7, bn = blockIdx.x << 7;

    float acc[4][4][4];
    #pragma unroll
    for (int mi = 0; mi < 4; mi++)
        #pragma unroll
        for (int ni = 0; ni < 4; ni++)
            #pragma unroll
            for (int e = 0; e < 4; e++) acc[mi][ni][e] = 0.f;

    int nch = K >> 5;
    load_stage(sb, Ah, Al, Bh, Bl, K, bm, bn, 0, tid);
    CP_COMMIT();
    load_stage(sb + STG, Ah, Al, Bh, Bl, K, bm, bn, 32, tid);
    CP_COMMIT();

    int arow = lane & 15;
    int acol = (lane >> 4) << 3;
    int bg   = lane >> 3;
    int brow = lane & 7;

    for (int i = 0; i < nch; i++) {
        if (i + 2 < nch) {
            load_stage(sb + (uint32_t)((i + 2) % 3) * STG,
                       Ah, Al, Bh, Bl, K, bm, bn, (i + 2) << 5, tid);
        }
        CP_COMMIT();
        CP_WAIT2();
        __syncthreads();

        uint32_t st = sb + (uint32_t)(i % 3) * STG;
        #pragma unroll
        for (int ks = 0; ks < 2; ks++) {
            uint32_t aH[4][4], aL[4][4];
            #pragma unroll
            for (int mi = 0; mi < 4; mi++) {
                uint32_t off = (uint32_t)(((wm << 6) + (mi << 4) + arow) * ROWB
                                          + ((ks << 4) + acol) * 2);
                ldsm4(aH[mi], st + OFF_AH + off);
                ldsm4(aL[mi], st + OFF_AL + off);
            }
            uint32_t bH[4][2], bL[4][2];
            #pragma unroll
            for (int np = 0; np < 2; np++) {
                uint32_t off = (uint32_t)(((wn << 5) + (np << 4) + ((bg >> 1) << 3) + brow) * ROWB
                                          + ((ks << 4) + ((bg & 1) << 3)) * 2);
                uint32_t r[4];
                ldsm4(r, st + OFF_BH + off);
                bH[2*np][0] = r[0]; bH[2*np][1] = r[1];
                bH[2*np+1][0] = r[2]; bH[2*np+1][1] = r[3];
                ldsm4(r, st + OFF_BL + off);
                bL[2*np][0] = r[0]; bL[2*np][1] = r[1];
                bL[2*np+1][0] = r[2]; bL[2*np+1][1] = r[3];
            }
            #pragma unroll
            for (int mi = 0; mi < 4; mi++)
                #pragma unroll
                for (int ni = 0; ni < 4; ni++) {
                    mma_bf16(acc[mi][ni], aH[mi], bH[ni][0], bH[ni][1]);
                    mma_bf16(acc[mi][ni], aH[mi], bL[ni][0], bL[ni][1]);
                    mma_bf16(acc[mi][ni], aL[mi], bH[ni][0], bH[ni][1]);
                }
        }
        __syncthreads();
    }

    #pragma unroll
    for (int mi = 0; mi < 4; mi++) {
        #pragma unroll
        for (int ni = 0; ni < 4; ni++) {
            int row0 = bm + (wm << 6) + (mi << 4) + (lane >> 2);
            int col  = bn + (wn << 5) + (ni << 3) + ((lane & 3) << 1);
            float b0 = __ldg(bias + col), b1 = __ldg(bias + col + 1);
            #pragma unroll
            for (int half = 0; half < 2; half++) {
                int row = row0 + half * 8;
                float v0 = acc[mi][ni][half * 2 + 0] + b0;
                float v1 = acc[mi][ni][half * 2 + 1] + b1;
                size_t oi = (size_t)row * N + col;
                if (EPI == 0) {
                    float2 ov; ov.x = v0; ov.y = v1;
                    *(float2*)(Cf + oi) = ov;
                } else if (EPI == 2) {
                    float2 rv = *(const float2*)(res + oi);
                    float2 ov; ov.x = v0 + rv.x; ov.y = v1 + rv.y;
                    *(float2*)(Cf + oi) = ov;
                } else {
                    float a0 = (EPI == 1) ? gelu_f(v0) : v0;
                    float a1 = (EPI == 1) ? gelu_f(v1) : v1;
                    __nv_bfloat16 h0, h1, l0, l1;
                    split_bf16(a0, h0, l0); split_bf16(a1, h1, l1);
                    __nv_bfloat162 hh; hh.x = h0; hh.y = h1;
                    __nv_bfloat162 ll; ll.x = l0; ll.y = l1;
                    *(__nv_bfloat162*)(Ch + oi) = hh;
                    *(__nv_bfloat162*)(Cl + oi) = ll;
                }
            }
        }
    }
}

// ------------------------- tensor-core flash attention -----------------------
// qkv split hi/lo [BT, 3D]; BQ=128 (8 warps x 16 rows), BK=64, hd=64.
// Split-bf16 (3 products) for both QK^T and PV. fp32 softmax in registers.
#define AQ_STRIDE 144                 // bytes per smem row (72 bf16)
#define SM_QH 0
#define SM_QL 18432
#define SM_KV0 36864
#define KV_STG 36864
#define KOFF_H 0
#define KOFF_L 9216
#define VOFF_H 18432
#define VOFF_L 27648
#define ATT_SMEM (SM_KV0 + 2 * KV_STG)   // 110592

__global__ void __launch_bounds__(256, 1) attn_tc(
    const __nv_bfloat16* __restrict__ qvh, const __nv_bfloat16* __restrict__ qvl,
    __nv_bfloat16* __restrict__ oh, __nv_bfloat16* __restrict__ ol)
{
    extern __shared__ __align__(1024) char smem[];
    uint32_t sb = s2u(smem);
    int qt = (int)gridDim.x - 1 - (int)blockIdx.x;      // heavy tiles first
    int b  = blockIdx.y >> 4;
    int h  = blockIdx.y & 15;
    int tid = threadIdx.x, wid = tid >> 5, lane = tid & 31;
    const size_t TD3 = 3 * DDIM;
    size_t qrow0 = (size_t)b * TTOK + (size_t)qt * 128;

    // ---- Q tile load (hi+lo), 2048 cp16 over 256 threads ----
    #pragma unroll
    for (int i = 0; i < 8; i++) {
        int e = tid + (i << 8);
        int t = e >> 10;                  // 0 hi, 1 lo
        int rem = e & 1023;
        int r = rem >> 3, c = rem & 7;
        const __nv_bfloat16* src = (t ? qvl : qvh) + (qrow0 + r) * TD3 + h * HDIM + (c << 3);
        cp16(sb + (t ? SM_QL : SM_QH) + r * AQ_STRIDE + (c << 4), src);
    }
    // ---- stage 0 KV ----
    {
        size_t kvrow0 = (size_t)b * TTOK;
        uint32_t base = sb + SM_KV0;
        #pragma unroll
        for (int i = 0; i < 8; i++) {
            int e = tid + (i << 8);
            int t = e >> 9;               // 0 Kh 1 Kl 2 Vh 3 Vl
            int rem = e & 511;
            int r = rem >> 3, c = rem & 7;
            const __nv_bfloat16* p = (t & 1) ? qvl : qvh;
            size_t off = (kvrow0 + r) * TD3 + ((t >> 1) ? 2 * DDIM : DDIM) + h * HDIM + (c << 3);
            uint32_t doff = ((t & 1) ? (uint32_t)KOFF_L : 0u) + ((t >> 1) ? (uint32_t)VOFF_H : 0u);
            cp16(base + doff + r * AQ_STRIDE + (c << 4), p + off);
        }
    }
    CP_COMMIT();

    uint32_t qhf[4][4], qlf[4][4];
    float O[8][4];
    #pragma unroll
    for (int n = 0; n < 8; n++)
        #pragma unroll
        for (int e = 0; e < 4; e++) O[n][e] = 0.f;
    float m0 = -1e30f, m1 = -1e30f, l0 = 0.f, l1 = 0.f;

    int bg = lane >> 3, brow = lane & 7;
    int ntiles = 2 * qt + 2;
    bool qloaded = false;

    for (int j = 0; j < ntiles; j++) {
        if (j + 1 < ntiles) {
            size_t kvrow0 = (size_t)b * TTOK + (size_t)(j + 1) * 64;
            uint32_t base = sb + SM_KV0 + (uint32_t)((j + 1) & 1) * KV_STG;
            #pragma unroll
            for (int i = 0; i < 8; i++) {
                int e = tid + (i << 8);
                int t = e >> 9;
                int rem = e & 511;
                int r = rem >> 3, c = rem & 7;
                const __nv_bfloat16* p = (t & 1) ? qvl : qvh;
                size_t off = (kvrow0 + r) * TD3 + ((t >> 1) ? 2 * DDIM : DDIM) + h * HDIM + (c << 3);
                uint32_t doff = ((t & 1) ? (uint32_t)KOFF_L : 0u) + ((t >> 1) ? (uint32_t)VOFF_H : 0u);
                cp16(base + doff + r * AQ_STRIDE + (c << 4), p + off);
            }
            CP_COMMIT();
            CP_WAIT1();
        } else {
            CP_WAIT0();
        }
        __syncthreads();

        if (!qloaded) {
            qloaded = true;
            #pragma unroll
            for (int kc = 0; kc < 4; kc++) {
                uint32_t aoff = (uint32_t)((wid * 16 + (lane & 15)) * AQ_STRIDE
                                           + ((kc << 4) + ((lane >> 4) << 3)) * 2);
                ldsm4(qhf[kc], sb + SM_QH + aoff);
                ldsm4(qlf[kc], sb + SM_QL + aoff);
            }
        }

        uint32_t kb = sb + SM_KV0 + (uint32_t)(j & 1) * KV_STG;

        // ---- S = Q K^T (3 products) ----
        float S[8][4];
        #pragma unroll
        for (int n = 0; n < 8; n++)
            #pragma unroll
            for (int e = 0; e < 4; e++) S[n][e] = 0.f;

        #pragma unroll
        for (int p = 0; p < 4; p++) {
            #pragma unroll
            for (int kc = 0; kc < 4; kc++) {
                uint32_t koff = (uint32_t)(((p << 4) + ((bg >> 1) << 3) + brow) * AQ_STRIDE
                                           + ((kc << 4) + ((bg & 1) << 3)) * 2);
                uint32_t rh[4], rl[4];
                ldsm4(rh, kb + KOFF_H + koff);
                ldsm4(rl, kb + KOFF_L + koff);
                mma_bf16(S[2*p],   qhf[kc], rh[0], rh[1]);
                mma_bf16(S[2*p],   qhf[kc], rl[0], rl[1]);
                mma_bf16(S[2*p],   qlf[kc], rh[0], rh[1]);
                mma_bf16(S[2*p+1], qhf[kc], rh[2], rh[3]);
                mma_bf16(S[2*p+1], qhf[kc], rl[2], rl[3]);
                mma_bf16(S[2*p+1], qlf[kc], rh[2], rh[3]);
            }
        }

        // ---- scale + causal mask ----
        int row0 = qt * 128 + wid * 16 + (lane >> 2);
        int row1 = row0 + 8;
        int cbase = j * 64 + ((lane & 3) << 1);
        bool need_mask = (j >= 2 * qt);
        #pragma unroll
        for (int n = 0; n < 8; n++) {
            #pragma unroll
            for (int e = 0; e < 4; e++) S[n][e] *= 0.125f;
            if (need_mask) {
                int c0 = cbase + n * 8;
                if (c0     > row0) S[n][0] = -1e30f;
                if (c0 + 1 > row0) S[n][1] = -1e30f;
                if (c0     > row1) S[n][2] = -1e30f;
                if (c0 + 1 > row1) S[n][3] = -1e30f;
            }
        }

        // ---- online softmax (rows warp-local, quad reduce) ----
        float mr0 = -1e30f, mr1 = -1e30f;
        #pragma unroll
        for (int n = 0; n < 8; n++) {
            mr0 = fmaxf(mr0, fmaxf(S[n][0], S[n][1]));
            mr1 = fmaxf(mr1, fmaxf(S[n][2], S[n][3]));
        }
        mr0 = fmaxf(mr0, __shfl_xor_sync(0xffffffffu, mr0, 1));
        mr0 = fmaxf(mr0, __shfl_xor_sync(0xffffffffu, mr0, 2));
        mr1 = fmaxf(mr1, __shfl_xor_sync(0xffffffffu, mr1, 1));
        mr1 = fmaxf(mr1, __shfl_xor_sync(0xffffffffu, mr1, 2));
        float mn0 = fmaxf(m0, mr0), mn1 = fmaxf(m1, mr1);
        float alpha0 = __expf(m0 - mn0), alpha1 = __expf(m1 - mn1);
        float sum0 = 0.f, sum1 = 0.f;
        #pragma unroll
        for (int n = 0; n < 8; n++) {
            S[n][0] = __expf(S[n][0] - mn0); sum0 += S[n][0];
            S[n][1] = __expf(S[n][1] - mn0); sum0 += S[n][1];
            S[n][2] = __expf(S[n][2] - mn1); sum1 += S[n][2];
            S[n][3] = __expf(S[n][3] - mn1); sum1 += S[n][3];
        }
        sum0 += __shfl_xor_sync(0xffffffffu, sum0, 1);
        sum0 += __shfl_xor_sync(0xffffffffu, sum0, 2);
        sum1 += __shfl_xor_sync(0xffffffffu, sum1, 1);
        sum1 += __shfl_xor_sync(0xffffffffu, sum1, 2);
        l0 = l0 * alpha0 + sum0;
        l1 = l1 * alpha1 + sum1;
        m0 = mn0; m1 = mn1;
        #pragma unroll
        for (int n = 0; n < 8; n++) {
            O[n][0] *= alpha0; O[n][1] *= alpha0;
            O[n][2] *= alpha1; O[n][3] *= alpha1;
        }

        // ---- O += P V (3 products), P frags built in-register ----
        #pragma unroll
        for (int kc = 0; kc < 4; kc++) {
            uint32_t ph[4], pl[4];
            {
                float v[8] = { S[2*kc][0], S[2*kc][1], S[2*kc][2], S[2*kc][3],
                               S[2*kc+1][0], S[2*kc+1][1], S[2*kc+1][2], S[2*kc+1][3] };
                __nv_bfloat16 hh[8], llq[8];
                #pragma unroll
                for (int e = 0; e < 8; e++) split_bf16(v[e], hh[e], llq[e]);
                #pragma unroll
                for (int e = 0; e < 4; e++) {
                    __nv_bfloat162 t1; t1.x = hh[2*e]; t1.y = hh[2*e+1];
                    __nv_bfloat162 t2; t2.x = llq[2*e]; t2.y = llq[2*e+1];
                    ph[e] = *(uint32_t*)&t1;
                    pl[e] = *(uint32_t*)&t2;
                }
            }
            #pragma unroll
            for (int np = 0; np < 4; np++) {
                uint32_t voff = (uint32_t)(((kc << 4) + ((bg & 1) << 3) + brow) * AQ_STRIDE
                                           + ((np << 4) + ((bg >> 1) << 3)) * 2);
                uint32_t rh[4], rl[4];
                ldsm4t(rh, kb + VOFF_H + voff);
                ldsm4t(rl, kb + VOFF_L + voff);
                mma_bf16(O[2*np],   ph, rh[0], rh[1]);
                mma_bf16(O[2*np],   ph, rl[0], rl[1]);
                mma_bf16(O[2*np],   pl, rh[0], rh[1]);
                mma_bf16(O[2*np+1], ph, rh[2], rh[3]);
                mma_bf16(O[2*np+1], ph, rl[2], rl[3]);
                mma_bf16(O[2*np+1], pl, rh[2], rh[3]);
            }
        }
        __syncthreads();
    }

    // ---- normalize + split store ----
    float inv0 = 1.0f / l0, inv1 = 1.0f / l1;
    size_t row0g = qrow0 + wid * 16 + (lane >> 2);
    int colb = h * HDIM + ((lane & 3) << 1);
    #pragma unroll
    for (int n = 0; n < 8; n++) {
        int col = colb + n * 8;
        float v0 = O[n][0] * inv0, v1 = O[n][1] * inv0;
        float v2 = O[n][2] * inv1, v3 = O[n][3] * inv1;
        __nv_bfloat16 h0,h1,h2,h3,l0b,l1b,l2b,l3b;
        split_bf16(v0,h0,l0b); split_bf16(v1,h1,l1b);
        split_bf16(v2,h2,l2b); split_bf16(v3,h3,l3b);
        __nv_bfloat162 t;
        t.x = h0; t.y = h1; *(__nv_bfloat162*)(oh + row0g * DDIM + col) = t;
        t.x = l0b; t.y = l1b; *(__nv_bfloat162*)(ol + row0g * DDIM + col) = t;
        t.x = h2; t.y = h3; *(__nv_bfloat162*)(oh + (row0g + 8) * DDIM + col) = t;
        t.x = l2b; t.y = l3b; *(__nv_bfloat162*)(ol + (row0g + 8) * DDIM + col) = t;
    }
}

// ------------------------- launch --------------------------------------------
extern "C" void kernel_launch(void* const* d_in, const int* in_sizes, int n_in,
                              void* d_out, int out_size) {
    const float* x      = (const float*)d_in[0];
    const float* ln1_g  = (const float*)d_in[1];
    const float* ln1_b  = (const float*)d_in[2];
    const float* ln2_g  = (const float*)d_in[3];
    const float* ln2_b  = (const float*)d_in[4];
    const float* w_qkv  = (const float*)d_in[5];
    const float* b_qkv  = (const float*)d_in[6];
    const float* w_o    = (const float*)d_in[7];
    const float* b_o    = (const float*)d_in[8];
    const float* w_fc1  = (const float*)d_in[9];
    const float* b_fc1  = (const float*)d_in[10];
    const float* w_fc2  = (const float*)d_in[11];
    const float* b_fc2  = (const float*)d_in[12];
    float* out = (float*)d_out;

    float *p_x1;
    __nv_bfloat16 *p_ah, *p_al, *p_hh, *p_hl, *p_qvh, *p_qvl;
    __nv_bfloat16 *p_wqh, *p_wql, *p_woh, *p_wol, *p_w1h, *p_w1l, *p_w2h, *p_w2l;
    cudaGetSymbolAddress((void**)&p_x1,  g_x1);
    cudaGetSymbolAddress((void**)&p_ah,  g_ah);
    cudaGetSymbolAddress((void**)&p_al,  g_al);
    cudaGetSymbolAddress((void**)&p_hh,  g_hh);
    cudaGetSymbolAddress((void**)&p_hl,  g_hl);
    cudaGetSymbolAddress((void**)&p_qvh, g_qvh);
    cudaGetSymbolAddress((void**)&p_qvl, g_qvl);
    cudaGetSymbolAddress((void**)&p_wqh, g_wq_h);
    cudaGetSymbolAddress((void**)&p_wql, g_wq_l);
    cudaGetSymbolAddress((void**)&p_woh, g_wo_h);
    cudaGetSymbolAddress((void**)&p_wol, g_wo_l);
    cudaGetSymbolAddress((void**)&p_w1h, g_w1_h);
    cudaGetSymbolAddress((void**)&p_w1l, g_w1_l);
    cudaGetSymbolAddress((void**)&p_w2h, g_w2_h);
    cudaGetSymbolAddress((void**)&p_w2l, g_w2_l);

    cudaFuncSetAttribute(attn_tc, cudaFuncAttributeMaxDynamicSharedMemorySize, ATT_SMEM);
    cudaFuncSetAttribute(hmma_gemm<1>, cudaFuncAttributeMaxDynamicSharedMemorySize, GEMM_SMEM);
    cudaFuncSetAttribute(hmma_gemm<2>, cudaFuncAttributeMaxDynamicSharedMemorySize, GEMM_SMEM);
    cudaFuncSetAttribute(hmma_gemm<3>, cudaFuncAttributeMaxDynamicSharedMemorySize, GEMM_SMEM);

    dim3 wblk(32, 8);
    wsplit_t<<<dim3(3 * DDIM / 32, DDIM / 32), wblk>>>(w_qkv, p_wqh, p_wql, DDIM, 3 * DDIM);
    wsplit_t<<<dim3(DDIM / 32, DDIM / 32), wblk>>>(w_o, p_woh, p_wol, DDIM, DDIM);
    wsplit_t<<<dim3(4 * DDIM / 32, DDIM / 32), wblk>>>(w_fc1, p_w1h, p_w1l, DDIM, 4 * DDIM);
    wsplit_t<<<dim3(DDIM / 32, 4 * DDIM / 32), wblk>>>(w_fc2, p_w2h, p_w2l, 4 * DDIM, DDIM);

    // 1) LN1 -> split
    ln_split<<<BT, 256>>>(x, ln1_g, ln1_b, p_ah, p_al);
    // 2) QKV GEMM -> split bf16 qkv
    hmma_gemm<3><<<dim3(3 * DDIM / 128, BT / 128), 256, GEMM_SMEM>>>(
        p_ah, p_al, p_wqh, p_wql, b_qkv, nullptr, nullptr, p_qvh, p_qvl, 3 * DDIM, DDIM);
    // 3) tensor-core attention -> split att
    attn_tc<<<dim3(TTOK / 128, BB * NH), 256, ATT_SMEM>>>(p_qvh, p_qvl, p_ah, p_al);
    // 4) O-proj + residual(x) -> x1 fp32
    hmma_gemm<2><<<dim3(DDIM / 128, BT / 128), 256, GEMM_SMEM>>>(
        p_ah, p_al, p_woh, p_wol, b_o, x, p_x1, nullptr, nullptr, DDIM, DDIM);
    // 5) LN2 -> split
    ln_split<<<BT, 256>>>(p_x1, ln2_g, ln2_b, p_ah, p_al);
    // 6) FC1 + GELU -> split h
    hmma_gemm<1><<<dim3(4 * DDIM / 128, BT / 128), 256, GEMM_SMEM>>>(
        p_ah, p_al, p_w1h, p_w1l, b_fc1, nullptr, nullptr, p_hh, p_hl, 4 * DDIM, DDIM);
    // 7) FC2 + residual(x1) -> out fp32
    hmma_gemm<2><<<dim3(DDIM / 128, BT / 128), 256, GEMM_SMEM>>>(
        p_hh, p_hl, p_w2h, p_w2l, b_fc2, p_x1, out, nullptr, nullptr, DDIM, 4 * DDIM);
}

// round 5
// speedup vs baseline: 2.6751x; 1.1206x over previous
#include <cuda_runtime.h>
#include <cuda_bf16.h>
#include <math.h>
#include <stdint.h>

#define BB   2
#define TTOK 2048
#define DDIM 1024
#define NH   16
#define HDIM 64
#define BT   (BB*TTOK)   // 4096

// ------------------------- scratch (static device arrays) --------------------
__device__ float g_x1 [BT * DDIM];
__device__ __nv_bfloat16 g_ah[BT * DDIM];
__device__ __nv_bfloat16 g_al[BT * DDIM];
__device__ __nv_bfloat16 g_qvh[BT * 3 * DDIM];
__device__ __nv_bfloat16 g_qvl[BT * 3 * DDIM];
__device__ __nv_bfloat16 g_hh[BT * 4 * DDIM];
__device__ __nv_bfloat16 g_hl[BT * 4 * DDIM];
__device__ __nv_bfloat16 g_wq_h[3 * DDIM * DDIM], g_wq_l[3 * DDIM * DDIM];
__device__ __nv_bfloat16 g_wo_h[DDIM * DDIM],     g_wo_l[DDIM * DDIM];
__device__ __nv_bfloat16 g_w1_h[4 * DDIM * DDIM], g_w1_l[4 * DDIM * DDIM];
__device__ __nv_bfloat16 g_w2_h[4 * DDIM * DDIM], g_w2_l[4 * DDIM * DDIM];

// ------------------------- PTX helpers ---------------------------------------
__device__ __forceinline__ uint32_t s2u(const void* p) {
    uint32_t a;
    asm("{ .reg .u64 t; cvta.to.shared.u64 t, %1; cvt.u32.u64 %0, t; }" : "=r"(a) : "l"(p));
    return a;
}
__device__ __forceinline__ void cp16(uint32_t dst, const void* src) {
    asm volatile("cp.async.cg.shared.global [%0], [%1], 16;" :: "r"(dst), "l"(src));
}
#define CP_COMMIT() asm volatile("cp.async.commit_group;" ::: "memory")
#define CP_WAIT0()  asm volatile("cp.async.wait_group 0;" ::: "memory")

__device__ __forceinline__ void ldsm4(uint32_t* r, uint32_t addr) {
    asm volatile("ldmatrix.sync.aligned.m8n8.x4.shared.b16 {%0,%1,%2,%3}, [%4];"
                 : "=r"(r[0]), "=r"(r[1]), "=r"(r[2]), "=r"(r[3]) : "r"(addr));
}
__device__ __forceinline__ void ldsm4t(uint32_t* r, uint32_t addr) {
    asm volatile("ldmatrix.sync.aligned.m8n8.x4.trans.shared.b16 {%0,%1,%2,%3}, [%4];"
                 : "=r"(r[0]), "=r"(r[1]), "=r"(r[2]), "=r"(r[3]) : "r"(addr));
}
// NOTE: non-volatile -> compiler may schedule/interleave HMMAs (register-only op)
__device__ __forceinline__ void mma_bf16(float* c, const uint32_t* a,
                                         uint32_t b0, uint32_t b1) {
    asm("mma.sync.aligned.m16n8k16.row.col.f32.bf16.bf16.f32 "
        "{%0,%1,%2,%3}, {%4,%5,%6,%7}, {%8,%9}, {%0,%1,%2,%3};"
        : "+f"(c[0]), "+f"(c[1]), "+f"(c[2]), "+f"(c[3])
        : "r"(a[0]), "r"(a[1]), "r"(a[2]), "r"(a[3]), "r"(b0), "r"(b1));
}

__device__ __forceinline__ float gelu_f(float x) {
    float x3 = x * x * x;
    return 0.5f * x * (1.0f + tanhf(0.7978845608028654f * (x + 0.044715f * x3)));
}
__device__ __forceinline__ void split_bf16(float v, __nv_bfloat16& h, __nv_bfloat16& l) {
    h = __float2bfloat16(v);
    l = __float2bfloat16(v - __bfloat162float(h));
}

// ------------------------- weight transpose + bf16 split ---------------------
__global__ void wsplit_t(const float* __restrict__ W,
                         __nv_bfloat16* __restrict__ Oh, __nv_bfloat16* __restrict__ Ol,
                         int K, int N) {
    __shared__ float t[32][33];
    int nx = blockIdx.x * 32, kx = blockIdx.y * 32;
    int tx = threadIdx.x, ty = threadIdx.y;
    #pragma unroll
    for (int i = 0; i < 32; i += 8)
        t[ty + i][tx] = W[(size_t)(kx + ty + i) * N + nx + tx];
    __syncthreads();
    #pragma unroll
    for (int i = 0; i < 32; i += 8) {
        float v = t[tx][ty + i];
        __nv_bfloat16 h, l; split_bf16(v, h, l);
        size_t oi = (size_t)(nx + ty + i) * K + kx + tx;
        Oh[oi] = h; Ol[oi] = l;
    }
}

// ------------------------- LayerNorm -> split bf16 ---------------------------
__global__ void ln_split(const float* __restrict__ x, const float* __restrict__ g,
                         const float* __restrict__ b,
                         __nv_bfloat16* __restrict__ oh, __nv_bfloat16* __restrict__ ol) {
    int row = blockIdx.x;
    int tid = threadIdx.x;
    float4 v = ((const float4*)(x + (size_t)row * DDIM))[tid];
    float s  = v.x + v.y + v.z + v.w;
    float ss = v.x*v.x + v.y*v.y + v.z*v.z + v.w*v.w;
    #pragma unroll
    for (int off = 16; off > 0; off >>= 1) {
        s  += __shfl_xor_sync(0xffffffffu, s,  off);
        ss += __shfl_xor_sync(0xffffffffu, ss, off);
    }
    __shared__ float rs[8], rss[8];
    int w = tid >> 5, ln = tid & 31;
    if (ln == 0) { rs[w] = s; rss[w] = ss; }
    __syncthreads();
    float tot = 0.f, tots = 0.f;
    #pragma unroll
    for (int i = 0; i < 8; i++) { tot += rs[i]; tots += rss[i]; }
    float mu  = tot * (1.0f / DDIM);
    float var = tots * (1.0f / DDIM) - mu * mu;
    float inv = rsqrtf(var + 1e-5f);
    float4 gg = ((const float4*)g)[tid];
    float4 bb = ((const float4*)b)[tid];
    float r0 = (v.x - mu) * inv * gg.x + bb.x;
    float r1 = (v.y - mu) * inv * gg.y + bb.y;
    float r2 = (v.z - mu) * inv * gg.z + bb.z;
    float r3 = (v.w - mu) * inv * gg.w + bb.w;
    __nv_bfloat16 h0,h1,h2,h3,l0,l1,l2,l3;
    split_bf16(r0,h0,l0); split_bf16(r1,h1,l1); split_bf16(r2,h2,l2); split_bf16(r3,h3,l3);
    size_t base = (size_t)row * DDIM + tid * 4;
    __nv_bfloat162 a01; a01.x = h0; a01.y = h1;
    __nv_bfloat162 a23; a23.x = h2; a23.y = h3;
    __nv_bfloat162 b01; b01.x = l0; b01.y = l1;
    __nv_bfloat162 b23; b23.x = l2; b23.y = l3;
    *(__nv_bfloat162*)(oh + base)     = a01;
    *(__nv_bfloat162*)(oh + base + 2) = a23;
    *(__nv_bfloat162*)(ol + base)     = b01;
    *(__nv_bfloat162*)(ol + base + 2) = b23;
}

// ------------------------- HMMA split-bf16 GEMM ------------------------------
// K-chunk 64, 2-stage cp.async, ONE barrier per chunk.
// EPI: 0 plain fp32 / 1 gelu->split / 2 +res fp32 / 3 split (no gelu)
#define ROWB   144                    // 64 data bf16 (128B) + 16B pad
#define OFF_AH 0
#define OFF_AL (128*144)
#define OFF_BH (2*128*144)
#define OFF_BL (3*128*144)
#define STG    (4*128*144)            // 73728
#define GEMM_SMEM (2 * STG)           // 147456

__device__ __forceinline__ void load_stage(
    uint32_t st,
    const __nv_bfloat16* __restrict__ Ah, const __nv_bfloat16* __restrict__ Al,
    const __nv_bfloat16* __restrict__ Bh, const __nv_bfloat16* __restrict__ Bl,
    int K, int bm, int bn, int k0, int tid)
{
    #pragma unroll
    for (int j = 0; j < 4; j++) {
        int o = tid + (j << 8);          // 0..1023
        int r = o >> 3, c = o & 7;       // 128 rows x 8 chunks of 16B
        size_t ga = (size_t)(bm + r) * K + k0 + (c << 3);
        size_t gb = (size_t)(bn + r) * K + k0 + (c << 3);
        uint32_t so = (uint32_t)(r * ROWB + (c << 4));
        cp16(st + OFF_AH + so, Ah + ga);
        cp16(st + OFF_AL + so, Al + ga);
        cp16(st + OFF_BH + so, Bh + gb);
        cp16(st + OFF_BL + so, Bl + gb);
    }
}

template<int EPI>
__global__ void __launch_bounds__(256, 1) hmma_gemm(
    const __nv_bfloat16* __restrict__ Ah, const __nv_bfloat16* __restrict__ Al,
    const __nv_bfloat16* __restrict__ Bh, const __nv_bfloat16* __restrict__ Bl,
    const float* __restrict__ bias, const float* __restrict__ res,
    float* __restrict__ Cf, __nv_bfloat16* __restrict__ Ch, __nv_bfloat16* __restrict__ Cl,
    int N, int K)
{
    extern __shared__ __align__(1024) char smem[];
    uint32_t sb = s2u(smem);
    int tid = threadIdx.x, wid = tid >> 5, lane = tid & 31;
    int wm = wid & 1, wn = wid >> 1;
    int bm = blockIdx.y << 7, bn = blockIdx.x << 7;

    float acc[4][4][4];
    #pragma unroll
    for (int mi = 0; mi < 4; mi++)
        #pragma unroll
        for (int ni = 0; ni < 4; ni++)
            #pragma unroll
            for (int e = 0; e < 4; e++) acc[mi][ni][e] = 0.f;

    int nch = K >> 6;
    load_stage(sb, Ah, Al, Bh, Bl, K, bm, bn, 0, tid);
    CP_COMMIT();

    int arow = lane & 15;
    int acol = (lane >> 4) << 3;
    int bg   = lane >> 3;
    int brow = lane & 7;

    for (int i = 0; i < nch; i++) {
        CP_WAIT0();
        __syncthreads();               // stage i ready; all warps past chunk i-1
        if (i + 1 < nch) {
            load_stage(sb + (uint32_t)((i + 1) & 1) * STG,
                       Ah, Al, Bh, Bl, K, bm, bn, (i + 1) << 6, tid);
            CP_COMMIT();
        }
        uint32_t st = sb + (uint32_t)(i & 1) * STG;
        #pragma unroll
        for (int ks = 0; ks < 4; ks++) {
            uint32_t aH[4][4], aL[4][4];
            #pragma unroll
            for (int mi = 0; mi < 4; mi++) {
                uint32_t off = (uint32_t)(((wm << 6) + (mi << 4) + arow) * ROWB
                                          + ((ks << 4) + acol) * 2);
                ldsm4(aH[mi], st + OFF_AH + off);
                ldsm4(aL[mi], st + OFF_AL + off);
            }
            uint32_t bH[4][2], bL[4][2];
            #pragma unroll
            for (int np = 0; np < 2; np++) {
                uint32_t off = (uint32_t)(((wn << 5) + (np << 4) + ((bg >> 1) << 3) + brow) * ROWB
                                          + ((ks << 4) + ((bg & 1) << 3)) * 2);
                uint32_t r[4];
                ldsm4(r, st + OFF_BH + off);
                bH[2*np][0] = r[0]; bH[2*np][1] = r[1];
                bH[2*np+1][0] = r[2]; bH[2*np+1][1] = r[3];
                ldsm4(r, st + OFF_BL + off);
                bL[2*np][0] = r[0]; bL[2*np][1] = r[1];
                bL[2*np+1][0] = r[2]; bL[2*np+1][1] = r[3];
            }
            // product-outer ordering: same-acc reuse distance = 16 MMAs
            #pragma unroll
            for (int mi = 0; mi < 4; mi++)
                #pragma unroll
                for (int ni = 0; ni < 4; ni++)
                    mma_bf16(acc[mi][ni], aH[mi], bH[ni][0], bH[ni][1]);
            #pragma unroll
            for (int mi = 0; mi < 4; mi++)
                #pragma unroll
                for (int ni = 0; ni < 4; ni++)
                    mma_bf16(acc[mi][ni], aH[mi], bL[ni][0], bL[ni][1]);
            #pragma unroll
            for (int mi = 0; mi < 4; mi++)
                #pragma unroll
                for (int ni = 0; ni < 4; ni++)
                    mma_bf16(acc[mi][ni], aL[mi], bH[ni][0], bH[ni][1]);
        }
    }

    __syncthreads();
    #pragma unroll
    for (int mi = 0; mi < 4; mi++) {
        #pragma unroll
        for (int ni = 0; ni < 4; ni++) {
            int row0 = bm + (wm << 6) + (mi << 4) + (lane >> 2);
            int col  = bn + (wn << 5) + (ni << 3) + ((lane & 3) << 1);
            float b0 = __ldg(bias + col), b1 = __ldg(bias + col + 1);
            #pragma unroll
            for (int half = 0; half < 2; half++) {
                int row = row0 + half * 8;
                float v0 = acc[mi][ni][half * 2 + 0] + b0;
                float v1 = acc[mi][ni][half * 2 + 1] + b1;
                size_t oi = (size_t)row * N + col;
                if (EPI == 0) {
                    float2 ov; ov.x = v0; ov.y = v1;
                    *(float2*)(Cf + oi) = ov;
                } else if (EPI == 2) {
                    float2 rv = *(const float2*)(res + oi);
                    float2 ov; ov.x = v0 + rv.x; ov.y = v1 + rv.y;
                    *(float2*)(Cf + oi) = ov;
                } else {
                    float a0 = (EPI == 1) ? gelu_f(v0) : v0;
                    float a1 = (EPI == 1) ? gelu_f(v1) : v1;
                    __nv_bfloat16 h0, h1, l0, l1;
                    split_bf16(a0, h0, l0); split_bf16(a1, h1, l1);
                    __nv_bfloat162 hh; hh.x = h0; hh.y = h1;
                    __nv_bfloat162 ll; ll.x = l0; ll.y = l1;
                    *(__nv_bfloat162*)(Ch + oi) = hh;
                    *(__nv_bfloat162*)(Cl + oi) = ll;
                }
            }
        }
    }
}

// ------------------------- tensor-core flash attention -----------------------
#define AQ_STRIDE 144
#define SM_QH 0
#define SM_QL 18432
#define SM_KV0 36864
#define KV_STG 36864
#define KOFF_H 0
#define KOFF_L 9216
#define VOFF_H 18432
#define VOFF_L 27648
#define ATT_SMEM (SM_KV0 + 2 * KV_STG)   // 110592

__device__ __forceinline__ void att_load_kv(
    uint32_t base, const __nv_bfloat16* __restrict__ qvh,
    const __nv_bfloat16* __restrict__ qvl, size_t kvrow0, int tid)
{
    const size_t TD3 = 3 * DDIM;
    #pragma unroll
    for (int i = 0; i < 8; i++) {
        int e = tid + (i << 8);
        int t = e >> 9;               // 0 Kh 1 Kl 2 Vh 3 Vl
        int rem = e & 511;
        int r = rem >> 3, c = rem & 7;
        const __nv_bfloat16* p = (t & 1) ? qvl : qvh;
        size_t off = (kvrow0 + r) * TD3 + ((t >> 1) ? 2 * DDIM : DDIM) + (c << 3);
        uint32_t doff = ((t & 1) ? (uint32_t)KOFF_L : 0u) + ((t >> 1) ? (uint32_t)VOFF_H : 0u);
        cp16(base + doff + r * AQ_STRIDE + (c << 4), p + off);
    }
}

__global__ void __launch_bounds__(256, 1) attn_tc(
    const __nv_bfloat16* __restrict__ qvh, const __nv_bfloat16* __restrict__ qvl,
    __nv_bfloat16* __restrict__ oh, __nv_bfloat16* __restrict__ ol)
{
    extern __shared__ __align__(1024) char smem[];
    uint32_t sb = s2u(smem);
    int qt = (int)gridDim.x - 1 - (int)blockIdx.x;
    int b  = blockIdx.y >> 4;
    int h  = blockIdx.y & 15;
    int tid = threadIdx.x, wid = tid >> 5, lane = tid & 31;
    const size_t TD3 = 3 * DDIM;
    size_t qrow0 = (size_t)b * TTOK + (size_t)qt * 128;
    const __nv_bfloat16* qh_head = qvh + h * HDIM;
    const __nv_bfloat16* ql_head = qvl + h * HDIM;

    // Q tile (hi+lo)
    #pragma unroll
    for (int i = 0; i < 8; i++) {
        int e = tid + (i << 8);
        int t = e >> 10;
        int rem = e & 1023;
        int r = rem >> 3, c = rem & 7;
        const __nv_bfloat16* src = (t ? ql_head : qh_head) + (qrow0 + r) * TD3 + (c << 3);
        cp16(sb + (t ? SM_QL : SM_QH) + r * AQ_STRIDE + (c << 4), src);
    }
    att_load_kv(sb + SM_KV0, qh_head, ql_head, (size_t)b * TTOK, tid);
    CP_COMMIT();

    uint32_t qhf[4][4], qlf[4][4];
    float O[8][4];
    #pragma unroll
    for (int n = 0; n < 8; n++)
        #pragma unroll
        for (int e = 0; e < 4; e++) O[n][e] = 0.f;
    float m0 = -1e30f, m1 = -1e30f, l0 = 0.f, l1 = 0.f;

    int bg = lane >> 3, brow = lane & 7;
    int ntiles = 2 * qt + 2;
    bool qloaded = false;

    for (int j = 0; j < ntiles; j++) {
        CP_WAIT0();
        __syncthreads();
        if (j + 1 < ntiles) {
            att_load_kv(sb + SM_KV0 + (uint32_t)((j + 1) & 1) * KV_STG,
                        qh_head, ql_head, (size_t)b * TTOK + (size_t)(j + 1) * 64, tid);
            CP_COMMIT();
        }
        if (!qloaded) {
            qloaded = true;
            #pragma unroll
            for (int kc = 0; kc < 4; kc++) {
                uint32_t aoff = (uint32_t)((wid * 16 + (lane & 15)) * AQ_STRIDE
                                           + ((kc << 4) + ((lane >> 4) << 3)) * 2);
                ldsm4(qhf[kc], sb + SM_QH + aoff);
                ldsm4(qlf[kc], sb + SM_QL + aoff);
            }
        }

        uint32_t kb = sb + SM_KV0 + (uint32_t)(j & 1) * KV_STG;

        float S[8][4];
        #pragma unroll
        for (int n = 0; n < 8; n++)
            #pragma unroll
            for (int e = 0; e < 4; e++) S[n][e] = 0.f;

        #pragma unroll
        for (int p = 0; p < 4; p++) {
            #pragma unroll
            for (int kc = 0; kc < 4; kc++) {
                uint32_t koff = (uint32_t)(((p << 4) + ((bg >> 1) << 3) + brow) * AQ_STRIDE
                                           + ((kc << 4) + ((bg & 1) << 3)) * 2);
                uint32_t rh[4], rl[4];
                ldsm4(rh, kb + KOFF_H + koff);
                ldsm4(rl, kb + KOFF_L + koff);
                mma_bf16(S[2*p],   qhf[kc], rh[0], rh[1]);
                mma_bf16(S[2*p+1], qhf[kc], rh[2], rh[3]);
                mma_bf16(S[2*p],   qhf[kc], rl[0], rl[1]);
                mma_bf16(S[2*p+1], qhf[kc], rl[2], rl[3]);
                mma_bf16(S[2*p],   qlf[kc], rh[0], rh[1]);
                mma_bf16(S[2*p+1], qlf[kc], rh[2], rh[3]);
            }
        }

        int row0 = qt * 128 + wid * 16 + (lane >> 2);
        int row1 = row0 + 8;
        int cbase = j * 64 + ((lane & 3) << 1);
        bool need_mask = (j >= 2 * qt);
        #pragma unroll
        for (int n = 0; n < 8; n++) {
            #pragma unroll
            for (int e = 0; e < 4; e++) S[n][e] *= 0.125f;
            if (need_mask) {
                int c0 = cbase + n * 8;
                if (c0     > row0) S[n][0] = -1e30f;
                if (c0 + 1 > row0) S[n][1] = -1e30f;
                if (c0     > row1) S[n][2] = -1e30f;
                if (c0 + 1 > row1) S[n][3] = -1e30f;
            }
        }

        float mr0 = -1e30f, mr1 = -1e30f;
        #pragma unroll
        for (int n = 0; n < 8; n++) {
            mr0 = fmaxf(mr0, fmaxf(S[n][0], S[n][1]));
            mr1 = fmaxf(mr1, fmaxf(S[n][2], S[n][3]));
        }
        mr0 = fmaxf(mr0, __shfl_xor_sync(0xffffffffu, mr0, 1));
        mr0 = fmaxf(mr0, __shfl_xor_sync(0xffffffffu, mr0, 2));
        mr1 = fmaxf(mr1, __shfl_xor_sync(0xffffffffu, mr1, 1));
        mr1 = fmaxf(mr1, __shfl_xor_sync(0xffffffffu, mr1, 2));
        float mn0 = fmaxf(m0, mr0), mn1 = fmaxf(m1, mr1);
        float alpha0 = __expf(m0 - mn0), alpha1 = __expf(m1 - mn1);
        float sum0 = 0.f, sum1 = 0.f;
        #pragma unroll
        for (int n = 0; n < 8; n++) {
            S[n][0] = __expf(S[n][0] - mn0); sum0 += S[n][0];
            S[n][1] = __expf(S[n][1] - mn0); sum0 += S[n][1];
            S[n][2] = __expf(S[n][2] - mn1); sum1 += S[n][2];
            S[n][3] = __expf(S[n][3] - mn1); sum1 += S[n][3];
        }
        sum0 += __shfl_xor_sync(0xffffffffu, sum0, 1);
        sum0 += __shfl_xor_sync(0xffffffffu, sum0, 2);
        sum1 += __shfl_xor_sync(0xffffffffu, sum1, 1);
        sum1 += __shfl_xor_sync(0xffffffffu, sum1, 2);
        l0 = l0 * alpha0 + sum0;
        l1 = l1 * alpha1 + sum1;
        m0 = mn0; m1 = mn1;
        #pragma unroll
        for (int n = 0; n < 8; n++) {
            O[n][0] *= alpha0; O[n][1] *= alpha0;
            O[n][2] *= alpha1; O[n][3] *= alpha1;
        }

        #pragma unroll
        for (int kc = 0; kc < 4; kc++) {
            uint32_t ph[4], pl[4];
            {
                float v[8] = { S[2*kc][0], S[2*kc][1], S[2*kc][2], S[2*kc][3],
                               S[2*kc+1][0], S[2*kc+1][1], S[2*kc+1][2], S[2*kc+1][3] };
                __nv_bfloat16 hh[8], llq[8];
                #pragma unroll
                for (int e = 0; e < 8; e++) split_bf16(v[e], hh[e], llq[e]);
                #pragma unroll
                for (int e = 0; e < 4; e++) {
                    __nv_bfloat162 t1; t1.x = hh[2*e]; t1.y = hh[2*e+1];
                    __nv_bfloat162 t2; t2.x = llq[2*e]; t2.y = llq[2*e+1];
                    ph[e] = *(uint32_t*)&t1;
                    pl[e] = *(uint32_t*)&t2;
                }
            }
            #pragma unroll
            for (int np = 0; np < 4; np++) {
                uint32_t voff = (uint32_t)(((kc << 4) + ((bg & 1) << 3) + brow) * AQ_STRIDE
                                           + ((np << 4) + ((bg >> 1) << 3)) * 2);
                uint32_t rh[4], rl[4];
                ldsm4t(rh, kb + VOFF_H + voff);
                ldsm4t(rl, kb + VOFF_L + voff);
                mma_bf16(O[2*np],   ph, rh[0], rh[1]);
                mma_bf16(O[2*np+1], ph, rh[2], rh[3]);
                mma_bf16(O[2*np],   ph, rl[0], rl[1]);
                mma_bf16(O[2*np+1], ph, rl[2], rl[3]);
                mma_bf16(O[2*np],   pl, rh[0], rh[1]);
                mma_bf16(O[2*np+1], pl, rh[2], rh[3]);
            }
        }
    }

    float inv0 = 1.0f / l0, inv1 = 1.0f / l1;
    size_t row0g = qrow0 + wid * 16 + (lane >> 2);
    int colb = h * HDIM + ((lane & 3) << 1);
    #pragma unroll
    for (int n = 0; n < 8; n++) {
        int col = colb + n * 8;
        float v0 = O[n][0] * inv0, v1 = O[n][1] * inv0;
        float v2 = O[n][2] * inv1, v3 = O[n][3] * inv1;
        __nv_bfloat16 h0,h1,h2,h3,l0b,l1b,l2b,l3b;
        split_bf16(v0,h0,l0b); split_bf16(v1,h1,l1b);
        split_bf16(v2,h2,l2b); split_bf16(v3,h3,l3b);
        __nv_bfloat162 t;
        t.x = h0; t.y = h1; *(__nv_bfloat162*)(oh + row0g * DDIM + col) = t;
        t.x = l0b; t.y = l1b; *(__nv_bfloat162*)(ol + row0g * DDIM + col) = t;
        t.x = h2; t.y = h3; *(__nv_bfloat162*)(oh + (row0g + 8) * DDIM + col) = t;
        t.x = l2b; t.y = l3b; *(__nv_bfloat162*)(ol + (row0g + 8) * DDIM + col) = t;
    }
}

// ------------------------- launch --------------------------------------------
extern "C" void kernel_launch(void* const* d_in, const int* in_sizes, int n_in,
                              void* d_out, int out_size) {
    const float* x      = (const float*)d_in[0];
    const float* ln1_g  = (const float*)d_in[1];
    const float* ln1_b  = (const float*)d_in[2];
    const float* ln2_g  = (const float*)d_in[3];
    const float* ln2_b  = (const float*)d_in[4];
    const float* w_qkv  = (const float*)d_in[5];
    const float* b_qkv  = (const float*)d_in[6];
    const float* w_o    = (const float*)d_in[7];
    const float* b_o    = (const float*)d_in[8];
    const float* w_fc1  = (const float*)d_in[9];
    const float* b_fc1  = (const float*)d_in[10];
    const float* w_fc2  = (const float*)d_in[11];
    const float* b_fc2  = (const float*)d_in[12];
    float* out = (float*)d_out;

    float *p_x1;
    __nv_bfloat16 *p_ah, *p_al, *p_hh, *p_hl, *p_qvh, *p_qvl;
    __nv_bfloat16 *p_wqh, *p_wql, *p_woh, *p_wol, *p_w1h, *p_w1l, *p_w2h, *p_w2l;
    cudaGetSymbolAddress((void**)&p_x1,  g_x1);
    cudaGetSymbolAddress((void**)&p_ah,  g_ah);
    cudaGetSymbolAddress((void**)&p_al,  g_al);
    cudaGetSymbolAddress((void**)&p_hh,  g_hh);
    cudaGetSymbolAddress((void**)&p_hl,  g_hl);
    cudaGetSymbolAddress((void**)&p_qvh, g_qvh);
    cudaGetSymbolAddress((void**)&p_qvl, g_qvl);
    cudaGetSymbolAddress((void**)&p_wqh, g_wq_h);
    cudaGetSymbolAddress((void**)&p_wql, g_wq_l);
    cudaGetSymbolAddress((void**)&p_woh, g_wo_h);
    cudaGetSymbolAddress((void**)&p_wol, g_wo_l);
    cudaGetSymbolAddress((void**)&p_w1h, g_w1_h);
    cudaGetSymbolAddress((void**)&p_w1l, g_w1_l);
    cudaGetSymbolAddress((void**)&p_w2h, g_w2_h);
    cudaGetSymbolAddress((void**)&p_w2l, g_w2_l);

    cudaFuncSetAttribute(attn_tc, cudaFuncAttributeMaxDynamicSharedMemorySize, ATT_SMEM);
    cudaFuncSetAttribute(hmma_gemm<1>, cudaFuncAttributeMaxDynamicSharedMemorySize, GEMM_SMEM);
    cudaFuncSetAttribute(hmma_gemm<2>, cudaFuncAttributeMaxDynamicSharedMemorySize, GEMM_SMEM);
    cudaFuncSetAttribute(hmma_gemm<3>, cudaFuncAttributeMaxDynamicSharedMemorySize, GEMM_SMEM);

    dim3 wblk(32, 8);
    wsplit_t<<<dim3(3 * DDIM / 32, DDIM / 32), wblk>>>(w_qkv, p_wqh, p_wql, DDIM, 3 * DDIM);
    wsplit_t<<<dim3(DDIM / 32, DDIM / 32), wblk>>>(w_o, p_woh, p_wol, DDIM, DDIM);
    wsplit_t<<<dim3(4 * DDIM / 32, DDIM / 32), wblk>>>(w_fc1, p_w1h, p_w1l, DDIM, 4 * DDIM);
    wsplit_t<<<dim3(DDIM / 32, 4 * DDIM / 32), wblk>>>(w_fc2, p_w2h, p_w2l, 4 * DDIM, DDIM);

    ln_split<<<BT, 256>>>(x, ln1_g, ln1_b, p_ah, p_al);
    hmma_gemm<3><<<dim3(3 * DDIM / 128, BT / 128), 256, GEMM_SMEM>>>(
        p_ah, p_al, p_wqh, p_wql, b_qkv, nullptr, nullptr, p_qvh, p_qvl, 3 * DDIM, DDIM);
    attn_tc<<<dim3(TTOK / 128, BB * NH), 256, ATT_SMEM>>>(p_qvh, p_qvl, p_ah, p_al);
    hmma_gemm<2><<<dim3(DDIM / 128, BT / 128), 256, GEMM_SMEM>>>(
        p_ah, p_al, p_woh, p_wol, b_o, x, p_x1, nullptr, nullptr, DDIM, DDIM);
    ln_split<<<BT, 256>>>(p_x1, ln2_g, ln2_b, p_ah, p_al);
    hmma_gemm<1><<<dim3(4 * DDIM / 128, BT / 128), 256, GEMM_SMEM>>>(
        p_ah, p_al, p_w1h, p_w1l, b_fc1, nullptr, nullptr, p_hh, p_hl, 4 * DDIM, DDIM);
    hmma_gemm<2><<<dim3(DDIM / 128, BT / 128), 256, GEMM_SMEM>>>(
        p_hh, p_hl, p_w2h, p_w2l, b_fc2, p_x1, out, nullptr, nullptr, DDIM, 4 * DDIM);
}

// round 8
// speedup vs baseline: 5.6400x; 2.1083x over previous
#include <cuda_runtime.h>
#include <cuda_fp16.h>
#include <math.h>
#include <stdint.h>

#define BB   2
#define TTOK 2048
#define DDIM 1024
#define NH   16
#define HDIM 64
#define BT   (BB*TTOK)   // 4096

// scratch (static device arrays)
__device__ float  g_x1 [BT * DDIM];          // fp32 residual after attn
__device__ __half g_a16[BT * DDIM];          // fp16 activations (ln1/attn/ln2)
__device__ __half g_qv16[BT * 3 * DDIM];     // fp16 qkv
__device__ __half g_h16[BT * 4 * DDIM];      // fp16 gelu(h)
__device__ __half g_wq16[3 * DDIM * DDIM];
__device__ __half g_wo16[DDIM * DDIM];
__device__ __half g_w116[4 * DDIM * DDIM];
__device__ __half g_w216[4 * DDIM * DDIM];

__device__ __forceinline__ uint32_t s2u(const void* p) {
    uint32_t a;
    asm("{ .reg .u64 t; cvta.to.shared.u64 t, %1; cvt.u32.u64 %0, t; }" : "=r"(a) : "l"(p));
    return a;
}
__device__ __forceinline__ void cp16(uint32_t dst, const void* src) {
    asm volatile("cp.async.cg.shared.global [%0], [%1], 16;" :: "r"(dst), "l"(src));
}
#define CP_COMMIT() asm volatile("cp.async.commit_group;" ::: "memory")
#define CP_WAIT0()  asm volatile("cp.async.wait_group 0;" ::: "memory")
#define CP_WAIT1()  asm volatile("cp.async.wait_group 1;" ::: "memory")

__device__ __forceinline__ void ldsm4(uint32_t* r, uint32_t addr) {
    asm volatile("ldmatrix.sync.aligned.m8n8.x4.shared.b16 {%0,%1,%2,%3}, [%4];"
                 : "=r"(r[0]), "=r"(r[1]), "=r"(r[2]), "=r"(r[3]) : "r"(addr));
}
__device__ __forceinline__ void ldsm4t(uint32_t* r, uint32_t addr) {
    asm volatile("ldmatrix.sync.aligned.m8n8.x4.trans.shared.b16 {%0,%1,%2,%3}, [%4];"
                 : "=r"(r[0]), "=r"(r[1]), "=r"(r[2]), "=r"(r[3]) : "r"(addr));
}
// non-volatile: compiler may interleave HMMAs across accumulators
__device__ __forceinline__ void mma_f16(float* c, const uint32_t* a,
                                        uint32_t b0, uint32_t b1) {
    asm("mma.sync.aligned.m16n8k16.row.col.f32.f16.f16.f32 "
        "{%0,%1,%2,%3}, {%4,%5,%6,%7}, {%8,%9}, {%0,%1,%2,%3};"
        : "+f"(c[0]), "+f"(c[1]), "+f"(c[2]), "+f"(c[3])
        : "r"(a[0]), "r"(a[1]), "r"(a[2]), "r"(a[3]), "r"(b0), "r"(b1));
}

__device__ __forceinline__ float gelu_f(float x) {
    float x3 = x * x * x;
    return 0.5f * x * (1.0f + tanhf(0.7978845608028654f * (x + 0.044715f * x3)));
}

// weight transpose -> fp16 : W[K,N] fp32 -> O[N,K] fp16
__global__ void wtrans16(const float* __restrict__ W, __half* __restrict__ O,
                         int K, int N) {
    __shared__ float t[32][33];
    int nx = blockIdx.x * 32, kx = blockIdx.y * 32;
    int tx = threadIdx.x, ty = threadIdx.y;   // 32 x 8
    #pragma unroll
    for (int i = 0; i < 32; i += 8)
        t[ty + i][tx] = W[(size_t)(kx + ty + i) * N + nx + tx];
    __syncthreads();
    #pragma unroll
    for (int i = 0; i < 32; i += 8)
        O[(size_t)(nx + ty + i) * K + kx + tx] = __float2half(t[tx][ty + i]);
}

// LayerNorm -> fp16
__global__ void ln_h(const float* __restrict__ x, const float* __restrict__ g,
                     const float* __restrict__ b, __half* __restrict__ o) {
    int row = blockIdx.x;
    int tid = threadIdx.x;
    float4 v = ((const float4*)(x + (size_t)row * DDIM))[tid];
    float s  = v.x + v.y + v.z + v.w;
    float ss = v.x*v.x + v.y*v.y + v.z*v.z + v.w*v.w;
    #pragma unroll
    for (int off = 16; off > 0; off >>= 1) {
        s  += __shfl_xor_sync(0xffffffffu, s,  off);
        ss += __shfl_xor_sync(0xffffffffu, ss, off);
    }
    __shared__ float rs[8], rss[8];
    int w = tid >> 5, ln = tid & 31;
    if (ln == 0) { rs[w] = s; rss[w] = ss; }
    __syncthreads();
    float tot = 0.f, tots = 0.f;
    #pragma unroll
    for (int i = 0; i < 8; i++) { tot += rs[i]; tots += rss[i]; }
    float mu  = tot * (1.0f / DDIM);
    float var = tots * (1.0f / DDIM) - mu * mu;
    float inv = rsqrtf(var + 1e-5f);
    float4 gg = ((const float4*)g)[tid];
    float4 bb = ((const float4*)b)[tid];
    float r0 = (v.x - mu) * inv * gg.x + bb.x;
    float r1 = (v.y - mu) * inv * gg.y + bb.y;
    float r2 = (v.z - mu) * inv * gg.z + bb.z;
    float r3 = (v.w - mu) * inv * gg.w + bb.w;
    size_t base = (size_t)row * DDIM + tid * 4;
    *(__half2*)(o + base)     = __floats2half2_rn(r0, r1);
    *(__half2*)(o + base + 2) = __floats2half2_rn(r2, r3);
}

// HMMA fp16 GEMM: C[M,N] = A[M,K] @ B[N,K]^T + bias
// 128x128 block, 8 warps (2x4), warp 64x32, K-chunk 64, 3-stage cp.async.
// EPI: 1 gelu->fp16 / 2 +res fp32 / 3 plain fp16
#define ROWB   144
#define OFF_A  0
#define OFF_B  (128*144)
#define STG    (2*128*144)
#define GEMM_SMEM (3 * STG)

__device__ __forceinline__ void load_stage(
    uint32_t st, const __half* __restrict__ A, const __half* __restrict__ B,
    int K, int bm, int bn, int k0, int tid)
{
    #pragma unroll
    for (int j = 0; j < 4; j++) {
        int o = tid + (j << 8);
        int r = o >> 3, c = o & 7;
        uint32_t so = (uint32_t)(r * ROWB + (c << 4));
        cp16(st + OFF_A + so, A + (size_t)(bm + r) * K + k0 + (c << 3));
        cp16(st + OFF_B + so, B + (size_t)(bn + r) * K + k0 + (c << 3));
    }
}

template<int EPI>
__global__ void __launch_bounds__(256, 1) hmma_gemm(
    const __half* __restrict__ A, const __half* __restrict__ B,
    const float* __restrict__ bias, const float* __restrict__ res,
    float* __restrict__ Cf, __half* __restrict__ Ch, int N, int K)
{
    extern __shared__ __align__(1024) char smem[];
    uint32_t sb = s2u(smem);
    int tid = threadIdx.x, wid = tid >> 5, lane = tid & 31;
    int wm = wid & 1, wn = wid >> 1;
    int bm = blockIdx.y << 7, bn = blockIdx.x << 7;

    float acc[4][4][4];
    #pragma unroll
    for (int mi = 0; mi < 4; mi++)
        #pragma unroll
        for (int ni = 0; ni < 4; ni++)
            #pragma unroll
            for (int e = 0; e < 4; e++) acc[mi][ni][e] = 0.f;

    int nch = K >> 6;
    load_stage(sb,       A, B, K, bm, bn, 0,  tid); CP_COMMIT();
    load_stage(sb + STG, A, B, K, bm, bn, 64, tid); CP_COMMIT();

    int arow = lane & 15;
    int acol = (lane >> 4) << 3;
    int bg   = lane >> 3;
    int brow = lane & 7;

    for (int i = 0; i < nch; i++) {
        CP_WAIT1();
        __syncthreads();
        if (i + 2 < nch) {
            load_stage(sb + (uint32_t)((i + 2) % 3) * STG,
                       A, B, K, bm, bn, (i + 2) << 6, tid);
            CP_COMMIT();
        }
        uint32_t st = sb + (uint32_t)(i % 3) * STG;
        #pragma unroll
        for (int ks = 0; ks < 4; ks++) {
            uint32_t aF[4][4];
            #pragma unroll
            for (int mi = 0; mi < 4; mi++) {
                uint32_t off = (uint32_t)(((wm << 6) + (mi << 4) + arow) * ROWB
                                          + ((ks << 4) + acol) * 2);
                ldsm4(aF[mi], st + OFF_A + off);
            }
            uint32_t bF[4][2];
            #pragma unroll
            for (int np = 0; np < 2; np++) {
                uint32_t off = (uint32_t)(((wn << 5) + (np << 4) + ((bg >> 1) << 3) + brow) * ROWB
                                          + ((ks << 4) + ((bg & 1) << 3)) * 2);
                uint32_t r[4];
                ldsm4(r, st + OFF_B + off);
                bF[2*np][0]   = r[0]; bF[2*np][1]   = r[1];
                bF[2*np+1][0] = r[2]; bF[2*np+1][1] = r[3];
            }
            #pragma unroll
            for (int mi = 0; mi < 4; mi++)
                #pragma unroll
                for (int ni = 0; ni < 4; ni++)
                    mma_f16(acc[mi][ni], aF[mi], bF[ni][0], bF[ni][1]);
        }
    }

    __syncthreads();
    #pragma unroll
    for (int mi = 0; mi < 4; mi++) {
        #pragma unroll
        for (int ni = 0; ni < 4; ni++) {
            int row0 = bm + (wm << 6) + (mi << 4) + (lane >> 2);
            int col  = bn + (wn << 5) + (ni << 3) + ((lane & 3) << 1);
            float b0 = __ldg(bias + col), b1 = __ldg(bias + col + 1);
            #pragma unroll
            for (int hf = 0; hf < 2; hf++) {
                int row = row0 + hf * 8;
                float v0 = acc[mi][ni][hf * 2 + 0] + b0;
                float v1 = acc[mi][ni][hf * 2 + 1] + b1;
                size_t oi = (size_t)row * N + col;
                if (EPI == 2) {
                    float2 rv = *(const float2*)(res + oi);
                    float2 ov; ov.x = v0 + rv.x; ov.y = v1 + rv.y;
                    *(float2*)(Cf + oi) = ov;
                } else {
                    float a0 = (EPI == 1) ? gelu_f(v0) : v0;
                    float a1 = (EPI == 1) ? gelu_f(v1) : v1;
                    *(__half2*)(Ch + oi) = __floats2half2_rn(a0, a1);
                }
            }
        }
    }
}

// fp16 tensor-core flash attention: BQ=128 (8 warps x 16 rows), BK=64, hd=64
#define AQ_STRIDE 144
#define SM_Q   0
#define SM_KV0 18432
#define KV_STG 18432
#define VOFF   9216
#define ATT_SMEM (SM_KV0 + 2 * KV_STG)

__device__ __forceinline__ void att_load_kv(
    uint32_t base, const __half* __restrict__ qv, size_t kvrow0, int tid)
{
    const size_t TD3 = 3 * DDIM;
    #pragma unroll
    for (int i = 0; i < 4; i++) {
        int e = tid + (i << 8);
        int t = e >> 9;               // 0 K, 1 V
        int rem = e & 511;
        int r = rem >> 3, c = rem & 7;
        size_t off = (kvrow0 + r) * TD3 + (t ? 2 * DDIM : DDIM) + (c << 3);
        cp16(base + (t ? (uint32_t)VOFF : 0u) + r * AQ_STRIDE + (c << 4), qv + off);
    }
}

__global__ void __launch_bounds__(256, 1) attn_tc(
    const __half* __restrict__ qv, __half* __restrict__ o16)
{
    extern __shared__ __align__(1024) char smem[];
    uint32_t sb = s2u(smem);
    int qt = (int)gridDim.x - 1 - (int)blockIdx.x;
    int b  = blockIdx.y >> 4;
    int h  = blockIdx.y & 15;
    int tid = threadIdx.x, wid = tid >> 5, lane = tid & 31;
    const size_t TD3 = 3 * DDIM;
    size_t qrow0 = (size_t)b * TTOK + (size_t)qt * 128;
    const __half* qv_head = qv + h * HDIM;

    // Q tile 128x64 fp16
    #pragma unroll
    for (int i = 0; i < 4; i++) {
        int e = tid + (i << 8);
        int r = e >> 3, c = e & 7;
        cp16(sb + SM_Q + r * AQ_STRIDE + (c << 4),
             qv_head + (qrow0 + r) * TD3 + (c << 3));
    }
    att_load_kv(sb + SM_KV0, qv_head, (size_t)b * TTOK, tid);
    CP_COMMIT();

    uint32_t qf[4][4];
    float O[8][4];
    #pragma unroll
    for (int n = 0; n < 8; n++)
        #pragma unroll
        for (int e = 0; e < 4; e++) O[n][e] = 0.f;
    float m0 = -1e30f, m1 = -1e30f, l0 = 0.f, l1 = 0.f;

    int bg = lane >> 3, brow = lane & 7;
    int ntiles = 2 * qt + 2;
    bool qloaded = false;

    for (int j = 0; j < ntiles; j++) {
        CP_WAIT0();
        __syncthreads();
        if (j + 1 < ntiles) {
            att_load_kv(sb + SM_KV0 + (uint32_t)((j + 1) & 1) * KV_STG,
                        qv_head, (size_t)b * TTOK + (size_t)(j + 1) * 64, tid);
            CP_COMMIT();
        }
        if (!qloaded) {
            qloaded = true;
            #pragma unroll
            for (int kc = 0; kc < 4; kc++) {
                uint32_t aoff = (uint32_t)((wid * 16 + (lane & 15)) * AQ_STRIDE
                                           + ((kc << 4) + ((lane >> 4) << 3)) * 2);
                ldsm4(qf[kc], sb + SM_Q + aoff);
            }
        }

        uint32_t kb = sb + SM_KV0 + (uint32_t)(j & 1) * KV_STG;

        float S[8][4];
        #pragma unroll
        for (int n = 0; n < 8; n++)
            #pragma unroll
            for (int e = 0; e < 4; e++) S[n][e] = 0.f;
        #pragma unroll
        for (int p = 0; p < 4; p++) {
            #pragma unroll
            for (int kc = 0; kc < 4; kc++) {
                uint32_t koff = (uint32_t)(((p << 4) + ((bg >> 1) << 3) + brow) * AQ_STRIDE
                                           + ((kc << 4) + ((bg & 1) << 3)) * 2);
                uint32_t rh[4];
                ldsm4(rh, kb + koff);
                mma_f16(S[2*p],   qf[kc], rh[0], rh[1]);
                mma_f16(S[2*p+1], qf[kc], rh[2], rh[3]);
            }
        }

        int row0 = qt * 128 + wid * 16 + (lane >> 2);
        int row1 = row0 + 8;
        int cbase = j * 64 + ((lane & 3) << 1);
        bool need_mask = (j >= 2 * qt);
        #pragma unroll
        for (int n = 0; n < 8; n++) {
            #pragma unroll
            for (int e = 0; e < 4; e++) S[n][e] *= 0.125f;
            if (need_mask) {
                int c0 = cbase + n * 8;
                if (c0     > row0) S[n][0] = -1e30f;
                if (c0 + 1 > row0) S[n][1] = -1e30f;
                if (c0     > row1) S[n][2] = -1e30f;
                if (c0 + 1 > row1) S[n][3] = -1e30f;
            }
        }

        float mr0 = -1e30f, mr1 = -1e30f;
        #pragma unroll
        for (int n = 0; n < 8; n++) {
            mr0 = fmaxf(mr0, fmaxf(S[n][0], S[n][1]));
            mr1 = fmaxf(mr1, fmaxf(S[n][2], S[n][3]));
        }
        mr0 = fmaxf(mr0, __shfl_xor_sync(0xffffffffu, mr0, 1));
        mr0 = fmaxf(mr0, __shfl_xor_sync(0xffffffffu, mr0, 2));
        mr1 = fmaxf(mr1, __shfl_xor_sync(0xffffffffu, mr1, 1));
        mr1 = fmaxf(mr1, __shfl_xor_sync(0xffffffffu, mr1, 2));
        float mn0 = fmaxf(m0, mr0), mn1 = fmaxf(m1, mr1);
        float alpha0 = __expf(m0 - mn0), alpha1 = __expf(m1 - mn1);
        float sum0 = 0.f, sum1 = 0.f;
        #pragma unroll
        for (int n = 0; n < 8; n++) {
            S[n][0] = __expf(S[n][0] - mn0); sum0 += S[n][0];
            S[n][1] = __expf(S[n][1] - mn0); sum0 += S[n][1];
            S[n][2] = __expf(S[n][2] - mn1); sum1 += S[n][2];
            S[n][3] = __expf(S[n][3] - mn1); sum1 += S[n][3];
        }
        sum0 += __shfl_xor_sync(0xffffffffu, sum0, 1);
        sum0 += __shfl_xor_sync(0xffffffffu, sum0, 2);
        sum1 += __shfl_xor_sync(0xffffffffu, sum1, 1);
        sum1 += __shfl_xor_sync(0xffffffffu, sum1, 2);
        l0 = l0 * alpha0 + sum0;
        l1 = l1 * alpha1 + sum1;
        m0 = mn0; m1 = mn1;
        #pragma unroll
        for (int n = 0; n < 8; n++) {
            O[n][0] *= alpha0; O[n][1] *= alpha0;
            O[n][2] *= alpha1; O[n][3] *= alpha1;
        }

        #pragma unroll
        for (int kc = 0; kc < 4; kc++) {
            uint32_t pf[4];
            __half2 t0 = __floats2half2_rn(S[2*kc][0],   S[2*kc][1]);
            __half2 t1 = __floats2half2_rn(S[2*kc][2],   S[2*kc][3]);
            __half2 t2 = __floats2half2_rn(S[2*kc+1][0], S[2*kc+1][1]);
            __half2 t3 = __floats2half2_rn(S[2*kc+1][2], S[2*kc+1][3]);
            pf[0] = *(uint32_t*)&t0;
            pf[1] = *(uint32_t*)&t1;
            pf[2] = *(uint32_t*)&t2;
            pf[3] = *(uint32_t*)&t3;
            #pragma unroll
            for (int np = 0; np < 4; np++) {
                uint32_t voff = (uint32_t)(((kc << 4) + ((bg & 1) << 3) + brow) * AQ_STRIDE
                                           + ((np << 4) + ((bg >> 1) << 3)) * 2);
                uint32_t rv[4];
                ldsm4t(rv, kb + VOFF + voff);
                mma_f16(O[2*np],   pf, rv[0], rv[1]);
                mma_f16(O[2*np+1], pf, rv[2], rv[3]);
            }
        }
    }

    float inv0 = 1.0f / l0, inv1 = 1.0f / l1;
    size_t row0g = qrow0 + wid * 16 + (lane >> 2);
    int colb = h * HDIM + ((lane & 3) << 1);
    #pragma unroll
    for (int n = 0; n < 8; n++) {
        int col = colb + n * 8;
        *(__half2*)(o16 + row0g * DDIM + col) =
            __floats2half2_rn(O[n][0] * inv0, O[n][1] * inv0);
        *(__half2*)(o16 + (row0g + 8) * DDIM + col) =
            __floats2half2_rn(O[n][2] * inv1, O[n][3] * inv1);
    }
}

extern "C" void kernel_launch(void* const* d_in, const int* in_sizes, int n_in,
                              void* d_out, int out_size) {
    const float* x      = (const float*)d_in[0];
    const float* ln1_g  = (const float*)d_in[1];
    const float* ln1_b  = (const float*)d_in[2];
    const float* ln2_g  = (const float*)d_in[3];
    const float* ln2_b  = (const float*)d_in[4];
    const float* w_qkv  = (const float*)d_in[5];
    const float* b_qkv  = (const float*)d_in[6];
    const float* w_o    = (const float*)d_in[7];
    const float* b_o    = (const float*)d_in[8];
    const float* w_fc1  = (const float*)d_in[9];
    const float* b_fc1  = (const float*)d_in[10];
    const float* w_fc2  = (const float*)d_in[11];
    const float* b_fc2  = (const float*)d_in[12];
    float* out = (float*)d_out;

    float* p_x1;
    __half *p_a16, *p_qv16, *p_h16, *p_wq, *p_wo, *p_w1, *p_w2;
    cudaGetSymbolAddress((void**)&p_x1,   g_x1);
    cudaGetSymbolAddress((void**)&p_a16,  g_a16);
    cudaGetSymbolAddress((void**)&p_qv16, g_qv16);
    cudaGetSymbolAddress((void**)&p_h16,  g_h16);
    cudaGetSymbolAddress((void**)&p_wq,   g_wq16);
    cudaGetSymbolAddress((void**)&p_wo,   g_wo16);
    cudaGetSymbolAddress((void**)&p_w1,   g_w116);
    cudaGetSymbolAddress((void**)&p_w2,   g_w216);

    cudaFuncSetAttribute(attn_tc, cudaFuncAttributeMaxDynamicSharedMemorySize, ATT_SMEM);
    cudaFuncSetAttribute(hmma_gemm<1>, cudaFuncAttributeMaxDynamicSharedMemorySize, GEMM_SMEM);
    cudaFuncSetAttribute(hmma_gemm<2>, cudaFuncAttributeMaxDynamicSharedMemorySize, GEMM_SMEM);
    cudaFuncSetAttribute(hmma_gemm<3>, cudaFuncAttributeMaxDynamicSharedMemorySize, GEMM_SMEM);

    dim3 wblk(32, 8);
    wtrans16<<<dim3(3 * DDIM / 32, DDIM / 32), wblk>>>(w_qkv, p_wq, DDIM, 3 * DDIM);
    wtrans16<<<dim3(DDIM / 32, DDIM / 32), wblk>>>(w_o, p_wo, DDIM, DDIM);
    wtrans16<<<dim3(4 * DDIM / 32, DDIM / 32), wblk>>>(w_fc1, p_w1, DDIM, 4 * DDIM);
    wtrans16<<<dim3(DDIM / 32, 4 * DDIM / 32), wblk>>>(w_fc2, p_w2, 4 * DDIM, DDIM);

    ln_h<<<BT, 256>>>(x, ln1_g, ln1_b, p_a16);
    hmma_gemm<3><<<dim3(3 * DDIM / 128, BT / 128), 256, GEMM_SMEM>>>(
        p_a16, p_wq, b_qkv, nullptr, nullptr, p_qv16, 3 * DDIM, DDIM);
    attn_tc<<<dim3(TTOK / 128, BB * NH), 256, ATT_SMEM>>>(p_qv16, p_a16);
    hmma_gemm<2><<<dim3(DDIM / 128, BT / 128), 256, GEMM_SMEM>>>(
        p_a16, p_wo, b_o, x, p_x1, nullptr, DDIM, DDIM);
    ln_h<<<BT, 256>>>(p_x1, ln2_g, ln2_b, p_a16);
    hmma_gemm<1><<<dim3(4 * DDIM / 128, BT / 128), 256, GEMM_SMEM>>>(
        p_a16, p_w1, b_fc1, nullptr, nullptr, p_h16, 4 * DDIM, DDIM);
    hmma_gemm<2><<<dim3(DDIM / 128, BT / 128), 256, GEMM_SMEM>>>(
        p_h16, p_w2, b_fc2, p_x1, out, nullptr, DDIM, 4 * DDIM);
}

// round 9
// speedup vs baseline: 5.9951x; 1.0630x over previous
#include <cuda_runtime.h>
#include <cuda_fp16.h>
#include <math.h>
#include <stdint.h>

#define BB   2
#define TTOK 2048
#define DDIM 1024
#define NH   16
#define HDIM 64
#define BT   (BB*TTOK)   // 4096

// scratch (static device arrays)
__device__ float  g_x1 [BT * DDIM];          // fp32 residual after attn
__device__ __half g_a16[BT * DDIM];          // fp16 activations (ln1/attn/ln2)
__device__ __half g_qv16[BT * 3 * DDIM];     // fp16 qkv
__device__ __half g_h16[BT * 4 * DDIM];      // fp16 gelu(h)
__device__ __half g_wq16[3 * DDIM * DDIM];
__device__ __half g_wo16[DDIM * DDIM];
__device__ __half g_w116[4 * DDIM * DDIM];
__device__ __half g_w216[4 * DDIM * DDIM];

__device__ __forceinline__ uint32_t s2u(const void* p) {
    uint32_t a;
    asm("{ .reg .u64 t; cvta.to.shared.u64 t, %1; cvt.u32.u64 %0, t; }" : "=r"(a) : "l"(p));
    return a;
}
__device__ __forceinline__ void cp16(uint32_t dst, const void* src) {
    asm volatile("cp.async.cg.shared.global [%0], [%1], 16;" :: "r"(dst), "l"(src));
}
#define CP_COMMIT() asm volatile("cp.async.commit_group;" ::: "memory")
#define CP_WAIT0()  asm volatile("cp.async.wait_group 0;" ::: "memory")
#define CP_WAIT1()  asm volatile("cp.async.wait_group 1;" ::: "memory")

__device__ __forceinline__ void ldsm4(uint32_t* r, uint32_t addr) {
    asm volatile("ldmatrix.sync.aligned.m8n8.x4.shared.b16 {%0,%1,%2,%3}, [%4];"
                 : "=r"(r[0]), "=r"(r[1]), "=r"(r[2]), "=r"(r[3]) : "r"(addr));
}
__device__ __forceinline__ void ldsm4t(uint32_t* r, uint32_t addr) {
    asm volatile("ldmatrix.sync.aligned.m8n8.x4.trans.shared.b16 {%0,%1,%2,%3}, [%4];"
                 : "=r"(r[0]), "=r"(r[1]), "=r"(r[2]), "=r"(r[3]) : "r"(addr));
}
// non-volatile: compiler may interleave HMMAs across accumulators
__device__ __forceinline__ void mma_f16(float* c, const uint32_t* a,
                                        uint32_t b0, uint32_t b1) {
    asm("mma.sync.aligned.m16n8k16.row.col.f32.f16.f16.f32 "
        "{%0,%1,%2,%3}, {%4,%5,%6,%7}, {%8,%9}, {%0,%1,%2,%3};"
        : "+f"(c[0]), "+f"(c[1]), "+f"(c[2]), "+f"(c[3])
        : "r"(a[0]), "r"(a[1]), "r"(a[2]), "r"(a[3]), "r"(b0), "r"(b1));
}

__device__ __forceinline__ float gelu_f(float x) {
    float x3 = x * x * x;
    return 0.5f * x * (1.0f + tanhf(0.7978845608028654f * (x + 0.044715f * x3)));
}

// weight transpose -> fp16 : W[K,N] fp32 -> O[N,K] fp16 (vectorized half2 stores)
__global__ void wtrans16(const float* __restrict__ W, __half* __restrict__ O,
                         int K, int N) {
    __shared__ float t[32][33];
    int nx = blockIdx.x * 32, kx = blockIdx.y * 32;
    int tid = threadIdx.x;                    // 256 threads
    int lx = tid & 31, ly = tid >> 5;         // 32 x 8
    #pragma unroll
    for (int i = 0; i < 32; i += 8)
        t[ly + i][lx] = W[(size_t)(kx + ly + i) * N + nx + lx];
    __syncthreads();
    // store: n_local = tid>>4 (+16), k_local = (tid&15)*2 ; half2 along K
    int nl = tid >> 4, kl = (tid & 15) << 1;
    #pragma unroll
    for (int pass = 0; pass < 2; pass++) {
        int n = nl + pass * 16;
        __half2 v = __floats2half2_rn(t[kl][n], t[kl + 1][n]);
        *(__half2*)(O + (size_t)(nx + n) * K + kx + kl) = v;
    }
}

// LayerNorm -> fp16
__global__ void ln_h(const float* __restrict__ x, const float* __restrict__ g,
                     const float* __restrict__ b, __half* __restrict__ o) {
    int row = blockIdx.x;
    int tid = threadIdx.x;
    float4 v = ((const float4*)(x + (size_t)row * DDIM))[tid];
    float s  = v.x + v.y + v.z + v.w;
    float ss = v.x*v.x + v.y*v.y + v.z*v.z + v.w*v.w;
    #pragma unroll
    for (int off = 16; off > 0; off >>= 1) {
        s  += __shfl_xor_sync(0xffffffffu, s,  off);
        ss += __shfl_xor_sync(0xffffffffu, ss, off);
    }
    __shared__ float rs[8], rss[8];
    int w = tid >> 5, ln = tid & 31;
    if (ln == 0) { rs[w] = s; rss[w] = ss; }
    __syncthreads();
    float tot = 0.f, tots = 0.f;
    #pragma unroll
    for (int i = 0; i < 8; i++) { tot += rs[i]; tots += rss[i]; }
    float mu  = tot * (1.0f / DDIM);
    float var = tots * (1.0f / DDIM) - mu * mu;
    float inv = rsqrtf(var + 1e-5f);
    float4 gg = ((const float4*)g)[tid];
    float4 bb = ((const float4*)b)[tid];
    float r0 = (v.x - mu) * inv * gg.x + bb.x;
    float r1 = (v.y - mu) * inv * gg.y + bb.y;
    float r2 = (v.z - mu) * inv * gg.z + bb.z;
    float r3 = (v.w - mu) * inv * gg.w + bb.w;
    size_t base = (size_t)row * DDIM + tid * 4;
    *(__half2*)(o + base)     = __floats2half2_rn(r0, r1);
    *(__half2*)(o + base + 2) = __floats2half2_rn(r2, r3);
}

// HMMA fp16 GEMM: C[M,N] = A[M,K] @ B[N,K]^T + bias
// 128x256 block, 8 warps (2Mx4N), warp tile 64x64, K-chunk 64, 2-stage cp.async.
// EPI: 1 gelu->fp16 / 2 +res fp32 / 3 plain fp16
#define ROWB   144
#define OFF_A  0
#define OFF_B  (128*144)
#define STG    ((128+256)*144)          // 55296
#define GEMM_SMEM (2 * STG)             // 110592

__device__ __forceinline__ void load_stage(
    uint32_t st, const __half* __restrict__ A, const __half* __restrict__ B,
    int K, int bm, int bn, int k0, int tid)
{
    #pragma unroll
    for (int j = 0; j < 4; j++) {                 // A: 128 rows x 8 x 16B
        int o = tid + (j << 8);
        int r = o >> 3, c = o & 7;
        cp16(st + OFF_A + (uint32_t)(r * ROWB + (c << 4)),
             A + (size_t)(bm + r) * K + k0 + (c << 3));
    }
    #pragma unroll
    for (int j = 0; j < 8; j++) {                 // B: 256 rows x 8 x 16B
        int o = tid + (j << 8);
        int r = o >> 3, c = o & 7;
        cp16(st + OFF_B + (uint32_t)(r * ROWB + (c << 4)),
             B + (size_t)(bn + r) * K + k0 + (c << 3));
    }
}

template<int EPI>
__global__ void __launch_bounds__(256, 1) hmma_gemm(
    const __half* __restrict__ A, const __half* __restrict__ B,
    const float* __restrict__ bias, const float* __restrict__ res,
    float* __restrict__ Cf, __half* __restrict__ Ch, int N, int K)
{
    extern __shared__ __align__(1024) char smem[];
    uint32_t sb = s2u(smem);
    int tid = threadIdx.x, wid = tid >> 5, lane = tid & 31;
    int wm = wid & 1, wn = wid >> 1;      // 2(M) x 4(N), warp tile 64x64
    int bm = blockIdx.y << 7, bn = blockIdx.x << 8;

    float acc[4][8][4];
    #pragma unroll
    for (int mi = 0; mi < 4; mi++)
        #pragma unroll
        for (int ni = 0; ni < 8; ni++)
            #pragma unroll
            for (int e = 0; e < 4; e++) acc[mi][ni][e] = 0.f;

    int nch = K >> 6;
    load_stage(sb, A, B, K, bm, bn, 0, tid);
    CP_COMMIT();

    int arow = lane & 15;
    int acol = (lane >> 4) << 3;
    int bg   = lane >> 3;
    int brow = lane & 7;

    for (int i = 0; i < nch; i++) {
        CP_WAIT0();
        __syncthreads();
        if (i + 1 < nch) {
            load_stage(sb + (uint32_t)((i + 1) & 1) * STG,
                       A, B, K, bm, bn, (i + 1) << 6, tid);
            CP_COMMIT();
        }
        uint32_t st = sb + (uint32_t)(i & 1) * STG;
        #pragma unroll
        for (int ks = 0; ks < 4; ks++) {
            uint32_t aF[4][4];
            #pragma unroll
            for (int mi = 0; mi < 4; mi++) {
                uint32_t off = (uint32_t)(((wm << 6) + (mi << 4) + arow) * ROWB
                                          + ((ks << 4) + acol) * 2);
                ldsm4(aF[mi], st + OFF_A + off);
            }
            uint32_t bF[8][2];
            #pragma unroll
            for (int np = 0; np < 4; np++) {
                uint32_t off = (uint32_t)(((wn << 6) + (np << 4) + ((bg >> 1) << 3) + brow) * ROWB
                                          + ((ks << 4) + ((bg & 1) << 3)) * 2);
                uint32_t r[4];
                ldsm4(r, st + OFF_B + off);
                bF[2*np][0]   = r[0]; bF[2*np][1]   = r[1];
                bF[2*np+1][0] = r[2]; bF[2*np+1][1] = r[3];
            }
            #pragma unroll
            for (int mi = 0; mi < 4; mi++)
                #pragma unroll
                for (int ni = 0; ni < 8; ni++)
                    mma_f16(acc[mi][ni], aF[mi], bF[ni][0], bF[ni][1]);
        }
    }

    __syncthreads();
    #pragma unroll
    for (int mi = 0; mi < 4; mi++) {
        #pragma unroll
        for (int ni = 0; ni < 8; ni++) {
            int row0 = bm + (wm << 6) + (mi << 4) + (lane >> 2);
            int col  = bn + (wn << 6) + (ni << 3) + ((lane & 3) << 1);
            float b0 = __ldg(bias + col), b1 = __ldg(bias + col + 1);
            #pragma unroll
            for (int hf = 0; hf < 2; hf++) {
                int row = row0 + hf * 8;
                float v0 = acc[mi][ni][hf * 2 + 0] + b0;
                float v1 = acc[mi][ni][hf * 2 + 1] + b1;
                size_t oi = (size_t)row * N + col;
                if (EPI == 2) {
                    float2 rv = *(const float2*)(res + oi);
                    float2 ov; ov.x = v0 + rv.x; ov.y = v1 + rv.y;
                    *(float2*)(Cf + oi) = ov;
                } else {
                    float a0 = (EPI == 1) ? gelu_f(v0) : v0;
                    float a1 = (EPI == 1) ? gelu_f(v1) : v1;
                    *(__half2*)(Ch + oi) = __floats2half2_rn(a0, a1);
                }
            }
        }
    }
}

// fp16 tensor-core flash attention: BQ=128 (8 warps x 16 rows), BK=64, hd=64
#define AQ_STRIDE 144
#define SM_Q   0
#define SM_KV0 18432
#define KV_STG 18432
#define VOFF   9216
#define ATT_SMEM (SM_KV0 + 2 * KV_STG)

__device__ __forceinline__ void att_load_kv(
    uint32_t base, const __half* __restrict__ qv, size_t kvrow0, int tid)
{
    const size_t TD3 = 3 * DDIM;
    #pragma unroll
    for (int i = 0; i < 4; i++) {
        int e = tid + (i << 8);
        int t = e >> 9;               // 0 K, 1 V
        int rem = e & 511;
        int r = rem >> 3, c = rem & 7;
        size_t off = (kvrow0 + r) * TD3 + (t ? 2 * DDIM : DDIM) + (c << 3);
        cp16(base + (t ? (uint32_t)VOFF : 0u) + r * AQ_STRIDE + (c << 4), qv + off);
    }
}

__global__ void __launch_bounds__(256, 1) attn_tc(
    const __half* __restrict__ qv, __half* __restrict__ o16)
{
    extern __shared__ __align__(1024) char smem[];
    uint32_t sb = s2u(smem);
    int qt = (int)gridDim.x - 1 - (int)blockIdx.x;
    int b  = blockIdx.y >> 4;
    int h  = blockIdx.y & 15;
    int tid = threadIdx.x, wid = tid >> 5, lane = tid & 31;
    const size_t TD3 = 3 * DDIM;
    size_t qrow0 = (size_t)b * TTOK + (size_t)qt * 128;
    const __half* qv_head = qv + h * HDIM;

    #pragma unroll
    for (int i = 0; i < 4; i++) {
        int e = tid + (i << 8);
        int r = e >> 3, c = e & 7;
        cp16(sb + SM_Q + r * AQ_STRIDE + (c << 4),
             qv_head + (qrow0 + r) * TD3 + (c << 3));
    }
    att_load_kv(sb + SM_KV0, qv_head, (size_t)b * TTOK, tid);
    CP_COMMIT();

    uint32_t qf[4][4];
    float O[8][4];
    #pragma unroll
    for (int n = 0; n < 8; n++)
        #pragma unroll
        for (int e = 0; e < 4; e++) O[n][e] = 0.f;
    float m0 = -1e30f, m1 = -1e30f, l0 = 0.f, l1 = 0.f;

    int bg = lane >> 3, brow = lane & 7;
    int ntiles = 2 * qt + 2;
    bool qloaded = false;

    for (int j = 0; j < ntiles; j++) {
        CP_WAIT0();
        __syncthreads();
        if (j + 1 < ntiles) {
            att_load_kv(sb + SM_KV0 + (uint32_t)((j + 1) & 1) * KV_STG,
                        qv_head, (size_t)b * TTOK + (size_t)(j + 1) * 64, tid);
            CP_COMMIT();
        }
        if (!qloaded) {
            qloaded = true;
            #pragma unroll
            for (int kc = 0; kc < 4; kc++) {
                uint32_t aoff = (uint32_t)((wid * 16 + (lane & 15)) * AQ_STRIDE
                                           + ((kc << 4) + ((lane >> 4) << 3)) * 2);
                ldsm4(qf[kc], sb + SM_Q + aoff);
            }
        }

        uint32_t kb = sb + SM_KV0 + (uint32_t)(j & 1) * KV_STG;

        float S[8][4];
        #pragma unroll
        for (int n = 0; n < 8; n++)
            #pragma unroll
            for (int e = 0; e < 4; e++) S[n][e] = 0.f;
        #pragma unroll
        for (int p = 0; p < 4; p++) {
            #pragma unroll
            for (int kc = 0; kc < 4; kc++) {
                uint32_t koff = (uint32_t)(((p << 4) + ((bg >> 1) << 3) + brow) * AQ_STRIDE
                                           + ((kc << 4) + ((bg & 1) << 3)) * 2);
                uint32_t rh[4];
                ldsm4(rh, kb + koff);
                mma_f16(S[2*p],   qf[kc], rh[0], rh[1]);
                mma_f16(S[2*p+1], qf[kc], rh[2], rh[3]);
            }
        }

        int row0 = qt * 128 + wid * 16 + (lane >> 2);
        int row1 = row0 + 8;
        int cbase = j * 64 + ((lane & 3) << 1);
        bool need_mask = (j >= 2 * qt);
        #pragma unroll
        for (int n = 0; n < 8; n++) {
            #pragma unroll
            for (int e = 0; e < 4; e++) S[n][e] *= 0.125f;
            if (need_mask) {
                int c0 = cbase + n * 8;
                if (c0     > row0) S[n][0] = -1e30f;
                if (c0 + 1 > row0) S[n][1] = -1e30f;
                if (c0     > row1) S[n][2] = -1e30f;
                if (c0 + 1 > row1) S[n][3] = -1e30f;
            }
        }

        float mr0 = -1e30f, mr1 = -1e30f;
        #pragma unroll
        for (int n = 0; n < 8; n++) {
            mr0 = fmaxf(mr0, fmaxf(S[n][0], S[n][1]));
            mr1 = fmaxf(mr1, fmaxf(S[n][2], S[n][3]));
        }
        mr0 = fmaxf(mr0, __shfl_xor_sync(0xffffffffu, mr0, 1));
        mr0 = fmaxf(mr0, __shfl_xor_sync(0xffffffffu, mr0, 2));
        mr1 = fmaxf(mr1, __shfl_xor_sync(0xffffffffu, mr1, 1));
        mr1 = fmaxf(mr1, __shfl_xor_sync(0xffffffffu, mr1, 2));
        float mn0 = fmaxf(m0, mr0), mn1 = fmaxf(m1, mr1);
        float alpha0 = __expf(m0 - mn0), alpha1 = __expf(m1 - mn1);
        float sum0 = 0.f, sum1 = 0.f;
        #pragma unroll
        for (int n = 0; n < 8; n++) {
            S[n][0] = __expf(S[n][0] - mn0); sum0 += S[n][0];
            S[n][1] = __expf(S[n][1] - mn0); sum0 += S[n][1];
            S[n][2] = __expf(S[n][2] - mn1); sum1 += S[n][2];
            S[n][3] = __expf(S[n][3] - mn1); sum1 += S[n][3];
        }
        sum0 += __shfl_xor_sync(0xffffffffu, sum0, 1);
        sum0 += __shfl_xor_sync(0xffffffffu, sum0, 2);
        sum1 += __shfl_xor_sync(0xffffffffu, sum1, 1);
        sum1 += __shfl_xor_sync(0xffffffffu, sum1, 2);
        l0 = l0 * alpha0 + sum0;
        l1 = l1 * alpha1 + sum1;
        m0 = mn0; m1 = mn1;
        #pragma unroll
        for (int n = 0; n < 8; n++) {
            O[n][0] *= alpha0; O[n][1] *= alpha0;
            O[n][2] *= alpha1; O[n][3] *= alpha1;
        }

        #pragma unroll
        for (int kc = 0; kc < 4; kc++) {
            uint32_t pf[4];
            __half2 t0 = __floats2half2_rn(S[2*kc][0],   S[2*kc][1]);
            __half2 t1 = __floats2half2_rn(S[2*kc][2],   S[2*kc][3]);
            __half2 t2 = __floats2half2_rn(S[2*kc+1][0], S[2*kc+1][1]);
            __half2 t3 = __floats2half2_rn(S[2*kc+1][2], S[2*kc+1][3]);
            pf[0] = *(uint32_t*)&t0;
            pf[1] = *(uint32_t*)&t1;
            pf[2] = *(uint32_t*)&t2;
            pf[3] = *(uint32_t*)&t3;
            #pragma unroll
            for (int np = 0; np < 4; np++) {
                uint32_t voff = (uint32_t)(((kc << 4) + ((bg & 1) << 3) + brow) * AQ_STRIDE
                                           + ((np << 4) + ((bg >> 1) << 3)) * 2);
                uint32_t rv[4];
                ldsm4t(rv, kb + VOFF + voff);
                mma_f16(O[2*np],   pf, rv[0], rv[1]);
                mma_f16(O[2*np+1], pf, rv[2], rv[3]);
            }
        }
    }

    float inv0 = 1.0f / l0, inv1 = 1.0f / l1;
    size_t row0g = qrow0 + wid * 16 + (lane >> 2);
    int colb = h * HDIM + ((lane & 3) << 1);
    #pragma unroll
    for (int n = 0; n < 8; n++) {
        int col = colb + n * 8;
        *(__half2*)(o16 + row0g * DDIM + col) =
            __floats2half2_rn(O[n][0] * inv0, O[n][1] * inv0);
        *(__half2*)(o16 + (row0g + 8) * DDIM + col) =
            __floats2half2_rn(O[n][2] * inv1, O[n][3] * inv1);
    }
}

extern "C" void kernel_launch(void* const* d_in, const int* in_sizes, int n_in,
                              void* d_out, int out_size) {
    const float* x      = (const float*)d_in[0];
    const float* ln1_g  = (const float*)d_in[1];
    const float* ln1_b  = (const float*)d_in[2];
    const float* ln2_g  = (const float*)d_in[3];
    const float* ln2_b  = (const float*)d_in[4];
    const float* w_qkv  = (const float*)d_in[5];
    const float* b_qkv  = (const float*)d_in[6];
    const float* w_o    = (const float*)d_in[7];
    const float* b_o    = (const float*)d_in[8];
    const float* w_fc1  = (const float*)d_in[9];
    const float* b_fc1  = (const float*)d_in[10];
    const float* w_fc2  = (const float*)d_in[11];
    const float* b_fc2  = (const float*)d_in[12];
    float* out = (float*)d_out;

    float* p_x1;
    __half *p_a16, *p_qv16, *p_h16, *p_wq, *p_wo, *p_w1, *p_w2;
    cudaGetSymbolAddress((void**)&p_x1,   g_x1);
    cudaGetSymbolAddress((void**)&p_a16,  g_a16);
    cudaGetSymbolAddress((void**)&p_qv16, g_qv16);
    cudaGetSymbolAddress((void**)&p_h16,  g_h16);
    cudaGetSymbolAddress((void**)&p_wq,   g_wq16);
    cudaGetSymbolAddress((void**)&p_wo,   g_wo16);
    cudaGetSymbolAddress((void**)&p_w1,   g_w116);
    cudaGetSymbolAddress((void**)&p_w2,   g_w216);

    cudaFuncSetAttribute(attn_tc, cudaFuncAttributeMaxDynamicSharedMemorySize, ATT_SMEM);
    cudaFuncSetAttribute(hmma_gemm<1>, cudaFuncAttributeMaxDynamicSharedMemorySize, GEMM_SMEM);
    cudaFuncSetAttribute(hmma_gemm<2>, cudaFuncAttributeMaxDynamicSharedMemorySize, GEMM_SMEM);
    cudaFuncSetAttribute(hmma_gemm<3>, cudaFuncAttributeMaxDynamicSharedMemorySize, GEMM_SMEM);

    wtrans16<<<dim3(3 * DDIM / 32, DDIM / 32), 256>>>(w_qkv, p_wq, DDIM, 3 * DDIM);
    wtrans16<<<dim3(DDIM / 32, DDIM / 32), 256>>>(w_o, p_wo, DDIM, DDIM);
    wtrans16<<<dim3(4 * DDIM / 32, DDIM / 32), 256>>>(w_fc1, p_w1, DDIM, 4 * DDIM);
    wtrans16<<<dim3(DDIM / 32, 4 * DDIM / 32), 256>>>(w_fc2, p_w2, 4 * DDIM, DDIM);

    ln_h<<<BT, 256>>>(x, ln1_g, ln1_b, p_a16);
    hmma_gemm<3><<<dim3(3 * DDIM / 256, BT / 128), 256, GEMM_SMEM>>>(
        p_a16, p_wq, b_qkv, nullptr, nullptr, p_qv16, 3 * DDIM, DDIM);
    attn_tc<<<dim3(TTOK / 128, BB * NH), 256, ATT_SMEM>>>(p_qv16, p_a16);
    hmma_gemm<2><<<dim3(DDIM / 256, BT / 128), 256, GEMM_SMEM>>>(
        p_a16, p_wo, b_o, x, p_x1, nullptr, DDIM, DDIM);
    ln_h<<<BT, 256>>>(p_x1, ln2_g, ln2_b, p_a16);
    hmma_gemm<1><<<dim3(4 * DDIM / 256, BT / 128), 256, GEMM_SMEM>>>(
        p_a16, p_w1, b_fc1, nullptr, nullptr, p_h16, 4 * DDIM, DDIM);
    hmma_gemm<2><<<dim3(DDIM / 256, BT / 128), 256, GEMM_SMEM>>>(
        p_h16, p_w2, b_fc2, p_x1, out, nullptr, DDIM, 4 * DDIM);
}

// round 10
// speedup vs baseline: 6.0577x; 1.0104x over previous
#include <cuda_runtime.h>
#include <cuda_fp16.h>
#include <math.h>
#include <stdint.h>

#define BB   2
#define TTOK 2048
#define DDIM 1024
#define NH   16
#define HDIM 64
#define BT   (BB*TTOK)   // 4096

// scratch (static device arrays)
__device__ float  g_x1 [BT * DDIM];          // fp32 residual after attn
__device__ __half g_a16[BT * DDIM];          // fp16 activations (ln1/attn/ln2)
__device__ __half g_qv16[BT * 3 * DDIM];     // fp16 qkv
__device__ __half g_h16[BT * 4 * DDIM];      // fp16 gelu(h)
__device__ __half g_wq16[3 * DDIM * DDIM];   // [K,N] fp16 weights
__device__ __half g_wo16[DDIM * DDIM];
__device__ __half g_w116[4 * DDIM * DDIM];
__device__ __half g_w216[4 * DDIM * DDIM];

__device__ __forceinline__ uint32_t s2u(const void* p) {
    uint32_t a;
    asm("{ .reg .u64 t; cvta.to.shared.u64 t, %1; cvt.u32.u64 %0, t; }" : "=r"(a) : "l"(p));
    return a;
}
__device__ __forceinline__ void cp16(uint32_t dst, const void* src) {
    asm volatile("cp.async.cg.shared.global [%0], [%1], 16;" :: "r"(dst), "l"(src));
}
#define CP_COMMIT() asm volatile("cp.async.commit_group;" ::: "memory")
#define CP_WAIT0()  asm volatile("cp.async.wait_group 0;" ::: "memory")
#define CP_WAIT1()  asm volatile("cp.async.wait_group 1;" ::: "memory")

__device__ __forceinline__ void ldsm4(uint32_t* r, uint32_t addr) {
    asm volatile("ldmatrix.sync.aligned.m8n8.x4.shared.b16 {%0,%1,%2,%3}, [%4];"
                 : "=r"(r[0]), "=r"(r[1]), "=r"(r[2]), "=r"(r[3]) : "r"(addr));
}
__device__ __forceinline__ void ldsm4t(uint32_t* r, uint32_t addr) {
    asm volatile("ldmatrix.sync.aligned.m8n8.x4.trans.shared.b16 {%0,%1,%2,%3}, [%4];"
                 : "=r"(r[0]), "=r"(r[1]), "=r"(r[2]), "=r"(r[3]) : "r"(addr));
}
// non-volatile: compiler may interleave HMMAs across accumulators
__device__ __forceinline__ void mma_f16(float* c, const uint32_t* a,
                                        uint32_t b0, uint32_t b1) {
    asm("mma.sync.aligned.m16n8k16.row.col.f32.f16.f16.f32 "
        "{%0,%1,%2,%3}, {%4,%5,%6,%7}, {%8,%9}, {%0,%1,%2,%3};"
        : "+f"(c[0]), "+f"(c[1]), "+f"(c[2]), "+f"(c[3])
        : "r"(a[0]), "r"(a[1]), "r"(a[2]), "r"(a[3]), "r"(b0), "r"(b1));
}

__device__ __forceinline__ float gelu_f(float x) {
    float x3 = x * x * x;
    return 0.5f * x * (1.0f + tanhf(0.7978845608028654f * (x + 0.044715f * x3)));
}

// streaming fp32 -> fp16 convert (same [K,N] layout, no transpose)
__global__ void wconv16(const float* __restrict__ W, __half* __restrict__ O, int n8) {
    int idx = blockIdx.x * 256 + threadIdx.x;
    if (idx >= n8) return;
    size_t base = (size_t)idx * 8;
    float4 a = *(const float4*)(W + base);
    float4 b = *(const float4*)(W + base + 4);
    __half2 h[4];
    h[0] = __floats2half2_rn(a.x, a.y);
    h[1] = __floats2half2_rn(a.z, a.w);
    h[2] = __floats2half2_rn(b.x, b.y);
    h[3] = __floats2half2_rn(b.z, b.w);
    *(uint4*)(O + base) = *(uint4*)h;
}

// LayerNorm -> fp16
__global__ void ln_h(const float* __restrict__ x, const float* __restrict__ g,
                     const float* __restrict__ b, __half* __restrict__ o) {
    int row = blockIdx.x;
    int tid = threadIdx.x;
    float4 v = ((const float4*)(x + (size_t)row * DDIM))[tid];
    float s  = v.x + v.y + v.z + v.w;
    float ss = v.x*v.x + v.y*v.y + v.z*v.z + v.w*v.w;
    #pragma unroll
    for (int off = 16; off > 0; off >>= 1) {
        s  += __shfl_xor_sync(0xffffffffu, s,  off);
        ss += __shfl_xor_sync(0xffffffffu, ss, off);
    }
    __shared__ float rs[8], rss[8];
    int w = tid >> 5, ln = tid & 31;
    if (ln == 0) { rs[w] = s; rss[w] = ss; }
    __syncthreads();
    float tot = 0.f, tots = 0.f;
    #pragma unroll
    for (int i = 0; i < 8; i++) { tot += rs[i]; tots += rss[i]; }
    float mu  = tot * (1.0f / DDIM);
    float var = tots * (1.0f / DDIM) - mu * mu;
    float inv = rsqrtf(var + 1e-5f);
    float4 gg = ((const float4*)g)[tid];
    float4 bb = ((const float4*)b)[tid];
    float r0 = (v.x - mu) * inv * gg.x + bb.x;
    float r1 = (v.y - mu) * inv * gg.y + bb.y;
    float r2 = (v.z - mu) * inv * gg.z + bb.z;
    float r3 = (v.w - mu) * inv * gg.w + bb.w;
    size_t base = (size_t)row * DDIM + tid * 4;
    *(__half2*)(o + base)     = __floats2half2_rn(r0, r1);
    *(__half2*)(o + base + 2) = __floats2half2_rn(r2, r3);
}

// HMMA fp16 GEMM: C[M,N] = A[M,K] @ B[K,N] + bias   (B in [K,N] row-major!)
// 128x256 block, 8 warps (2Mx4N), warp tile 64x64, K-chunk 64, 3-stage cp.async.
// EPI: 1 gelu->fp16 / 2 +res fp32 / 3 plain fp16
#define AROWB  144                      // A row: 64 fp16 + pad
#define BROWB  528                      // B row: 256 fp16 + pad
#define OFF_A  0
#define OFF_B  (128*144)                // 18432
#define STG    (128*144 + 64*528)       // 52224
#define GEMM_SMEM (3 * STG)             // 156672

__device__ __forceinline__ void load_stage(
    uint32_t st, const __half* __restrict__ A, const __half* __restrict__ B,
    int N, int K, int bm, int bn, int k0, int tid)
{
    #pragma unroll
    for (int j = 0; j < 4; j++) {                 // A: 128 rows x 8 x 16B
        int o = tid + (j << 8);
        int r = o >> 3, c = o & 7;
        cp16(st + OFF_A + (uint32_t)(r * AROWB + (c << 4)),
             A + (size_t)(bm + r) * K + k0 + (c << 3));
    }
    #pragma unroll
    for (int j = 0; j < 8; j++) {                 // B: 64 k-rows x 32 x 16B
        int o = tid + (j << 8);
        int r = o >> 5, c = o & 31;
        cp16(st + OFF_B + (uint32_t)(r * BROWB + (c << 4)),
             B + (size_t)(k0 + r) * N + bn + (c << 3));
    }
}

template<int EPI>
__global__ void __launch_bounds__(256, 1) hmma_gemm(
    const __half* __restrict__ A, const __half* __restrict__ B,
    const float* __restrict__ bias, const float* __restrict__ res,
    float* __restrict__ Cf, __half* __restrict__ Ch, int N, int K)
{
    extern __shared__ __align__(1024) char smem[];
    uint32_t sb = s2u(smem);
    int tid = threadIdx.x, wid = tid >> 5, lane = tid & 31;
    int wm = wid & 1, wn = wid >> 1;      // 2(M) x 4(N), warp tile 64x64
    int bm = blockIdx.y << 7, bn = blockIdx.x << 8;

    float acc[4][8][4];
    #pragma unroll
    for (int mi = 0; mi < 4; mi++)
        #pragma unroll
        for (int ni = 0; ni < 8; ni++)
            #pragma unroll
            for (int e = 0; e < 4; e++) acc[mi][ni][e] = 0.f;

    int nch = K >> 6;
    load_stage(sb,       A, B, N, K, bm, bn, 0,  tid); CP_COMMIT();
    load_stage(sb + STG, A, B, N, K, bm, bn, 64, tid); CP_COMMIT();

    int arow = lane & 15;
    int acol = (lane >> 4) << 3;
    int bg   = lane >> 3;
    int brow = lane & 7;

    for (int i = 0; i < nch; i++) {
        CP_WAIT1();                 // groups 0..i complete -> stage i resident
        __syncthreads();            // all warps past stage (i-1) compute
        if (i + 2 < nch)
            load_stage(sb + (uint32_t)((i + 2) % 3) * STG,
                       A, B, N, K, bm, bn, (i + 2) << 6, tid);
        CP_COMMIT();                // unconditional: keeps group arithmetic exact
        uint32_t st = sb + (uint32_t)(i % 3) * STG;
        #pragma unroll
        for (int ks = 0; ks < 4; ks++) {
            uint32_t aF[4][4];
            #pragma unroll
            for (int mi = 0; mi < 4; mi++) {
                uint32_t off = (uint32_t)(((wm << 6) + (mi << 4) + arow) * AROWB
                                          + ((ks << 4) + acol) * 2);
                ldsm4(aF[mi], st + OFF_A + off);
            }
            uint32_t bF[8][2];
            #pragma unroll
            for (int np = 0; np < 4; np++) {
                // B tile is [k][n]; trans-load gives col-major fragments
                uint32_t off = (uint32_t)(((ks << 4) + ((bg & 1) << 3) + brow) * BROWB
                                          + ((wn << 6) + (np << 4) + ((bg >> 1) << 3)) * 2);
                uint32_t r[4];
                ldsm4t(r, st + OFF_B + off);
                bF[2*np][0]   = r[0]; bF[2*np][1]   = r[1];
                bF[2*np+1][0] = r[2]; bF[2*np+1][1] = r[3];
            }
            #pragma unroll
            for (int mi = 0; mi < 4; mi++)
                #pragma unroll
                for (int ni = 0; ni < 8; ni++)
                    mma_f16(acc[mi][ni], aF[mi], bF[ni][0], bF[ni][1]);
        }
    }

    __syncthreads();
    #pragma unroll
    for (int mi = 0; mi < 4; mi++) {
        #pragma unroll
        for (int ni = 0; ni < 8; ni++) {
            int row0 = bm + (wm << 6) + (mi << 4) + (lane >> 2);
            int col  = bn + (wn << 6) + (ni << 3) + ((lane & 3) << 1);
            float b0 = __ldg(bias + col), b1 = __ldg(bias + col + 1);
            #pragma unroll
            for (int hf = 0; hf < 2; hf++) {
                int row = row0 + hf * 8;
                float v0 = acc[mi][ni][hf * 2 + 0] + b0;
                float v1 = acc[mi][ni][hf * 2 + 1] + b1;
                size_t oi = (size_t)row * N + col;
                if (EPI == 2) {
                    float2 rv = *(const float2*)(res + oi);
                    float2 ov; ov.x = v0 + rv.x; ov.y = v1 + rv.y;
                    *(float2*)(Cf + oi) = ov;
                } else {
                    float a0 = (EPI == 1) ? gelu_f(v0) : v0;
                    float a1 = (EPI == 1) ? gelu_f(v1) : v1;
                    *(__half2*)(Ch + oi) = __floats2half2_rn(a0, a1);
                }
            }
        }
    }
}

// fp16 tensor-core flash attention: BQ=128 (8 warps x 16 rows), BK=64, hd=64
#define AQ_STRIDE 144
#define SM_Q   0
#define SM_KV0 18432
#define KV_STG 18432
#define VOFF   9216
#define ATT_SMEM (SM_KV0 + 2 * KV_STG)

__device__ __forceinline__ void att_load_kv(
    uint32_t base, const __half* __restrict__ qv, size_t kvrow0, int tid)
{
    const size_t TD3 = 3 * DDIM;
    #pragma unroll
    for (int i = 0; i < 4; i++) {
        int e = tid + (i << 8);
        int t = e >> 9;               // 0 K, 1 V
        int rem = e & 511;
        int r = rem >> 3, c = rem & 7;
        size_t off = (kvrow0 + r) * TD3 + (t ? 2 * DDIM : DDIM) + (c << 3);
        cp16(base + (t ? (uint32_t)VOFF : 0u) + r * AQ_STRIDE + (c << 4), qv + off);
    }
}

__global__ void __launch_bounds__(256, 1) attn_tc(
    const __half* __restrict__ qv, __half* __restrict__ o16)
{
    extern __shared__ __align__(1024) char smem[];
    uint32_t sb = s2u(smem);
    int qt = (int)gridDim.x - 1 - (int)blockIdx.x;
    int b  = blockIdx.y >> 4;
    int h  = blockIdx.y & 15;
    int tid = threadIdx.x, wid = tid >> 5, lane = tid & 31;
    const size_t TD3 = 3 * DDIM;
    size_t qrow0 = (size_t)b * TTOK + (size_t)qt * 128;
    const __half* qv_head = qv + h * HDIM;

    #pragma unroll
    for (int i = 0; i < 4; i++) {
        int e = tid + (i << 8);
        int r = e >> 3, c = e & 7;
        cp16(sb + SM_Q + r * AQ_STRIDE + (c << 4),
             qv_head + (qrow0 + r) * TD3 + (c << 3));
    }
    att_load_kv(sb + SM_KV0, qv_head, (size_t)b * TTOK, tid);
    CP_COMMIT();

    uint32_t qf[4][4];
    float O[8][4];
    #pragma unroll
    for (int n = 0; n < 8; n++)
        #pragma unroll
        for (int e = 0; e < 4; e++) O[n][e] = 0.f;
    float m0 = -1e30f, m1 = -1e30f, l0 = 0.f, l1 = 0.f;

    int bg = lane >> 3, brow = lane & 7;
    int ntiles = 2 * qt + 2;
    bool qloaded = false;

    for (int j = 0; j < ntiles; j++) {
        CP_WAIT0();
        __syncthreads();
        if (j + 1 < ntiles) {
            att_load_kv(sb + SM_KV0 + (uint32_t)((j + 1) & 1) * KV_STG,
                        qv_head, (size_t)b * TTOK + (size_t)(j + 1) * 64, tid);
            CP_COMMIT();
        }
        if (!qloaded) {
            qloaded = true;
            #pragma unroll
            for (int kc = 0; kc < 4; kc++) {
                uint32_t aoff = (uint32_t)((wid * 16 + (lane & 15)) * AQ_STRIDE
                                           + ((kc << 4) + ((lane >> 4) << 3)) * 2);
                ldsm4(qf[kc], sb + SM_Q + aoff);
            }
        }

        uint32_t kb = sb + SM_KV0 + (uint32_t)(j & 1) * KV_STG;

        float S[8][4];
        #pragma unroll
        for (int n = 0; n < 8; n++)
            #pragma unroll
            for (int e = 0; e < 4; e++) S[n][e] = 0.f;
        #pragma unroll
        for (int p = 0; p < 4; p++) {
            #pragma unroll
            for (int kc = 0; kc < 4; kc++) {
                uint32_t koff = (uint32_t)(((p << 4) + ((bg >> 1) << 3) + brow) * AQ_STRIDE
                                           + ((kc << 4) + ((bg & 1) << 3)) * 2);
                uint32_t rh[4];
                ldsm4(rh, kb + koff);
                mma_f16(S[2*p],   qf[kc], rh[0], rh[1]);
                mma_f16(S[2*p+1], qf[kc], rh[2], rh[3]);
            }
        }

        int row0 = qt * 128 + wid * 16 + (lane >> 2);
        int row1 = row0 + 8;
        int cbase = j * 64 + ((lane & 3) << 1);
        bool need_mask = (j >= 2 * qt);
        #pragma unroll
        for (int n = 0; n < 8; n++) {
            #pragma unroll
            for (int e = 0; e < 4; e++) S[n][e] *= 0.125f;
            if (need_mask) {
                int c0 = cbase + n * 8;
                if (c0     > row0) S[n][0] = -1e30f;
                if (c0 + 1 > row0) S[n][1] = -1e30f;
                if (c0     > row1) S[n][2] = -1e30f;
                if (c0 + 1 > row1) S[n][3] = -1e30f;
            }
        }

        float mr0 = -1e30f, mr1 = -1e30f;
        #pragma unroll
        for (int n = 0; n < 8; n++) {
            mr0 = fmaxf(mr0, fmaxf(S[n][0], S[n][1]));
            mr1 = fmaxf(mr1, fmaxf(S[n][2], S[n][3]));
        }
        mr0 = fmaxf(mr0, __shfl_xor_sync(0xffffffffu, mr0, 1));
        mr0 = fmaxf(mr0, __shfl_xor_sync(0xffffffffu, mr0, 2));
        mr1 = fmaxf(mr1, __shfl_xor_sync(0xffffffffu, mr1, 1));
        mr1 = fmaxf(mr1, __shfl_xor_sync(0xffffffffu, mr1, 2));
        float mn0 = fmaxf(m0, mr0), mn1 = fmaxf(m1, mr1);
        float alpha0 = __expf(m0 - mn0), alpha1 = __expf(m1 - mn1);
        float sum0 = 0.f, sum1 = 0.f;
        #pragma unroll
        for (int n = 0; n < 8; n++) {
            S[n][0] = __expf(S[n][0] - mn0); sum0 += S[n][0];
            S[n][1] = __expf(S[n][1] - mn0); sum0 += S[n][1];
            S[n][2] = __expf(S[n][2] - mn1); sum1 += S[n][2];
            S[n][3] = __expf(S[n][3] - mn1); sum1 += S[n][3];
        }
        sum0 += __shfl_xor_sync(0xffffffffu, sum0, 1);
        sum0 += __shfl_xor_sync(0xffffffffu, sum0, 2);
        sum1 += __shfl_xor_sync(0xffffffffu, sum1, 1);
        sum1 += __shfl_xor_sync(0xffffffffu, sum1, 2);
        l0 = l0 * alpha0 + sum0;
        l1 = l1 * alpha1 + sum1;
        m0 = mn0; m1 = mn1;
        #pragma unroll
        for (int n = 0; n < 8; n++) {
            O[n][0] *= alpha0; O[n][1] *= alpha0;
            O[n][2] *= alpha1; O[n][3] *= alpha1;
        }

        #pragma unroll
        for (int kc = 0; kc < 4; kc++) {
            uint32_t pf[4];
            __half2 t0 = __floats2half2_rn(S[2*kc][0],   S[2*kc][1]);
            __half2 t1 = __floats2half2_rn(S[2*kc][2],   S[2*kc][3]);
            __half2 t2 = __floats2half2_rn(S[2*kc+1][0], S[2*kc+1][1]);
            __half2 t3 = __floats2half2_rn(S[2*kc+1][2], S[2*kc+1][3]);
            pf[0] = *(uint32_t*)&t0;
            pf[1] = *(uint32_t*)&t1;
            pf[2] = *(uint32_t*)&t2;
            pf[3] = *(uint32_t*)&t3;
            #pragma unroll
            for (int np = 0; np < 4; np++) {
                uint32_t voff = (uint32_t)(((kc << 4) + ((bg & 1) << 3) + brow) * AQ_STRIDE
                                           + ((np << 4) + ((bg >> 1) << 3)) * 2);
                uint32_t rv[4];
                ldsm4t(rv, kb + VOFF + voff);
                mma_f16(O[2*np],   pf, rv[0], rv[1]);
                mma_f16(O[2*np+1], pf, rv[2], rv[3]);
            }
        }
    }

    float inv0 = 1.0f / l0, inv1 = 1.0f / l1;
    size_t row0g = qrow0 + wid * 16 + (lane >> 2);
    int colb = h * HDIM + ((lane & 3) << 1);
    #pragma unroll
    for (int n = 0; n < 8; n++) {
        int col = colb + n * 8;
        *(__half2*)(o16 + row0g * DDIM + col) =
            __floats2half2_rn(O[n][0] * inv0, O[n][1] * inv0);
        *(__half2*)(o16 + (row0g + 8) * DDIM + col) =
            __floats2half2_rn(O[n][2] * inv1, O[n][3] * inv1);
    }
}

extern "C" void kernel_launch(void* const* d_in, const int* in_sizes, int n_in,
                              void* d_out, int out_size) {
    const float* x      = (const float*)d_in[0];
    const float* ln1_g  = (const float*)d_in[1];
    const float* ln1_b  = (const float*)d_in[2];
    const float* ln2_g  = (const float*)d_in[3];
    const float* ln2_b  = (const float*)d_in[4];
    const float* w_qkv  = (const float*)d_in[5];
    const float* b_qkv  = (const float*)d_in[6];
    const float* w_o    = (const float*)d_in[7];
    const float* b_o    = (const float*)d_in[8];
    const float* w_fc1  = (const float*)d_in[9];
    const float* b_fc1  = (const float*)d_in[10];
    const float* w_fc2  = (const float*)d_in[11];
    const float* b_fc2  = (const float*)d_in[12];
    float* out = (float*)d_out;

    float* p_x1;
    __half *p_a16, *p_qv16, *p_h16, *p_wq, *p_wo, *p_w1, *p_w2;
    cudaGetSymbolAddress((void**)&p_x1,   g_x1);
    cudaGetSymbolAddress((void**)&p_a16,  g_a16);
    cudaGetSymbolAddress((void**)&p_qv16, g_qv16);
    cudaGetSymbolAddress((void**)&p_h16,  g_h16);
    cudaGetSymbolAddress((void**)&p_wq,   g_wq16);
    cudaGetSymbolAddress((void**)&p_wo,   g_wo16);
    cudaGetSymbolAddress((void**)&p_w1,   g_w116);
    cudaGetSymbolAddress((void**)&p_w2,   g_w216);

    cudaFuncSetAttribute(attn_tc, cudaFuncAttributeMaxDynamicSharedMemorySize, ATT_SMEM);
    cudaFuncSetAttribute(hmma_gemm<1>, cudaFuncAttributeMaxDynamicSharedMemorySize, GEMM_SMEM);
    cudaFuncSetAttribute(hmma_gemm<2>, cudaFuncAttributeMaxDynamicSharedMemorySize, GEMM_SMEM);
    cudaFuncSetAttribute(hmma_gemm<3>, cudaFuncAttributeMaxDynamicSharedMemorySize, GEMM_SMEM);

    // weight fp32->fp16 (same [K,N] layout, streaming)
    wconv16<<<(3 * DDIM * DDIM / 8 + 255) / 256, 256>>>(w_qkv, p_wq, 3 * DDIM * DDIM / 8);
    wconv16<<<(DDIM * DDIM / 8 + 255) / 256, 256>>>(w_o, p_wo, DDIM * DDIM / 8);
    wconv16<<<(4 * DDIM * DDIM / 8 + 255) / 256, 256>>>(w_fc1, p_w1, 4 * DDIM * DDIM / 8);
    wconv16<<<(4 * DDIM * DDIM / 8 + 255) / 256, 256>>>(w_fc2, p_w2, 4 * DDIM * DDIM / 8);

    ln_h<<<BT, 256>>>(x, ln1_g, ln1_b, p_a16);
    hmma_gemm<3><<<dim3(3 * DDIM / 256, BT / 128), 256, GEMM_SMEM>>>(
        p_a16, p_wq, b_qkv, nullptr, nullptr, p_qv16, 3 * DDIM, DDIM);
    attn_tc<<<dim3(TTOK / 128, BB * NH), 256, ATT_SMEM>>>(p_qv16, p_a16);
    hmma_gemm<2><<<dim3(DDIM / 256, BT / 128), 256, GEMM_SMEM>>>(
        p_a16, p_wo, b_o, x, p_x1, nullptr, DDIM, DDIM);
    ln_h<<<BT, 256>>>(p_x1, ln2_g, ln2_b, p_a16);
    hmma_gemm<1><<<dim3(4 * DDIM / 256, BT / 128), 256, GEMM_SMEM>>>(
        p_a16, p_w1, b_fc1, nullptr, nullptr, p_h16, 4 * DDIM, DDIM);
    hmma_gemm<2><<<dim3(DDIM / 256, BT / 128), 256, GEMM_SMEM>>>(
        p_h16, p_w2, b_fc2, p_x1, out, nullptr, DDIM, 4 * DDIM);
}

// round 11
// speedup vs baseline: 6.0974x; 1.0066x over previous
#include <cuda_runtime.h>
#include <cuda_fp16.h>
#include <math.h>
#include <stdint.h>

#define BB   2
#define TTOK 2048
#define DDIM 1024
#define NH   16
#define HDIM 64
#define BT   (BB*TTOK)   // 4096

// scratch (static device arrays)
__device__ float  g_x1 [BT * DDIM];
__device__ __half g_a16[BT * DDIM];
__device__ __half g_qv16[BT * 3 * DDIM];
__device__ __half g_h16[BT * 4 * DDIM];
__device__ __half g_wq16[3 * DDIM * DDIM];   // [K,N] fp16 weights
__device__ __half g_wo16[DDIM * DDIM];
__device__ __half g_w116[4 * DDIM * DDIM];
__device__ __half g_w216[4 * DDIM * DDIM];

__device__ __forceinline__ uint32_t s2u(const void* p) {
    uint32_t a;
    asm("{ .reg .u64 t; cvta.to.shared.u64 t, %1; cvt.u32.u64 %0, t; }" : "=r"(a) : "l"(p));
    return a;
}
__device__ __forceinline__ void cp16(uint32_t dst, const void* src) {
    asm volatile("cp.async.cg.shared.global [%0], [%1], 16;" :: "r"(dst), "l"(src));
}
#define CP_COMMIT() asm volatile("cp.async.commit_group;" ::: "memory")
#define CP_WAIT0()  asm volatile("cp.async.wait_group 0;" ::: "memory")
#define CP_WAIT1()  asm volatile("cp.async.wait_group 1;" ::: "memory")

__device__ __forceinline__ void ldsm4(uint32_t* r, uint32_t addr) {
    asm volatile("ldmatrix.sync.aligned.m8n8.x4.shared.b16 {%0,%1,%2,%3}, [%4];"
                 : "=r"(r[0]), "=r"(r[1]), "=r"(r[2]), "=r"(r[3]) : "r"(addr));
}
__device__ __forceinline__ void ldsm4t(uint32_t* r, uint32_t addr) {
    asm volatile("ldmatrix.sync.aligned.m8n8.x4.trans.shared.b16 {%0,%1,%2,%3}, [%4];"
                 : "=r"(r[0]), "=r"(r[1]), "=r"(r[2]), "=r"(r[3]) : "r"(addr));
}
__device__ __forceinline__ void mma_f16(float* c, const uint32_t* a,
                                        uint32_t b0, uint32_t b1) {
    asm("mma.sync.aligned.m16n8k16.row.col.f32.f16.f16.f32 "
        "{%0,%1,%2,%3}, {%4,%5,%6,%7}, {%8,%9}, {%0,%1,%2,%3};"
        : "+f"(c[0]), "+f"(c[1]), "+f"(c[2]), "+f"(c[3])
        : "r"(a[0]), "r"(a[1]), "r"(a[2]), "r"(a[3]), "r"(b0), "r"(b1));
}

__device__ __forceinline__ float gelu_f(float x) {
    float x3 = x * x * x;
    return 0.5f * x * (1.0f + tanhf(0.7978845608028654f * (x + 0.044715f * x3)));
}

// streaming fp32 -> fp16 convert (same [K,N] layout)
__global__ void wconv16(const float* __restrict__ W, __half* __restrict__ O, int n8) {
    int idx = blockIdx.x * 256 + threadIdx.x;
    if (idx >= n8) return;
    size_t base = (size_t)idx * 8;
    float4 a = *(const float4*)(W + base);
    float4 b = *(const float4*)(W + base + 4);
    __half2 h[4];
    h[0] = __floats2half2_rn(a.x, a.y);
    h[1] = __floats2half2_rn(a.z, a.w);
    h[2] = __floats2half2_rn(b.x, b.y);
    h[3] = __floats2half2_rn(b.z, b.w);
    *(uint4*)(O + base) = *(uint4*)h;
}

// LayerNorm -> fp16
__global__ void ln_h(const float* __restrict__ x, const float* __restrict__ g,
                     const float* __restrict__ b, __half* __restrict__ o) {
    int row = blockIdx.x;
    int tid = threadIdx.x;
    float4 v = ((const float4*)(x + (size_t)row * DDIM))[tid];
    float s  = v.x + v.y + v.z + v.w;
    float ss = v.x*v.x + v.y*v.y + v.z*v.z + v.w*v.w;
    #pragma unroll
    for (int off = 16; off > 0; off >>= 1) {
        s  += __shfl_xor_sync(0xffffffffu, s,  off);
        ss += __shfl_xor_sync(0xffffffffu, ss, off);
    }
    __shared__ float rs[8], rss[8];
    int w = tid >> 5, ln = tid & 31;
    if (ln == 0) { rs[w] = s; rss[w] = ss; }
    __syncthreads();
    float tot = 0.f, tots = 0.f;
    #pragma unroll
    for (int i = 0; i < 8; i++) { tot += rs[i]; tots += rss[i]; }
    float mu  = tot * (1.0f / DDIM);
    float var = tots * (1.0f / DDIM) - mu * mu;
    float inv = rsqrtf(var + 1e-5f);
    float4 gg = ((const float4*)g)[tid];
    float4 bb = ((const float4*)b)[tid];
    float r0 = (v.x - mu) * inv * gg.x + bb.x;
    float r1 = (v.y - mu) * inv * gg.y + bb.y;
    float r2 = (v.z - mu) * inv * gg.z + bb.z;
    float r3 = (v.w - mu) * inv * gg.w + bb.w;
    size_t base = (size_t)row * DDIM + tid * 4;
    *(__half2*)(o + base)     = __floats2half2_rn(r0, r1);
    *(__half2*)(o + base + 2) = __floats2half2_rn(r2, r3);
}

// HMMA fp16 GEMM: C[M,N] = A[M,K] @ B[K,N] + bias   (B in [K,N] row-major)
// 128x256 block, 8 warps (2Mx4N), warp 64x64, K-chunk 64, 3-stage cp.async,
// manual fragment double-buffering across k16 steps.
#define AROWB  144
#define BROWB  528
#define OFF_A  0
#define OFF_B  (128*144)
#define STG    (128*144 + 64*528)       // 52224
#define GEMM_SMEM (3 * STG)             // 156672

__device__ __forceinline__ void load_stage(
    uint32_t st, const __half* __restrict__ A, const __half* __restrict__ B,
    int N, int K, int bm, int bn, int k0, int tid)
{
    #pragma unroll
    for (int j = 0; j < 4; j++) {
        int o = tid + (j << 8);
        int r = o >> 3, c = o & 7;
        cp16(st + OFF_A + (uint32_t)(r * AROWB + (c << 4)),
             A + (size_t)(bm + r) * K + k0 + (c << 3));
    }
    #pragma unroll
    for (int j = 0; j < 8; j++) {
        int o = tid + (j << 8);
        int r = o >> 5, c = o & 31;
        cp16(st + OFF_B + (uint32_t)(r * BROWB + (c << 4)),
             B + (size_t)(k0 + r) * N + bn + (c << 3));
    }
}

__device__ __forceinline__ void load_frags(
    uint32_t st, int ks, int wm, int wn, int arow, int acol, int bg, int brow,
    uint32_t aF[4][4], uint32_t bF[8][2])
{
    #pragma unroll
    for (int mi = 0; mi < 4; mi++) {
        uint32_t off = (uint32_t)(((wm << 6) + (mi << 4) + arow) * AROWB
                                  + ((ks << 4) + acol) * 2);
        ldsm4(aF[mi], st + OFF_A + off);
    }
    #pragma unroll
    for (int np = 0; np < 4; np++) {
        uint32_t off = (uint32_t)(((ks << 4) + ((bg & 1) << 3) + brow) * BROWB
                                  + ((wn << 6) + (np << 4) + ((bg >> 1) << 3)) * 2);
        uint32_t r[4];
        ldsm4t(r, st + OFF_B + off);
        bF[2*np][0]   = r[0]; bF[2*np][1]   = r[1];
        bF[2*np+1][0] = r[2]; bF[2*np+1][1] = r[3];
    }
}

template<int EPI>
__global__ void __launch_bounds__(256, 1) hmma_gemm(
    const __half* __restrict__ A, const __half* __restrict__ B,
    const float* __restrict__ bias, const float* __restrict__ res,
    float* __restrict__ Cf, __half* __restrict__ Ch, int N, int K)
{
    extern __shared__ __align__(1024) char smem[];
    uint32_t sb = s2u(smem);
    int tid = threadIdx.x, wid = tid >> 5, lane = tid & 31;
    int wm = wid & 1, wn = wid >> 1;
    int bm = blockIdx.y << 7, bn = blockIdx.x << 8;

    float acc[4][8][4];
    #pragma unroll
    for (int mi = 0; mi < 4; mi++)
        #pragma unroll
        for (int ni = 0; ni < 8; ni++)
            #pragma unroll
            for (int e = 0; e < 4; e++) acc[mi][ni][e] = 0.f;

    int nch = K >> 6;
    load_stage(sb,       A, B, N, K, bm, bn, 0,  tid); CP_COMMIT();
    load_stage(sb + STG, A, B, N, K, bm, bn, 64, tid); CP_COMMIT();

    int arow = lane & 15;
    int acol = (lane >> 4) << 3;
    int bg   = lane >> 3;
    int brow = lane & 7;

    uint32_t aF[2][4][4], bF[2][8][2];

    for (int i = 0; i < nch; i++) {
        CP_WAIT1();
        __syncthreads();
        if (i + 2 < nch)
            load_stage(sb + (uint32_t)((i + 2) % 3) * STG,
                       A, B, N, K, bm, bn, (i + 2) << 6, tid);
        CP_COMMIT();
        uint32_t st = sb + (uint32_t)(i % 3) * STG;
        load_frags(st, 0, wm, wn, arow, acol, bg, brow, aF[0], bF[0]);
        #pragma unroll
        for (int ks = 0; ks < 4; ks++) {
            int cur = ks & 1;
            if (ks < 3)
                load_frags(st, ks + 1, wm, wn, arow, acol, bg, brow,
                           aF[cur ^ 1], bF[cur ^ 1]);
            #pragma unroll
            for (int mi = 0; mi < 4; mi++)
                #pragma unroll
                for (int ni = 0; ni < 8; ni++)
                    mma_f16(acc[mi][ni], aF[cur][mi], bF[cur][ni][0], bF[cur][ni][1]);
        }
    }

    __syncthreads();
    #pragma unroll
    for (int mi = 0; mi < 4; mi++) {
        #pragma unroll
        for (int ni = 0; ni < 8; ni++) {
            int row0 = bm + (wm << 6) + (mi << 4) + (lane >> 2);
            int col  = bn + (wn << 6) + (ni << 3) + ((lane & 3) << 1);
            float b0 = __ldg(bias + col), b1 = __ldg(bias + col + 1);
            #pragma unroll
            for (int hf = 0; hf < 2; hf++) {
                int row = row0 + hf * 8;
                float v0 = acc[mi][ni][hf * 2 + 0] + b0;
                float v1 = acc[mi][ni][hf * 2 + 1] + b1;
                size_t oi = (size_t)row * N + col;
                if (EPI == 2) {
                    float2 rv = *(const float2*)(res + oi);
                    float2 ov; ov.x = v0 + rv.x; ov.y = v1 + rv.y;
                    *(float2*)(Cf + oi) = ov;
                } else {
                    float a0 = (EPI == 1) ? gelu_f(v0) : v0;
                    float a1 = (EPI == 1) ? gelu_f(v1) : v1;
                    *(__half2*)(Ch + oi) = __floats2half2_rn(a0, a1);
                }
            }
        }
    }
}

// fp16 tensor-core flash attention: BQ=128 (8 warps x 16 rows), BK=64, hd=64
#define AQ_STRIDE 144
#define SM_Q   0
#define SM_KV0 18432
#define KV_STG 18432
#define VOFF   9216
#define ATT_SMEM (SM_KV0 + 2 * KV_STG)

__device__ __forceinline__ void att_load_kv(
    uint32_t base, const __half* __restrict__ qv, size_t kvrow0, int tid)
{
    const size_t TD3 = 3 * DDIM;
    #pragma unroll
    for (int i = 0; i < 4; i++) {
        int e = tid + (i << 8);
        int t = e >> 9;
        int rem = e & 511;
        int r = rem >> 3, c = rem & 7;
        size_t off = (kvrow0 + r) * TD3 + (t ? 2 * DDIM : DDIM) + (c << 3);
        cp16(base + (t ? (uint32_t)VOFF : 0u) + r * AQ_STRIDE + (c << 4), qv + off);
    }
}

__global__ void __launch_bounds__(256, 1) attn_tc(
    const __half* __restrict__ qv, __half* __restrict__ o16)
{
    extern __shared__ __align__(1024) char smem[];
    uint32_t sb = s2u(smem);
    int qt = (int)gridDim.x - 1 - (int)blockIdx.x;
    int b  = blockIdx.y >> 4;
    int h  = blockIdx.y & 15;
    int tid = threadIdx.x, wid = tid >> 5, lane = tid & 31;
    const size_t TD3 = 3 * DDIM;
    size_t qrow0 = (size_t)b * TTOK + (size_t)qt * 128;
    const __half* qv_head = qv + h * HDIM;

    #pragma unroll
    for (int i = 0; i < 4; i++) {
        int e = tid + (i << 8);
        int r = e >> 3, c = e & 7;
        cp16(sb + SM_Q + r * AQ_STRIDE + (c << 4),
             qv_head + (qrow0 + r) * TD3 + (c << 3));
    }
    att_load_kv(sb + SM_KV0, qv_head, (size_t)b * TTOK, tid);
    CP_COMMIT();

    uint32_t qf[4][4];
    float O[8][4];
    #pragma unroll
    for (int n = 0; n < 8; n++)
        #pragma unroll
        for (int e = 0; e < 4; e++) O[n][e] = 0.f;
    float m0 = -1e30f, m1 = -1e30f, l0 = 0.f, l1 = 0.f;

    int bg = lane >> 3, brow = lane & 7;
    int ntiles = 2 * qt + 2;
    bool qloaded = false;

    for (int j = 0; j < ntiles; j++) {
        CP_WAIT0();
        __syncthreads();
        if (j + 1 < ntiles) {
            att_load_kv(sb + SM_KV0 + (uint32_t)((j + 1) & 1) * KV_STG,
                        qv_head, (size_t)b * TTOK + (size_t)(j + 1) * 64, tid);
            CP_COMMIT();
        }
        if (!qloaded) {
            qloaded = true;
            #pragma unroll
            for (int kc = 0; kc < 4; kc++) {
                uint32_t aoff = (uint32_t)((wid * 16 + (lane & 15)) * AQ_STRIDE
                                           + ((kc << 4) + ((lane >> 4) << 3)) * 2);
                ldsm4(qf[kc], sb + SM_Q + aoff);
            }
        }

        uint32_t kb = sb + SM_KV0 + (uint32_t)(j & 1) * KV_STG;

        float S[8][4];
        #pragma unroll
        for (int n = 0; n < 8; n++)
            #pragma unroll
            for (int e = 0; e < 4; e++) S[n][e] = 0.f;
        #pragma unroll
        for (int p = 0; p < 4; p++) {
            #pragma unroll
            for (int kc = 0; kc < 4; kc++) {
                uint32_t koff = (uint32_t)(((p << 4) + ((bg >> 1) << 3) + brow) * AQ_STRIDE
                                           + ((kc << 4) + ((bg & 1) << 3)) * 2);
                uint32_t rh[4];
                ldsm4(rh, kb + koff);
                mma_f16(S[2*p],   qf[kc], rh[0], rh[1]);
                mma_f16(S[2*p+1], qf[kc], rh[2], rh[3]);
            }
        }

        int row0 = qt * 128 + wid * 16 + (lane >> 2);
        int row1 = row0 + 8;
        int cbase = j * 64 + ((lane & 3) << 1);
        bool need_mask = (j >= 2 * qt);
        #pragma unroll
        for (int n = 0; n < 8; n++) {
            #pragma unroll
            for (int e = 0; e < 4; e++) S[n][e] *= 0.125f;
            if (need_mask) {
                int c0 = cbase + n * 8;
                if (c0     > row0) S[n][0] = -1e30f;
                if (c0 + 1 > row0) S[n][1] = -1e30f;
                if (c0     > row1) S[n][2] = -1e30f;
                if (c0 + 1 > row1) S[n][3] = -1e30f;
            }
        }

        float mr0 = -1e30f, mr1 = -1e30f;
        #pragma unroll
        for (int n = 0; n < 8; n++) {
            mr0 = fmaxf(mr0, fmaxf(S[n][0], S[n][1]));
            mr1 = fmaxf(mr1, fmaxf(S[n][2], S[n][3]));
        }
        mr0 = fmaxf(mr0, __shfl_xor_sync(0xffffffffu, mr0, 1));
        mr0 = fmaxf(mr0, __shfl_xor_sync(0xffffffffu, mr0, 2));
        mr1 = fmaxf(mr1, __shfl_xor_sync(0xffffffffu, mr1, 1));
        mr1 = fmaxf(mr1, __shfl_xor_sync(0xffffffffu, mr1, 2));
        float mn0 = fmaxf(m0, mr0), mn1 = fmaxf(m1, mr1);
        float alpha0 = __expf(m0 - mn0), alpha1 = __expf(m1 - mn1);
        float sum0 = 0.f, sum1 = 0.f;
        #pragma unroll
        for (int n = 0; n < 8; n++) {
            S[n][0] = __expf(S[n][0] - mn0); sum0 += S[n][0];
            S[n][1] = __expf(S[n][1] - mn0); sum0 += S[n][1];
            S[n][2] = __expf(S[n][2] - mn1); sum1 += S[n][2];
            S[n][3] = __expf(S[n][3] - mn1); sum1 += S[n][3];
        }
        sum0 += __shfl_xor_sync(0xffffffffu, sum0, 1);
        sum0 += __shfl_xor_sync(0xffffffffu, sum0, 2);
        sum1 += __shfl_xor_sync(0xffffffffu, sum1, 1);
        sum1 += __shfl_xor_sync(0xffffffffu, sum1, 2);
        l0 = l0 * alpha0 + sum0;
        l1 = l1 * alpha1 + sum1;
        m0 = mn0; m1 = mn1;
        #pragma unroll
        for (int n = 0; n < 8; n++) {
            O[n][0] *= alpha0; O[n][1] *= alpha0;
            O[n][2] *= alpha1; O[n][3] *= alpha1;
        }

        #pragma unroll
        for (int kc = 0; kc < 4; kc++) {
            uint32_t pf[4];
            __half2 t0 = __floats2half2_rn(S[2*kc][0],   S[2*kc][1]);
            __half2 t1 = __floats2half2_rn(S[2*kc][2],   S[2*kc][3]);
            __half2 t2 = __floats2half2_rn(S[2*kc+1][0], S[2*kc+1][1]);
            __half2 t3 = __floats2half2_rn(S[2*kc+1][2], S[2*kc+1][3]);
            pf[0] = *(uint32_t*)&t0;
            pf[1] = *(uint32_t*)&t1;
            pf[2] = *(uint32_t*)&t2;
            pf[3] = *(uint32_t*)&t3;
            #pragma unroll
            for (int np = 0; np < 4; np++) {
                uint32_t voff = (uint32_t)(((kc << 4) + ((bg & 1) << 3) + brow) * AQ_STRIDE
                                           + ((np << 4) + ((bg >> 1) << 3)) * 2);
                uint32_t rv[4];
                ldsm4t(rv, kb + VOFF + voff);
                mma_f16(O[2*np],   pf, rv[0], rv[1]);
                mma_f16(O[2*np+1], pf, rv[2], rv[3]);
            }
        }
    }

    float inv0 = 1.0f / l0, inv1 = 1.0f / l1;
    size_t row0g = qrow0 + wid * 16 + (lane >> 2);
    int colb = h * HDIM + ((lane & 3) << 1);
    #pragma unroll
    for (int n = 0; n < 8; n++) {
        int col = colb + n * 8;
        *(__half2*)(o16 + row0g * DDIM + col) =
            __floats2half2_rn(O[n][0] * inv0, O[n][1] * inv0);
        *(__half2*)(o16 + (row0g + 8) * DDIM + col) =
            __floats2half2_rn(O[n][2] * inv1, O[n][3] * inv1);
    }
}

extern "C" void kernel_launch(void* const* d_in, const int* in_sizes, int n_in,
                              void* d_out, int out_size) {
    const float* x      = (const float*)d_in[0];
    const float* ln1_g  = (const float*)d_in[1];
    const float* ln1_b  = (const float*)d_in[2];
    const float* ln2_g  = (const float*)d_in[3];
    const float* ln2_b  = (const float*)d_in[4];
    const float* w_qkv  = (const float*)d_in[5];
    const float* b_qkv  = (const float*)d_in[6];
    const float* w_o    = (const float*)d_in[7];
    const float* b_o    = (const float*)d_in[8];
    const float* w_fc1  = (const float*)d_in[9];
    const float* b_fc1  = (const float*)d_in[10];
    const float* w_fc2  = (const float*)d_in[11];
    const float* b_fc2  = (const float*)d_in[12];
    float* out = (float*)d_out;

    float* p_x1;
    __half *p_a16, *p_qv16, *p_h16, *p_wq, *p_wo, *p_w1, *p_w2;
    cudaGetSymbolAddress((void**)&p_x1,   g_x1);
    cudaGetSymbolAddress((void**)&p_a16,  g_a16);
    cudaGetSymbolAddress((void**)&p_qv16, g_qv16);
    cudaGetSymbolAddress((void**)&p_h16,  g_h16);
    cudaGetSymbolAddress((void**)&p_wq,   g_wq16);
    cudaGetSymbolAddress((void**)&p_wo,   g_wo16);
    cudaGetSymbolAddress((void**)&p_w1,   g_w116);
    cudaGetSymbolAddress((void**)&p_w2,   g_w216);

    cudaFuncSetAttribute(attn_tc, cudaFuncAttributeMaxDynamicSharedMemorySize, ATT_SMEM);
    cudaFuncSetAttribute(hmma_gemm<1>, cudaFuncAttributeMaxDynamicSharedMemorySize, GEMM_SMEM);
    cudaFuncSetAttribute(hmma_gemm<2>, cudaFuncAttributeMaxDynamicSharedMemorySize, GEMM_SMEM);
    cudaFuncSetAttribute(hmma_gemm<3>, cudaFuncAttributeMaxDynamicSharedMemorySize, GEMM_SMEM);

    // side stream for weight conversions not needed until after attention
    static cudaStream_t s_side = nullptr;
    static cudaEvent_t ev_fork = nullptr, ev_join = nullptr;
    if (s_side == nullptr) {
        cudaStreamCreateWithFlags(&s_side, cudaStreamNonBlocking);
        cudaEventCreateWithFlags(&ev_fork, cudaEventDisableTiming);
        cudaEventCreateWithFlags(&ev_join, cudaEventDisableTiming);
    }

    // fork: wo/w1/w2 conversions run concurrently with qkv GEMM + attention
    cudaEventRecord(ev_fork, (cudaStream_t)0);
    cudaStreamWaitEvent(s_side, ev_fork, 0);
    wconv16<<<(DDIM * DDIM / 8 + 255) / 256, 256, 0, s_side>>>(w_o, p_wo, DDIM * DDIM / 8);
    wconv16<<<(4 * DDIM * DDIM / 8 + 255) / 256, 256, 0, s_side>>>(w_fc1, p_w1, 4 * DDIM * DDIM / 8);
    wconv16<<<(4 * DDIM * DDIM / 8 + 255) / 256, 256, 0, s_side>>>(w_fc2, p_w2, 4 * DDIM * DDIM / 8);
    cudaEventRecord(ev_join, s_side);

    // main stream
    wconv16<<<(3 * DDIM * DDIM / 8 + 255) / 256, 256>>>(w_qkv, p_wq, 3 * DDIM * DDIM / 8);
    ln_h<<<BT, 256>>>(x, ln1_g, ln1_b, p_a16);
    hmma_gemm<3><<<dim3(3 * DDIM / 256, BT / 128), 256, GEMM_SMEM>>>(
        p_a16, p_wq, b_qkv, nullptr, nullptr, p_qv16, 3 * DDIM, DDIM);
    attn_tc<<<dim3(TTOK / 128, BB * NH), 256, ATT_SMEM>>>(p_qv16, p_a16);

    // join: side-stream conversions must be done before o-proj/fc1/fc2
    cudaStreamWaitEvent((cudaStream_t)0, ev_join, 0);

    hmma_gemm<2><<<dim3(DDIM / 256, BT / 128), 256, GEMM_SMEM>>>(
        p_a16, p_wo, b_o, x, p_x1, nullptr, DDIM, DDIM);
    ln_h<<<BT, 256>>>(p_x1, ln2_g, ln2_b, p_a16);
    hmma_gemm<1><<<dim3(4 * DDIM / 256, BT / 128), 256, GEMM_SMEM>>>(
        p_a16, p_w1, b_fc1, nullptr, nullptr, p_h16, 4 * DDIM, DDIM);
    hmma_gemm<2><<<dim3(DDIM / 256, BT / 128), 256, GEMM_SMEM>>>(
        p_h16, p_w2, b_fc2, p_x1, out, nullptr, DDIM, 4 * DDIM);
}

// round 12
// speedup vs baseline: 6.2370x; 1.0229x over previous
#include <cuda_runtime.h>
#include <cuda_fp16.h>
#include <math.h>
#include <stdint.h>

#define BB   2
#define TTOK 2048
#define DDIM 1024
#define NH   16
#define HDIM 64
#define BT   (BB*TTOK)   // 4096

// scratch (static device arrays)
__device__ float  g_x1 [BT * DDIM];
__device__ __half g_a16[BT * DDIM];
__device__ __half g_qv16[BT * 3 * DDIM];
__device__ __half g_h16[BT * 4 * DDIM];
__device__ __half g_wq16[3 * DDIM * DDIM];   // [K,N] fp16 weights
__device__ __half g_wo16[DDIM * DDIM];
__device__ __half g_w116[4 * DDIM * DDIM];
__device__ __half g_w216[4 * DDIM * DDIM];

__device__ __forceinline__ uint32_t s2u(const void* p) {
    uint32_t a;
    asm("{ .reg .u64 t; cvta.to.shared.u64 t, %1; cvt.u32.u64 %0, t; }" : "=r"(a) : "l"(p));
    return a;
}
__device__ __forceinline__ void cp16(uint32_t dst, const void* src) {
    asm volatile("cp.async.cg.shared.global [%0], [%1], 16;" :: "r"(dst), "l"(src));
}
#define CP_COMMIT() asm volatile("cp.async.commit_group;" ::: "memory")
#define CP_WAIT0()  asm volatile("cp.async.wait_group 0;" ::: "memory")
#define CP_WAIT1()  asm volatile("cp.async.wait_group 1;" ::: "memory")

__device__ __forceinline__ void ldsm4(uint32_t* r, uint32_t addr) {
    asm volatile("ldmatrix.sync.aligned.m8n8.x4.shared.b16 {%0,%1,%2,%3}, [%4];"
                 : "=r"(r[0]), "=r"(r[1]), "=r"(r[2]), "=r"(r[3]) : "r"(addr));
}
__device__ __forceinline__ void ldsm4t(uint32_t* r, uint32_t addr) {
    asm volatile("ldmatrix.sync.aligned.m8n8.x4.trans.shared.b16 {%0,%1,%2,%3}, [%4];"
                 : "=r"(r[0]), "=r"(r[1]), "=r"(r[2]), "=r"(r[3]) : "r"(addr));
}
__device__ __forceinline__ void mma_f16(float* c, const uint32_t* a,
                                        uint32_t b0, uint32_t b1) {
    asm("mma.sync.aligned.m16n8k16.row.col.f32.f16.f16.f32 "
        "{%0,%1,%2,%3}, {%4,%5,%6,%7}, {%8,%9}, {%0,%1,%2,%3};"
        : "+f"(c[0]), "+f"(c[1]), "+f"(c[2]), "+f"(c[3])
        : "r"(a[0]), "r"(a[1]), "r"(a[2]), "r"(a[3]), "r"(b0), "r"(b1));
}

__device__ __forceinline__ float gelu_f(float x) {
    float x3 = x * x * x;
    return 0.5f * x * (1.0f + tanhf(0.7978845608028654f * (x + 0.044715f * x3)));
}

// streaming fp32 -> fp16 convert
__global__ void wconv16(const float* __restrict__ W, __half* __restrict__ O, int n8) {
    int idx = blockIdx.x * 256 + threadIdx.x;
    if (idx >= n8) return;
    size_t base = (size_t)idx * 8;
    float4 a = *(const float4*)(W + base);
    float4 b = *(const float4*)(W + base + 4);
    __half2 h[4];
    h[0] = __floats2half2_rn(a.x, a.y);
    h[1] = __floats2half2_rn(a.z, a.w);
    h[2] = __floats2half2_rn(b.x, b.y);
    h[3] = __floats2half2_rn(b.z, b.w);
    *(uint4*)(O + base) = *(uint4*)h;
}

// LayerNorm -> fp16
__global__ void ln_h(const float* __restrict__ x, const float* __restrict__ g,
                     const float* __restrict__ b, __half* __restrict__ o) {
    int row = blockIdx.x;
    int tid = threadIdx.x;
    float4 v = ((const float4*)(x + (size_t)row * DDIM))[tid];
    float s  = v.x + v.y + v.z + v.w;
    float ss = v.x*v.x + v.y*v.y + v.z*v.z + v.w*v.w;
    #pragma unroll
    for (int off = 16; off > 0; off >>= 1) {
        s  += __shfl_xor_sync(0xffffffffu, s,  off);
        ss += __shfl_xor_sync(0xffffffffu, ss, off);
    }
    __shared__ float rs[8], rss[8];
    int w = tid >> 5, ln = tid & 31;
    if (ln == 0) { rs[w] = s; rss[w] = ss; }
    __syncthreads();
    float tot = 0.f, tots = 0.f;
    #pragma unroll
    for (int i = 0; i < 8; i++) { tot += rs[i]; tots += rss[i]; }
    float mu  = tot * (1.0f / DDIM);
    float var = tots * (1.0f / DDIM) - mu * mu;
    float inv = rsqrtf(var + 1e-5f);
    float4 gg = ((const float4*)g)[tid];
    float4 bb = ((const float4*)b)[tid];
    float r0 = (v.x - mu) * inv * gg.x + bb.x;
    float r1 = (v.y - mu) * inv * gg.y + bb.y;
    float r2 = (v.z - mu) * inv * gg.z + bb.z;
    float r3 = (v.w - mu) * inv * gg.w + bb.w;
    size_t base = (size_t)row * DDIM + tid * 4;
    *(__half2*)(o + base)     = __floats2half2_rn(r0, r1);
    *(__half2*)(o + base + 2) = __floats2half2_rn(r2, r3);
}

// HMMA fp16 GEMM: C[M,N] = A[M,K] @ B[K,N] + bias   (B in [K,N] row-major)
// 128x256 block, 8 warps (2Mx4N), warp 64x64, K-chunk 64, 3-stage cp.async,
// manual fragment double-buffering across k16 steps.
#define AROWB  144
#define BROWB  528
#define OFF_A  0
#define OFF_B  (128*144)
#define STG    (128*144 + 64*528)       // 52224
#define GEMM_SMEM (3 * STG)             // 156672

__device__ __forceinline__ void load_stage(
    uint32_t st, const __half* __restrict__ A, const __half* __restrict__ B,
    int N, int K, int bm, int bn, int k0, int tid)
{
    #pragma unroll
    for (int j = 0; j < 4; j++) {
        int o = tid + (j << 8);
        int r = o >> 3, c = o & 7;
        cp16(st + OFF_A + (uint32_t)(r * AROWB + (c << 4)),
             A + (size_t)(bm + r) * K + k0 + (c << 3));
    }
    #pragma unroll
    for (int j = 0; j < 8; j++) {
        int o = tid + (j << 8);
        int r = o >> 5, c = o & 31;
        cp16(st + OFF_B + (uint32_t)(r * BROWB + (c << 4)),
             B + (size_t)(k0 + r) * N + bn + (c << 3));
    }
}

__device__ __forceinline__ void load_frags(
    uint32_t st, int ks, int wm, int wn, int arow, int acol, int bg, int brow,
    uint32_t aF[4][4], uint32_t bF[8][2])
{
    #pragma unroll
    for (int mi = 0; mi < 4; mi++) {
        uint32_t off = (uint32_t)(((wm << 6) + (mi << 4) + arow) * AROWB
                                  + ((ks << 4) + acol) * 2);
        ldsm4(aF[mi], st + OFF_A + off);
    }
    #pragma unroll
    for (int np = 0; np < 4; np++) {
        uint32_t off = (uint32_t)(((ks << 4) + ((bg & 1) << 3) + brow) * BROWB
                                  + ((wn << 6) + (np << 4) + ((bg >> 1) << 3)) * 2);
        uint32_t r[4];
        ldsm4t(r, st + OFF_B + off);
        bF[2*np][0]   = r[0]; bF[2*np][1]   = r[1];
        bF[2*np+1][0] = r[2]; bF[2*np+1][1] = r[3];
    }
}

template<int EPI>
__global__ void __launch_bounds__(256, 1) hmma_gemm(
    const __half* __restrict__ A, const __half* __restrict__ B,
    const float* __restrict__ bias, const float* __restrict__ res,
    float* __restrict__ Cf, __half* __restrict__ Ch, int N, int K)
{
    extern __shared__ __align__(1024) char smem[];
    uint32_t sb = s2u(smem);
    int tid = threadIdx.x, wid = tid >> 5, lane = tid & 31;
    int wm = wid & 1, wn = wid >> 1;
    int bm = blockIdx.y << 7, bn = blockIdx.x << 8;

    float acc[4][8][4];
    #pragma unroll
    for (int mi = 0; mi < 4; mi++)
        #pragma unroll
        for (int ni = 0; ni < 8; ni++)
            #pragma unroll
            for (int e = 0; e < 4; e++) acc[mi][ni][e] = 0.f;

    int nch = K >> 6;
    load_stage(sb,       A, B, N, K, bm, bn, 0,  tid); CP_COMMIT();
    load_stage(sb + STG, A, B, N, K, bm, bn, 64, tid); CP_COMMIT();

    int arow = lane & 15;
    int acol = (lane >> 4) << 3;
    int bg   = lane >> 3;
    int brow = lane & 7;

    uint32_t aF[2][4][4], bF[2][8][2];

    for (int i = 0; i < nch; i++) {
        CP_WAIT1();
        __syncthreads();
        if (i + 2 < nch)
            load_stage(sb + (uint32_t)((i + 2) % 3) * STG,
                       A, B, N, K, bm, bn, (i + 2) << 6, tid);
        CP_COMMIT();
        uint32_t st = sb + (uint32_t)(i % 3) * STG;
        load_frags(st, 0, wm, wn, arow, acol, bg, brow, aF[0], bF[0]);
        #pragma unroll
        for (int ks = 0; ks < 4; ks++) {
            int cur = ks & 1;
            if (ks < 3)
                load_frags(st, ks + 1, wm, wn, arow, acol, bg, brow,
                           aF[cur ^ 1], bF[cur ^ 1]);
            #pragma unroll
            for (int mi = 0; mi < 4; mi++)
                #pragma unroll
                for (int ni = 0; ni < 8; ni++)
                    mma_f16(acc[mi][ni], aF[cur][mi], bF[cur][ni][0], bF[cur][ni][1]);
        }
    }

    __syncthreads();
    #pragma unroll
    for (int mi = 0; mi < 4; mi++) {
        #pragma unroll
        for (int ni = 0; ni < 8; ni++) {
            int row0 = bm + (wm << 6) + (mi << 4) + (lane >> 2);
            int col  = bn + (wn << 6) + (ni << 3) + ((lane & 3) << 1);
            float b0 = __ldg(bias + col), b1 = __ldg(bias + col + 1);
            #pragma unroll
            for (int hf = 0; hf < 2; hf++) {
                int row = row0 + hf * 8;
                float v0 = acc[mi][ni][hf * 2 + 0] + b0;
                float v1 = acc[mi][ni][hf * 2 + 1] + b1;
                size_t oi = (size_t)row * N + col;
                if (EPI == 2) {
                    float2 rv = *(const float2*)(res + oi);
                    float2 ov; ov.x = v0 + rv.x; ov.y = v1 + rv.y;
                    *(float2*)(Cf + oi) = ov;
                } else {
                    float a0 = (EPI == 1) ? gelu_f(v0) : v0;
                    float a1 = (EPI == 1) ? gelu_f(v1) : v1;
                    *(__half2*)(Ch + oi) = __floats2half2_rn(a0, a1);
                }
            }
        }
    }
}

// fp16 flash attention: BQ=128 (8 warps x 16 rows), BK=128, hd=64
#define AQ_STRIDE 144
#define SM_Q   0
#define SM_KV0 18432
#define KV_STG 36864                 // K 128x144 + V 128x144
#define VOFF   18432
#define ATT_SMEM (SM_KV0 + 2 * KV_STG)   // 92160

__device__ __forceinline__ void att_load_kv(
    uint32_t base, const __half* __restrict__ qv, size_t kvrow0, int tid)
{
    const size_t TD3 = 3 * DDIM;
    #pragma unroll
    for (int i = 0; i < 8; i++) {
        int e = tid + (i << 8);       // 0..2047
        int t = e >> 10;              // 0 K, 1 V
        int rem = e & 1023;
        int r = rem >> 3, c = rem & 7;   // 128 rows x 8 x 16B
        size_t off = (kvrow0 + r) * TD3 + (t ? 2 * DDIM : DDIM) + (c << 3);
        cp16(base + (t ? (uint32_t)VOFF : 0u) + r * AQ_STRIDE + (c << 4), qv + off);
    }
}

__global__ void __launch_bounds__(256, 1) attn_tc(
    const __half* __restrict__ qv, __half* __restrict__ o16)
{
    extern __shared__ __align__(1024) char smem[];
    uint32_t sb = s2u(smem);
    int qt = (int)gridDim.x - 1 - (int)blockIdx.x;
    int b  = blockIdx.y >> 4;
    int h  = blockIdx.y & 15;
    int tid = threadIdx.x, wid = tid >> 5, lane = tid & 31;
    const size_t TD3 = 3 * DDIM;
    size_t qrow0 = (size_t)b * TTOK + (size_t)qt * 128;
    const __half* qv_head = qv + h * HDIM;

    #pragma unroll
    for (int i = 0; i < 4; i++) {
        int e = tid + (i << 8);
        int r = e >> 3, c = e & 7;
        cp16(sb + SM_Q + r * AQ_STRIDE + (c << 4),
             qv_head + (qrow0 + r) * TD3 + (c << 3));
    }
    att_load_kv(sb + SM_KV0, qv_head, (size_t)b * TTOK, tid);
    CP_COMMIT();

    uint32_t qf[4][4];
    float O[8][4];
    #pragma unroll
    for (int n = 0; n < 8; n++)
        #pragma unroll
        for (int e = 0; e < 4; e++) O[n][e] = 0.f;
    float m0 = -1e30f, m1 = -1e30f, l0 = 0.f, l1 = 0.f;

    int bg = lane >> 3, brow = lane & 7;
    int ntiles = qt + 1;
    bool qloaded = false;

    for (int j = 0; j < ntiles; j++) {
        CP_WAIT0();
        __syncthreads();
        if (j + 1 < ntiles) {
            att_load_kv(sb + SM_KV0 + (uint32_t)((j + 1) & 1) * KV_STG,
                        qv_head, (size_t)b * TTOK + (size_t)(j + 1) * 128, tid);
            CP_COMMIT();
        }
        if (!qloaded) {
            qloaded = true;
            #pragma unroll
            for (int kc = 0; kc < 4; kc++) {
                uint32_t aoff = (uint32_t)((wid * 16 + (lane & 15)) * AQ_STRIDE
                                           + ((kc << 4) + ((lane >> 4) << 3)) * 2);
                ldsm4(qf[kc], sb + SM_Q + aoff);
            }
        }

        uint32_t kb = sb + SM_KV0 + (uint32_t)(j & 1) * KV_STG;

        // ---- S = Q K^T over 128 kv cols ----
        float S[16][4];
        #pragma unroll
        for (int n = 0; n < 16; n++)
            #pragma unroll
            for (int e = 0; e < 4; e++) S[n][e] = 0.f;
        #pragma unroll
        for (int p = 0; p < 8; p++) {
            #pragma unroll
            for (int kc = 0; kc < 4; kc++) {
                uint32_t koff = (uint32_t)(((p << 4) + ((bg >> 1) << 3) + brow) * AQ_STRIDE
                                           + ((kc << 4) + ((bg & 1) << 3)) * 2);
                uint32_t rh[4];
                ldsm4(rh, kb + koff);
                mma_f16(S[2*p],   qf[kc], rh[0], rh[1]);
                mma_f16(S[2*p+1], qf[kc], rh[2], rh[3]);
            }
        }

        // ---- scale + causal mask (only the diagonal tile) ----
        int row0 = qt * 128 + wid * 16 + (lane >> 2);
        int row1 = row0 + 8;
        int cbase = j * 128 + ((lane & 3) << 1);
        bool need_mask = (j == qt);
        #pragma unroll
        for (int n = 0; n < 16; n++) {
            #pragma unroll
            for (int e = 0; e < 4; e++) S[n][e] *= 0.125f;
            if (need_mask) {
                int c0 = cbase + n * 8;
                if (c0     > row0) S[n][0] = -1e30f;
                if (c0 + 1 > row0) S[n][1] = -1e30f;
                if (c0     > row1) S[n][2] = -1e30f;
                if (c0 + 1 > row1) S[n][3] = -1e30f;
            }
        }

        // ---- online softmax (quad reduce; rows warp-local) ----
        float mr0 = -1e30f, mr1 = -1e30f;
        #pragma unroll
        for (int n = 0; n < 16; n++) {
            mr0 = fmaxf(mr0, fmaxf(S[n][0], S[n][1]));
            mr1 = fmaxf(mr1, fmaxf(S[n][2], S[n][3]));
        }
        mr0 = fmaxf(mr0, __shfl_xor_sync(0xffffffffu, mr0, 1));
        mr0 = fmaxf(mr0, __shfl_xor_sync(0xffffffffu, mr0, 2));
        mr1 = fmaxf(mr1, __shfl_xor_sync(0xffffffffu, mr1, 1));
        mr1 = fmaxf(mr1, __shfl_xor_sync(0xffffffffu, mr1, 2));
        float mn0 = fmaxf(m0, mr0), mn1 = fmaxf(m1, mr1);
        float alpha0 = __expf(m0 - mn0), alpha1 = __expf(m1 - mn1);
        float sum0 = 0.f, sum1 = 0.f;
        #pragma unroll
        for (int n = 0; n < 16; n++) {
            S[n][0] = __expf(S[n][0] - mn0); sum0 += S[n][0];
            S[n][1] = __expf(S[n][1] - mn0); sum0 += S[n][1];
            S[n][2] = __expf(S[n][2] - mn1); sum1 += S[n][2];
            S[n][3] = __expf(S[n][3] - mn1); sum1 += S[n][3];
        }
        sum0 += __shfl_xor_sync(0xffffffffu, sum0, 1);
        sum0 += __shfl_xor_sync(0xffffffffu, sum0, 2);
        sum1 += __shfl_xor_sync(0xffffffffu, sum1, 1);
        sum1 += __shfl_xor_sync(0xffffffffu, sum1, 2);
        l0 = l0 * alpha0 + sum0;
        l1 = l1 * alpha1 + sum1;
        m0 = mn0; m1 = mn1;
        #pragma unroll
        for (int n = 0; n < 8; n++) {
            O[n][0] *= alpha0; O[n][1] *= alpha0;
            O[n][2] *= alpha1; O[n][3] *= alpha1;
        }

        // ---- O += P V over 128 kv rows ----
        #pragma unroll
        for (int kc = 0; kc < 8; kc++) {
            uint32_t pf[4];
            __half2 t0 = __floats2half2_rn(S[2*kc][0],   S[2*kc][1]);
            __half2 t1 = __floats2half2_rn(S[2*kc][2],   S[2*kc][3]);
            __half2 t2 = __floats2half2_rn(S[2*kc+1][0], S[2*kc+1][1]);
            __half2 t3 = __floats2half2_rn(S[2*kc+1][2], S[2*kc+1][3]);
            pf[0] = *(uint32_t*)&t0;
            pf[1] = *(uint32_t*)&t1;
            pf[2] = *(uint32_t*)&t2;
            pf[3] = *(uint32_t*)&t3;
            #pragma unroll
            for (int np = 0; np < 4; np++) {
                uint32_t voff = (uint32_t)(((kc << 4) + ((bg & 1) << 3) + brow) * AQ_STRIDE
                                           + ((np << 4) + ((bg >> 1) << 3)) * 2);
                uint32_t rv[4];
                ldsm4t(rv, kb + VOFF + voff);
                mma_f16(O[2*np],   pf, rv[0], rv[1]);
                mma_f16(O[2*np+1], pf, rv[2], rv[3]);
            }
        }
    }

    float inv0 = 1.0f / l0, inv1 = 1.0f / l1;
    size_t row0g = qrow0 + wid * 16 + (lane >> 2);
    int colb = h * HDIM + ((lane & 3) << 1);
    #pragma unroll
    for (int n = 0; n < 8; n++) {
        int col = colb + n * 8;
        *(__half2*)(o16 + row0g * DDIM + col) =
            __floats2half2_rn(O[n][0] * inv0, O[n][1] * inv0);
        *(__half2*)(o16 + (row0g + 8) * DDIM + col) =
            __floats2half2_rn(O[n][2] * inv1, O[n][3] * inv1);
    }
}

extern "C" void kernel_launch(void* const* d_in, const int* in_sizes, int n_in,
                              void* d_out, int out_size) {
    const float* x      = (const float*)d_in[0];
    const float* ln1_g  = (const float*)d_in[1];
    const float* ln1_b  = (const float*)d_in[2];
    const float* ln2_g  = (const float*)d_in[3];
    const float* ln2_b  = (const float*)d_in[4];
    const float* w_qkv  = (const float*)d_in[5];
    const float* b_qkv  = (const float*)d_in[6];
    const float* w_o    = (const float*)d_in[7];
    const float* b_o    = (const float*)d_in[8];
    const float* w_fc1  = (const float*)d_in[9];
    const float* b_fc1  = (const float*)d_in[10];
    const float* w_fc2  = (const float*)d_in[11];
    const float* b_fc2  = (const float*)d_in[12];
    float* out = (float*)d_out;

    float* p_x1;
    __half *p_a16, *p_qv16, *p_h16, *p_wq, *p_wo, *p_w1, *p_w2;
    cudaGetSymbolAddress((void**)&p_x1,   g_x1);
    cudaGetSymbolAddress((void**)&p_a16,  g_a16);
    cudaGetSymbolAddress((void**)&p_qv16, g_qv16);
    cudaGetSymbolAddress((void**)&p_h16,  g_h16);
    cudaGetSymbolAddress((void**)&p_wq,   g_wq16);
    cudaGetSymbolAddress((void**)&p_wo,   g_wo16);
    cudaGetSymbolAddress((void**)&p_w1,   g_w116);
    cudaGetSymbolAddress((void**)&p_w2,   g_w216);

    cudaFuncSetAttribute(attn_tc, cudaFuncAttributeMaxDynamicSharedMemorySize, ATT_SMEM);
    cudaFuncSetAttribute(hmma_gemm<1>, cudaFuncAttributeMaxDynamicSharedMemorySize, GEMM_SMEM);
    cudaFuncSetAttribute(hmma_gemm<2>, cudaFuncAttributeMaxDynamicSharedMemorySize, GEMM_SMEM);
    cudaFuncSetAttribute(hmma_gemm<3>, cudaFuncAttributeMaxDynamicSharedMemorySize, GEMM_SMEM);

    static cudaStream_t s_side = nullptr;
    static cudaEvent_t ev_fork = nullptr, ev_ln = nullptr, ev_join = nullptr;
    if (s_side == nullptr) {
        cudaStreamCreateWithFlags(&s_side, cudaStreamNonBlocking);
        cudaEventCreateWithFlags(&ev_fork, cudaEventDisableTiming);
        cudaEventCreateWithFlags(&ev_ln,   cudaEventDisableTiming);
        cudaEventCreateWithFlags(&ev_join, cudaEventDisableTiming);
    }

    // fork: side stream does ln1 (needed before qkv GEMM) then wo/w1/w2 converts
    cudaEventRecord(ev_fork, (cudaStream_t)0);
    cudaStreamWaitEvent(s_side, ev_fork, 0);
    ln_h<<<BT, 256, 0, s_side>>>(x, ln1_g, ln1_b, p_a16);
    cudaEventRecord(ev_ln, s_side);
    wconv16<<<(DDIM * DDIM / 8 + 255) / 256, 256, 0, s_side>>>(w_o, p_wo, DDIM * DDIM / 8);
    wconv16<<<(4 * DDIM * DDIM / 8 + 255) / 256, 256, 0, s_side>>>(w_fc1, p_w1, 4 * DDIM * DDIM / 8);
    wconv16<<<(4 * DDIM * DDIM / 8 + 255) / 256, 256, 0, s_side>>>(w_fc2, p_w2, 4 * DDIM * DDIM / 8);
    cudaEventRecord(ev_join, s_side);

    // main stream
    wconv16<<<(3 * DDIM * DDIM / 8 + 255) / 256, 256>>>(w_qkv, p_wq, 3 * DDIM * DDIM / 8);
    cudaStreamWaitEvent((cudaStream_t)0, ev_ln, 0);
    hmma_gemm<3><<<dim3(3 * DDIM / 256, BT / 128), 256, GEMM_SMEM>>>(
        p_a16, p_wq, b_qkv, nullptr, nullptr, p_qv16, 3 * DDIM, DDIM);
    attn_tc<<<dim3(TTOK / 128, BB * NH), 256, ATT_SMEM>>>(p_qv16, p_a16);
    cudaStreamWaitEvent((cudaStream_t)0, ev_join, 0);
    hmma_gemm<2><<<dim3(DDIM / 256, BT / 128), 256, GEMM_SMEM>>>(
        p_a16, p_wo, b_o, x, p_x1, nullptr, DDIM, DDIM);
    ln_h<<<BT, 256>>>(p_x1, ln2_g, ln2_b, p_a16);
    hmma_gemm<1><<<dim3(4 * DDIM / 256, BT / 128), 256, GEMM_SMEM>>>(
        p_a16, p_w1, b_fc1, nullptr, nullptr, p_h16, 4 * DDIM, DDIM);
    hmma_gemm<2><<<dim3(DDIM / 256, BT / 128), 256, GEMM_SMEM>>>(
        p_h16, p_w2, b_fc2, p_x1, out, nullptr, DDIM, 4 * DDIM);
}

// round 13
// speedup vs baseline: 6.4126x; 1.0282x over previous
#include <cuda_runtime.h>
#include <cuda_fp16.h>
#include <math.h>
#include <stdint.h>

#define BB   2
#define TTOK 2048
#define DDIM 1024
#define NH   16
#define HDIM 64
#define BT   (BB*TTOK)   // 4096

// scratch (static device arrays)
__device__ float  g_x1 [BT * DDIM];
__device__ __half g_a16[BT * DDIM];
__device__ __half g_qv16[BT * 3 * DDIM];
__device__ __half g_h16[BT * 4 * DDIM];
__device__ __half g_wq16[3 * DDIM * DDIM];   // [K,N] fp16 weights
__device__ __half g_wo16[DDIM * DDIM];
__device__ __half g_w116[4 * DDIM * DDIM];
__device__ __half g_w216[4 * DDIM * DDIM];

__device__ __forceinline__ uint32_t s2u(const void* p) {
    uint32_t a;
    asm("{ .reg .u64 t; cvta.to.shared.u64 t, %1; cvt.u32.u64 %0, t; }" : "=r"(a) : "l"(p));
    return a;
}
__device__ __forceinline__ void cp16(uint32_t dst, const void* src) {
    asm volatile("cp.async.cg.shared.global [%0], [%1], 16;" :: "r"(dst), "l"(src));
}
#define CP_COMMIT() asm volatile("cp.async.commit_group;" ::: "memory")
#define CP_WAIT0()  asm volatile("cp.async.wait_group 0;" ::: "memory")

__device__ __forceinline__ void ldsm4(uint32_t* r, uint32_t addr) {
    asm volatile("ldmatrix.sync.aligned.m8n8.x4.shared.b16 {%0,%1,%2,%3}, [%4];"
                 : "=r"(r[0]), "=r"(r[1]), "=r"(r[2]), "=r"(r[3]) : "r"(addr));
}
__device__ __forceinline__ void ldsm4t(uint32_t* r, uint32_t addr) {
    asm volatile("ldmatrix.sync.aligned.m8n8.x4.trans.shared.b16 {%0,%1,%2,%3}, [%4];"
                 : "=r"(r[0]), "=r"(r[1]), "=r"(r[2]), "=r"(r[3]) : "r"(addr));
}
__device__ __forceinline__ void mma_f16(float* c, const uint32_t* a,
                                        uint32_t b0, uint32_t b1) {
    asm("mma.sync.aligned.m16n8k16.row.col.f32.f16.f16.f32 "
        "{%0,%1,%2,%3}, {%4,%5,%6,%7}, {%8,%9}, {%0,%1,%2,%3};"
        : "+f"(c[0]), "+f"(c[1]), "+f"(c[2]), "+f"(c[3])
        : "r"(a[0]), "r"(a[1]), "r"(a[2]), "r"(a[3]), "r"(b0), "r"(b1));
}

__device__ __forceinline__ float gelu_f(float x) {
    float x3 = x * x * x;
    return 0.5f * x * (1.0f + tanhf(0.7978845608028654f * (x + 0.044715f * x3)));
}

// streaming fp32 -> fp16 convert
__global__ void wconv16(const float* __restrict__ W, __half* __restrict__ O, int n8) {
    int idx = blockIdx.x * 256 + threadIdx.x;
    if (idx >= n8) return;
    size_t base = (size_t)idx * 8;
    float4 a = *(const float4*)(W + base);
    float4 b = *(const float4*)(W + base + 4);
    __half2 h[4];
    h[0] = __floats2half2_rn(a.x, a.y);
    h[1] = __floats2half2_rn(a.z, a.w);
    h[2] = __floats2half2_rn(b.x, b.y);
    h[3] = __floats2half2_rn(b.z, b.w);
    *(uint4*)(O + base) = *(uint4*)h;
}

// LayerNorm -> fp16
__global__ void ln_h(const float* __restrict__ x, const float* __restrict__ g,
                     const float* __restrict__ b, __half* __restrict__ o) {
    int row = blockIdx.x;
    int tid = threadIdx.x;
    float4 v = ((const float4*)(x + (size_t)row * DDIM))[tid];
    float s  = v.x + v.y + v.z + v.w;
    float ss = v.x*v.x + v.y*v.y + v.z*v.z + v.w*v.w;
    #pragma unroll
    for (int off = 16; off > 0; off >>= 1) {
        s  += __shfl_xor_sync(0xffffffffu, s,  off);
        ss += __shfl_xor_sync(0xffffffffu, ss, off);
    }
    __shared__ float rs[8], rss[8];
    int w = tid >> 5, ln = tid & 31;
    if (ln == 0) { rs[w] = s; rss[w] = ss; }
    __syncthreads();
    float tot = 0.f, tots = 0.f;
    #pragma unroll
    for (int i = 0; i < 8; i++) { tot += rs[i]; tots += rss[i]; }
    float mu  = tot * (1.0f / DDIM);
    float var = tots * (1.0f / DDIM) - mu * mu;
    float inv = rsqrtf(var + 1e-5f);
    float4 gg = ((const float4*)g)[tid];
    float4 bb = ((const float4*)b)[tid];
    float r0 = (v.x - mu) * inv * gg.x + bb.x;
    float r1 = (v.y - mu) * inv * gg.y + bb.y;
    float r2 = (v.z - mu) * inv * gg.z + bb.z;
    float r3 = (v.w - mu) * inv * gg.w + bb.w;
    size_t base = (size_t)row * DDIM + tid * 4;
    *(__half2*)(o + base)     = __floats2half2_rn(r0, r1);
    *(__half2*)(o + base + 2) = __floats2half2_rn(r2, r3);
}

// HMMA fp16 GEMM: C[M,N] = A[M,K] @ B[K,N] + bias   (B in [K,N] row-major)
// 128x256 block, 8 warps (2Mx4N), warp 64x64, K-chunk 128, 2-stage cp.async,
// manual fragment double-buffering across k16 steps.
#define AROWB  272                       // 128 fp16 (256B) + 16B pad
#define BROWB  528                       // 256 fp16 (512B) + 16B pad
#define OFF_A  0
#define OFF_B  (128*272)                 // 34816
#define STG    (128*272 + 128*528)       // 102400
#define GEMM_SMEM (2 * STG)              // 204800

__device__ __forceinline__ void load_stage(
    uint32_t st, const __half* __restrict__ A, const __half* __restrict__ B,
    int N, int K, int bm, int bn, int k0, int tid)
{
    #pragma unroll
    for (int j = 0; j < 8; j++) {                 // A: 128 rows x 16 x 16B
        int o = tid + (j << 8);
        int r = o >> 4, c = o & 15;
        cp16(st + OFF_A + (uint32_t)(r * AROWB + (c << 4)),
             A + (size_t)(bm + r) * K + k0 + (c << 3));
    }
    #pragma unroll
    for (int j = 0; j < 16; j++) {                // B: 128 k-rows x 32 x 16B
        int o = tid + (j << 8);
        int r = o >> 5, c = o & 31;
        cp16(st + OFF_B + (uint32_t)(r * BROWB + (c << 4)),
             B + (size_t)(k0 + r) * N + bn + (c << 3));
    }
}

__device__ __forceinline__ void load_frags(
    uint32_t st, int ks, int wm, int wn, int arow, int acol, int bg, int brow,
    uint32_t aF[4][4], uint32_t bF[8][2])
{
    #pragma unroll
    for (int mi = 0; mi < 4; mi++) {
        uint32_t off = (uint32_t)(((wm << 6) + (mi << 4) + arow) * AROWB
                                  + ((ks << 4) + acol) * 2);
        ldsm4(aF[mi], st + OFF_A + off);
    }
    #pragma unroll
    for (int np = 0; np < 4; np++) {
        uint32_t off = (uint32_t)(((ks << 4) + ((bg & 1) << 3) + brow) * BROWB
                                  + ((wn << 6) + (np << 4) + ((bg >> 1) << 3)) * 2);
        uint32_t r[4];
        ldsm4t(r, st + OFF_B + off);
        bF[2*np][0]   = r[0]; bF[2*np][1]   = r[1];
        bF[2*np+1][0] = r[2]; bF[2*np+1][1] = r[3];
    }
}

template<int EPI>
__global__ void __launch_bounds__(256, 1) hmma_gemm(
    const __half* __restrict__ A, const __half* __restrict__ B,
    const float* __restrict__ bias, const float* __restrict__ res,
    float* __restrict__ Cf, __half* __restrict__ Ch, int N, int K)
{
    extern __shared__ __align__(1024) char smem[];
    uint32_t sb = s2u(smem);
    int tid = threadIdx.x, wid = tid >> 5, lane = tid & 31;
    int wm = wid & 1, wn = wid >> 1;
    int bm = blockIdx.y << 7, bn = blockIdx.x << 8;

    float acc[4][8][4];
    #pragma unroll
    for (int mi = 0; mi < 4; mi++)
        #pragma unroll
        for (int ni = 0; ni < 8; ni++)
            #pragma unroll
            for (int e = 0; e < 4; e++) acc[mi][ni][e] = 0.f;

    int nch = K >> 7;
    load_stage(sb, A, B, N, K, bm, bn, 0, tid);
    CP_COMMIT();

    int arow = lane & 15;
    int acol = (lane >> 4) << 3;
    int bg   = lane >> 3;
    int brow = lane & 7;

    uint32_t aF[2][4][4], bF[2][8][2];

    for (int i = 0; i < nch; i++) {
        CP_WAIT0();
        __syncthreads();
        if (i + 1 < nch) {
            load_stage(sb + (uint32_t)((i + 1) & 1) * STG,
                       A, B, N, K, bm, bn, (i + 1) << 7, tid);
            CP_COMMIT();
        }
        uint32_t st = sb + (uint32_t)(i & 1) * STG;
        load_frags(st, 0, wm, wn, arow, acol, bg, brow, aF[0], bF[0]);
        #pragma unroll
        for (int ks = 0; ks < 8; ks++) {
            int cur = ks & 1;
            if (ks < 7)
                load_frags(st, ks + 1, wm, wn, arow, acol, bg, brow,
                           aF[cur ^ 1], bF[cur ^ 1]);
            #pragma unroll
            for (int mi = 0; mi < 4; mi++)
                #pragma unroll
                for (int ni = 0; ni < 8; ni++)
                    mma_f16(acc[mi][ni], aF[cur][mi], bF[cur][ni][0], bF[cur][ni][1]);
        }
    }

    __syncthreads();
    #pragma unroll
    for (int mi = 0; mi < 4; mi++) {
        #pragma unroll
        for (int ni = 0; ni < 8; ni++) {
            int row0 = bm + (wm << 6) + (mi << 4) + (lane >> 2);
            int col  = bn + (wn << 6) + (ni << 3) + ((lane & 3) << 1);
            float b0 = __ldg(bias + col), b1 = __ldg(bias + col + 1);
            #pragma unroll
            for (int hf = 0; hf < 2; hf++) {
                int row = row0 + hf * 8;
                float v0 = acc[mi][ni][hf * 2 + 0] + b0;
                float v1 = acc[mi][ni][hf * 2 + 1] + b1;
                size_t oi = (size_t)row * N + col;
                if (EPI == 2) {
                    float2 rv = *(const float2*)(res + oi);
                    float2 ov; ov.x = v0 + rv.x; ov.y = v1 + rv.y;
                    *(float2*)(Cf + oi) = ov;
                } else {
                    float a0 = (EPI == 1) ? gelu_f(v0) : v0;
                    float a1 = (EPI == 1) ? gelu_f(v1) : v1;
                    *(__half2*)(Ch + oi) = __floats2half2_rn(a0, a1);
                }
            }
        }
    }
}

// fp16 flash attention: BQ=128 (8 warps x 16 rows), BK=128, hd=64
#define AQ_STRIDE 144
#define SM_Q   0
#define SM_KV0 18432
#define KV_STG 36864                 // K 128x144 + V 128x144
#define VOFF   18432
#define ATT_SMEM (SM_KV0 + 2 * KV_STG)   // 92160

__device__ __forceinline__ void att_load_kv(
    uint32_t base, const __half* __restrict__ qv, size_t kvrow0, int tid)
{
    const size_t TD3 = 3 * DDIM;
    #pragma unroll
    for (int i = 0; i < 8; i++) {
        int e = tid + (i << 8);       // 0..2047
        int t = e >> 10;              // 0 K, 1 V
        int rem = e & 1023;
        int r = rem >> 3, c = rem & 7;
        size_t off = (kvrow0 + r) * TD3 + (t ? 2 * DDIM : DDIM) + (c << 3);
        cp16(base + (t ? (uint32_t)VOFF : 0u) + r * AQ_STRIDE + (c << 4), qv + off);
    }
}

__global__ void __launch_bounds__(256, 1) attn_tc(
    const __half* __restrict__ qv, __half* __restrict__ o16)
{
    extern __shared__ __align__(1024) char smem[];
    uint32_t sb = s2u(smem);
    int qt = (int)gridDim.x - 1 - (int)blockIdx.x;
    int b  = blockIdx.y >> 4;
    int h  = blockIdx.y & 15;
    int tid = threadIdx.x, wid = tid >> 5, lane = tid & 31;
    const size_t TD3 = 3 * DDIM;
    size_t qrow0 = (size_t)b * TTOK + (size_t)qt * 128;
    const __half* qv_head = qv + h * HDIM;

    #pragma unroll
    for (int i = 0; i < 4; i++) {
        int e = tid + (i << 8);
        int r = e >> 3, c = e & 7;
        cp16(sb + SM_Q + r * AQ_STRIDE + (c << 4),
             qv_head + (qrow0 + r) * TD3 + (c << 3));
    }
    att_load_kv(sb + SM_KV0, qv_head, (size_t)b * TTOK, tid);
    CP_COMMIT();

    uint32_t qf[4][4];
    float O[8][4];
    #pragma unroll
    for (int n = 0; n < 8; n++)
        #pragma unroll
        for (int e = 0; e < 4; e++) O[n][e] = 0.f;
    float m0 = -1e30f, m1 = -1e30f, l0 = 0.f, l1 = 0.f;

    int bg = lane >> 3, brow = lane & 7;
    int ntiles = qt + 1;
    bool qloaded = false;

    for (int j = 0; j < ntiles; j++) {
        CP_WAIT0();
        __syncthreads();
        if (j + 1 < ntiles) {
            att_load_kv(sb + SM_KV0 + (uint32_t)((j + 1) & 1) * KV_STG,
                        qv_head, (size_t)b * TTOK + (size_t)(j + 1) * 128, tid);
            CP_COMMIT();
        }
        if (!qloaded) {
            qloaded = true;
            #pragma unroll
            for (int kc = 0; kc < 4; kc++) {
                uint32_t aoff = (uint32_t)((wid * 16 + (lane & 15)) * AQ_STRIDE
                                           + ((kc << 4) + ((lane >> 4) << 3)) * 2);
                ldsm4(qf[kc], sb + SM_Q + aoff);
            }
        }

        uint32_t kb = sb + SM_KV0 + (uint32_t)(j & 1) * KV_STG;

        float S[16][4];
        #pragma unroll
        for (int n = 0; n < 16; n++)
            #pragma unroll
            for (int e = 0; e < 4; e++) S[n][e] = 0.f;
        #pragma unroll
        for (int p = 0; p < 8; p++) {
            #pragma unroll
            for (int kc = 0; kc < 4; kc++) {
                uint32_t koff = (uint32_t)(((p << 4) + ((bg >> 1) << 3) + brow) * AQ_STRIDE
                                           + ((kc << 4) + ((bg & 1) << 3)) * 2);
                uint32_t rh[4];
                ldsm4(rh, kb + koff);
                mma_f16(S[2*p],   qf[kc], rh[0], rh[1]);
                mma_f16(S[2*p+1], qf[kc], rh[2], rh[3]);
            }
        }

        int row0 = qt * 128 + wid * 16 + (lane >> 2);
        int row1 = row0 + 8;
        int cbase = j * 128 + ((lane & 3) << 1);
        bool need_mask = (j == qt);
        #pragma unroll
        for (int n = 0; n < 16; n++) {
            #pragma unroll
            for (int e = 0; e < 4; e++) S[n][e] *= 0.125f;
            if (need_mask) {
                int c0 = cbase + n * 8;
                if (c0     > row0) S[n][0] = -1e30f;
                if (c0 + 1 > row0) S[n][1] = -1e30f;
                if (c0     > row1) S[n][2] = -1e30f;
                if (c0 + 1 > row1) S[n][3] = -1e30f;
            }
        }

        float mr0 = -1e30f, mr1 = -1e30f;
        #pragma unroll
        for (int n = 0; n < 16; n++) {
            mr0 = fmaxf(mr0, fmaxf(S[n][0], S[n][1]));
            mr1 = fmaxf(mr1, fmaxf(S[n][2], S[n][3]));
        }
        mr0 = fmaxf(mr0, __shfl_xor_sync(0xffffffffu, mr0, 1));
        mr0 = fmaxf(mr0, __shfl_xor_sync(0xffffffffu, mr0, 2));
        mr1 = fmaxf(mr1, __shfl_xor_sync(0xffffffffu, mr1, 1));
        mr1 = fmaxf(mr1, __shfl_xor_sync(0xffffffffu, mr1, 2));
        float mn0 = fmaxf(m0, mr0), mn1 = fmaxf(m1, mr1);
        float alpha0 = __expf(m0 - mn0), alpha1 = __expf(m1 - mn1);
        float sum0 = 0.f, sum1 = 0.f;
        #pragma unroll
        for (int n = 0; n < 16; n++) {
            S[n][0] = __expf(S[n][0] - mn0); sum0 += S[n][0];
            S[n][1] = __expf(S[n][1] - mn0); sum0 += S[n][1];
            S[n][2] = __expf(S[n][2] - mn1); sum1 += S[n][2];
            S[n][3] = __expf(S[n][3] - mn1); sum1 += S[n][3];
        }
        sum0 += __shfl_xor_sync(0xffffffffu, sum0, 1);
        sum0 += __shfl_xor_sync(0xffffffffu, sum0, 2);
        sum1 += __shfl_xor_sync(0xffffffffu, sum1, 1);
        sum1 += __shfl_xor_sync(0xffffffffu, sum1, 2);
        l0 = l0 * alpha0 + sum0;
        l1 = l1 * alpha1 + sum1;
        m0 = mn0; m1 = mn1;
        #pragma unroll
        for (int n = 0; n < 8; n++) {
            O[n][0] *= alpha0; O[n][1] *= alpha0;
            O[n][2] *= alpha1; O[n][3] *= alpha1;
        }

        #pragma unroll
        for (int kc = 0; kc < 8; kc++) {
            uint32_t pf[4];
            __half2 t0 = __floats2half2_rn(S[2*kc][0],   S[2*kc][1]);
            __half2 t1 = __floats2half2_rn(S[2*kc][2],   S[2*kc][3]);
            __half2 t2 = __floats2half2_rn(S[2*kc+1][0], S[2*kc+1][1]);
            __half2 t3 = __floats2half2_rn(S[2*kc+1][2], S[2*kc+1][3]);
            pf[0] = *(uint32_t*)&t0;
            pf[1] = *(uint32_t*)&t1;
            pf[2] = *(uint32_t*)&t2;
            pf[3] = *(uint32_t*)&t3;
            #pragma unroll
            for (int np = 0; np < 4; np++) {
                uint32_t voff = (uint32_t)(((kc << 4) + ((bg & 1) << 3) + brow) * AQ_STRIDE
                                           + ((np << 4) + ((bg >> 1) << 3)) * 2);
                uint32_t rv[4];
                ldsm4t(rv, kb + VOFF + voff);
                mma_f16(O[2*np],   pf, rv[0], rv[1]);
                mma_f16(O[2*np+1], pf, rv[2], rv[3]);
            }
        }
    }

    float inv0 = 1.0f / l0, inv1 = 1.0f / l1;
    size_t row0g = qrow0 + wid * 16 + (lane >> 2);
    int colb = h * HDIM + ((lane & 3) << 1);
    #pragma unroll
    for (int n = 0; n < 8; n++) {
        int col = colb + n * 8;
        *(__half2*)(o16 + row0g * DDIM + col) =
            __floats2half2_rn(O[n][0] * inv0, O[n][1] * inv0);
        *(__half2*)(o16 + (row0g + 8) * DDIM + col) =
            __floats2half2_rn(O[n][2] * inv1, O[n][3] * inv1);
    }
}

extern "C" void kernel_launch(void* const* d_in, const int* in_sizes, int n_in,
                              void* d_out, int out_size) {
    const float* x      = (const float*)d_in[0];
    const float* ln1_g  = (const float*)d_in[1];
    const float* ln1_b  = (const float*)d_in[2];
    const float* ln2_g  = (const float*)d_in[3];
    const float* ln2_b  = (const float*)d_in[4];
    const float* w_qkv  = (const float*)d_in[5];
    const float* b_qkv  = (const float*)d_in[6];
    const float* w_o    = (const float*)d_in[7];
    const float* b_o    = (const float*)d_in[8];
    const float* w_fc1  = (const float*)d_in[9];
    const float* b_fc1  = (const float*)d_in[10];
    const float* w_fc2  = (const float*)d_in[11];
    const float* b_fc2  = (const float*)d_in[12];
    float* out = (float*)d_out;

    float* p_x1;
    __half *p_a16, *p_qv16, *p_h16, *p_wq, *p_wo, *p_w1, *p_w2;
    cudaGetSymbolAddress((void**)&p_x1,   g_x1);
    cudaGetSymbolAddress((void**)&p_a16,  g_a16);
    cudaGetSymbolAddress((void**)&p_qv16, g_qv16);
    cudaGetSymbolAddress((void**)&p_h16,  g_h16);
    cudaGetSymbolAddress((void**)&p_wq,   g_wq16);
    cudaGetSymbolAddress((void**)&p_wo,   g_wo16);
    cudaGetSymbolAddress((void**)&p_w1,   g_w116);
    cudaGetSymbolAddress((void**)&p_w2,   g_w216);

    cudaFuncSetAttribute(attn_tc, cudaFuncAttributeMaxDynamicSharedMemorySize, ATT_SMEM);
    cudaFuncSetAttribute(hmma_gemm<1>, cudaFuncAttributeMaxDynamicSharedMemorySize, GEMM_SMEM);
    cudaFuncSetAttribute(hmma_gemm<2>, cudaFuncAttributeMaxDynamicSharedMemorySize, GEMM_SMEM);
    cudaFuncSetAttribute(hmma_gemm<3>, cudaFuncAttributeMaxDynamicSharedMemorySize, GEMM_SMEM);

    static cudaStream_t s_side = nullptr;
    static cudaEvent_t ev_fork = nullptr, ev_ln = nullptr, ev_join = nullptr;
    if (s_side == nullptr) {
        cudaStreamCreateWithFlags(&s_side, cudaStreamNonBlocking);
        cudaEventCreateWithFlags(&ev_fork, cudaEventDisableTiming);
        cudaEventCreateWithFlags(&ev_ln,   cudaEventDisableTiming);
        cudaEventCreateWithFlags(&ev_join, cudaEventDisableTiming);
    }

    // fork: side stream does ln1 then wo/w1/w2 converts
    cudaEventRecord(ev_fork, (cudaStream_t)0);
    cudaStreamWaitEvent(s_side, ev_fork, 0);
    ln_h<<<BT, 256, 0, s_side>>>(x, ln1_g, ln1_b, p_a16);
    cudaEventRecord(ev_ln, s_side);
    wconv16<<<(DDIM * DDIM / 8 + 255) / 256, 256, 0, s_side>>>(w_o, p_wo, DDIM * DDIM / 8);
    wconv16<<<(4 * DDIM * DDIM / 8 + 255) / 256, 256, 0, s_side>>>(w_fc1, p_w1, 4 * DDIM * DDIM / 8);
    wconv16<<<(4 * DDIM * DDIM / 8 + 255) / 256, 256, 0, s_side>>>(w_fc2, p_w2, 4 * DDIM * DDIM / 8);
    cudaEventRecord(ev_join, s_side);

    // main stream
    wconv16<<<(3 * DDIM * DDIM / 8 + 255) / 256, 256>>>(w_qkv, p_wq, 3 * DDIM * DDIM / 8);
    cudaStreamWaitEvent((cudaStream_t)0, ev_ln, 0);
    hmma_gemm<3><<<dim3(3 * DDIM / 256, BT / 128), 256, GEMM_SMEM>>>(
        p_a16, p_wq, b_qkv, nullptr, nullptr, p_qv16, 3 * DDIM, DDIM);
    attn_tc<<<dim3(TTOK / 128, BB * NH), 256, ATT_SMEM>>>(p_qv16, p_a16);
    cudaStreamWaitEvent((cudaStream_t)0, ev_join, 0);
    hmma_gemm<2><<<dim3(DDIM / 256, BT / 128), 256, GEMM_SMEM>>>(
        p_a16, p_wo, b_o, x, p_x1, nullptr, DDIM, DDIM);
    ln_h<<<BT, 256>>>(p_x1, ln2_g, ln2_b, p_a16);
    hmma_gemm<1><<<dim3(4 * DDIM / 256, BT / 128), 256, GEMM_SMEM>>>(
        p_a16, p_w1, b_fc1, nullptr, nullptr, p_h16, 4 * DDIM, DDIM);
    hmma_gemm<2><<<dim3(DDIM / 256, BT / 128), 256, GEMM_SMEM>>>(
        p_h16, p_w2, b_fc2, p_x1, out, nullptr, DDIM, 4 * DDIM);
}

// round 14
// speedup vs baseline: 6.5341x; 1.0189x over previous
#include <cuda_runtime.h>
#include <cuda_fp16.h>
#include <math.h>
#include <stdint.h>

#define BB   2
#define TTOK 2048
#define DDIM 1024
#define NH   16
#define HDIM 64
#define BT   (BB*TTOK)   // 4096

// scratch (static device arrays)
__device__ float  g_x1 [BT * DDIM];
__device__ __half g_a16[BT * DDIM];
__device__ __half g_qv16[BT * 3 * DDIM];
__device__ __half g_h16[BT * 4 * DDIM];
__device__ __half g_wq16[3 * DDIM * DDIM];   // [K,N] fp16 weights
__device__ __half g_wo16[DDIM * DDIM];
__device__ __half g_w116[4 * DDIM * DDIM];
__device__ __half g_w216[4 * DDIM * DDIM];

__device__ __forceinline__ uint32_t s2u(const void* p) {
    uint32_t a;
    asm("{ .reg .u64 t; cvta.to.shared.u64 t, %1; cvt.u32.u64 %0, t; }" : "=r"(a) : "l"(p));
    return a;
}
__device__ __forceinline__ void cp16(uint32_t dst, const void* src) {
    asm volatile("cp.async.cg.shared.global [%0], [%1], 16;" :: "r"(dst), "l"(src));
}
#define CP_COMMIT() asm volatile("cp.async.commit_group;" ::: "memory")
#define CP_WAIT0()  asm volatile("cp.async.wait_group 0;" ::: "memory")

__device__ __forceinline__ void ldsm4(uint32_t* r, uint32_t addr) {
    asm volatile("ldmatrix.sync.aligned.m8n8.x4.shared.b16 {%0,%1,%2,%3}, [%4];"
                 : "=r"(r[0]), "=r"(r[1]), "=r"(r[2]), "=r"(r[3]) : "r"(addr));
}
__device__ __forceinline__ void ldsm4t(uint32_t* r, uint32_t addr) {
    asm volatile("ldmatrix.sync.aligned.m8n8.x4.trans.shared.b16 {%0,%1,%2,%3}, [%4];"
                 : "=r"(r[0]), "=r"(r[1]), "=r"(r[2]), "=r"(r[3]) : "r"(addr));
}
__device__ __forceinline__ void mma_f16(float* c, const uint32_t* a,
                                        uint32_t b0, uint32_t b1) {
    asm("mma.sync.aligned.m16n8k16.row.col.f32.f16.f16.f32 "
        "{%0,%1,%2,%3}, {%4,%5,%6,%7}, {%8,%9}, {%0,%1,%2,%3};"
        : "+f"(c[0]), "+f"(c[1]), "+f"(c[2]), "+f"(c[3])
        : "r"(a[0]), "r"(a[1]), "r"(a[2]), "r"(a[3]), "r"(b0), "r"(b1));
}
__device__ __forceinline__ uint32_t ex2_h2(float a0, float a1) {
    __half2 h = __floats2half2_rn(a0, a1);
    uint32_t r;
    asm("ex2.approx.f16x2 %0, %1;" : "=r"(r) : "r"(*(uint32_t*)&h));
    return r;
}

__device__ __forceinline__ float gelu_f(float x) {
    float x3 = x * x * x;
    return 0.5f * x * (1.0f + tanhf(0.7978845608028654f * (x + 0.044715f * x3)));
}

// streaming fp32 -> fp16 convert
__global__ void wconv16(const float* __restrict__ W, __half* __restrict__ O, int n8) {
    int idx = blockIdx.x * 256 + threadIdx.x;
    if (idx >= n8) return;
    size_t base = (size_t)idx * 8;
    float4 a = *(const float4*)(W + base);
    float4 b = *(const float4*)(W + base + 4);
    __half2 h[4];
    h[0] = __floats2half2_rn(a.x, a.y);
    h[1] = __floats2half2_rn(a.z, a.w);
    h[2] = __floats2half2_rn(b.x, b.y);
    h[3] = __floats2half2_rn(b.z, b.w);
    *(uint4*)(O + base) = *(uint4*)h;
}

// LayerNorm -> fp16
__global__ void ln_h(const float* __restrict__ x, const float* __restrict__ g,
                     const float* __restrict__ b, __half* __restrict__ o) {
    int row = blockIdx.x;
    int tid = threadIdx.x;
    float4 v = ((const float4*)(x + (size_t)row * DDIM))[tid];
    float s  = v.x + v.y + v.z + v.w;
    float ss = v.x*v.x + v.y*v.y + v.z*v.z + v.w*v.w;
    #pragma unroll
    for (int off = 16; off > 0; off >>= 1) {
        s  += __shfl_xor_sync(0xffffffffu, s,  off);
        ss += __shfl_xor_sync(0xffffffffu, ss, off);
    }
    __shared__ float rs[8], rss[8];
    int w = tid >> 5, ln = tid & 31;
    if (ln == 0) { rs[w] = s; rss[w] = ss; }
    __syncthreads();
    float tot = 0.f, tots = 0.f;
    #pragma unroll
    for (int i = 0; i < 8; i++) { tot += rs[i]; tots += rss[i]; }
    float mu  = tot * (1.0f / DDIM);
    float var = tots * (1.0f / DDIM) - mu * mu;
    float inv = rsqrtf(var + 1e-5f);
    float4 gg = ((const float4*)g)[tid];
    float4 bb = ((const float4*)b)[tid];
    float r0 = (v.x - mu) * inv * gg.x + bb.x;
    float r1 = (v.y - mu) * inv * gg.y + bb.y;
    float r2 = (v.z - mu) * inv * gg.z + bb.z;
    float r3 = (v.w - mu) * inv * gg.w + bb.w;
    size_t base = (size_t)row * DDIM + tid * 4;
    *(__half2*)(o + base)     = __floats2half2_rn(r0, r1);
    *(__half2*)(o + base + 2) = __floats2half2_rn(r2, r3);
}

// HMMA fp16 GEMM: C[M,N] = A[M,K] @ B[K,N] + bias   (B in [K,N] row-major)
// 128x256 block, 8 warps (2Mx4N), warp 64x64, K-chunk 128, 2-stage cp.async,
// manual fragment double-buffering across k16 steps.
#define AROWB  272
#define BROWB  528
#define OFF_A  0
#define OFF_B  (128*272)
#define STG    (128*272 + 128*528)       // 102400
#define GEMM_SMEM (2 * STG)              // 204800

__device__ __forceinline__ void load_stage(
    uint32_t st, const __half* __restrict__ A, const __half* __restrict__ B,
    int N, int K, int bm, int bn, int k0, int tid)
{
    #pragma unroll
    for (int j = 0; j < 8; j++) {
        int o = tid + (j << 8);
        int r = o >> 4, c = o & 15;
        cp16(st + OFF_A + (uint32_t)(r * AROWB + (c << 4)),
             A + (size_t)(bm + r) * K + k0 + (c << 3));
    }
    #pragma unroll
    for (int j = 0; j < 16; j++) {
        int o = tid + (j << 8);
        int r = o >> 5, c = o & 31;
        cp16(st + OFF_B + (uint32_t)(r * BROWB + (c << 4)),
             B + (size_t)(k0 + r) * N + bn + (c << 3));
    }
}

__device__ __forceinline__ void load_frags(
    uint32_t st, int ks, int wm, int wn, int arow, int acol, int bg, int brow,
    uint32_t aF[4][4], uint32_t bF[8][2])
{
    #pragma unroll
    for (int mi = 0; mi < 4; mi++) {
        uint32_t off = (uint32_t)(((wm << 6) + (mi << 4) + arow) * AROWB
                                  + ((ks << 4) + acol) * 2);
        ldsm4(aF[mi], st + OFF_A + off);
    }
    #pragma unroll
    for (int np = 0; np < 4; np++) {
        uint32_t off = (uint32_t)(((ks << 4) + ((bg & 1) << 3) + brow) * BROWB
                                  + ((wn << 6) + (np << 4) + ((bg >> 1) << 3)) * 2);
        uint32_t r[4];
        ldsm4t(r, st + OFF_B + off);
        bF[2*np][0]   = r[0]; bF[2*np][1]   = r[1];
        bF[2*np+1][0] = r[2]; bF[2*np+1][1] = r[3];
    }
}

template<int EPI>
__global__ void __launch_bounds__(256, 1) hmma_gemm(
    const __half* __restrict__ A, const __half* __restrict__ B,
    const float* __restrict__ bias, const float* __restrict__ res,
    float* __restrict__ Cf, __half* __restrict__ Ch, int N, int K)
{
    extern __shared__ __align__(1024) char smem[];
    uint32_t sb = s2u(smem);
    int tid = threadIdx.x, wid = tid >> 5, lane = tid & 31;
    int wm = wid & 1, wn = wid >> 1;
    int bm = blockIdx.y << 7, bn = blockIdx.x << 8;

    float acc[4][8][4];
    #pragma unroll
    for (int mi = 0; mi < 4; mi++)
        #pragma unroll
        for (int ni = 0; ni < 8; ni++)
            #pragma unroll
            for (int e = 0; e < 4; e++) acc[mi][ni][e] = 0.f;

    int nch = K >> 7;
    load_stage(sb, A, B, N, K, bm, bn, 0, tid);
    CP_COMMIT();

    int arow = lane & 15;
    int acol = (lane >> 4) << 3;
    int bg   = lane >> 3;
    int brow = lane & 7;

    uint32_t aF[2][4][4], bF[2][8][2];

    for (int i = 0; i < nch; i++) {
        CP_WAIT0();
        __syncthreads();
        if (i + 1 < nch) {
            load_stage(sb + (uint32_t)((i + 1) & 1) * STG,
                       A, B, N, K, bm, bn, (i + 1) << 7, tid);
            CP_COMMIT();
        }
        uint32_t st = sb + (uint32_t)(i & 1) * STG;
        load_frags(st, 0, wm, wn, arow, acol, bg, brow, aF[0], bF[0]);
        #pragma unroll
        for (int ks = 0; ks < 8; ks++) {
            int cur = ks & 1;
            if (ks < 7)
                load_frags(st, ks + 1, wm, wn, arow, acol, bg, brow,
                           aF[cur ^ 1], bF[cur ^ 1]);
            #pragma unroll
            for (int mi = 0; mi < 4; mi++)
                #pragma unroll
                for (int ni = 0; ni < 8; ni++)
                    mma_f16(acc[mi][ni], aF[cur][mi], bF[cur][ni][0], bF[cur][ni][1]);
        }
    }

    __syncthreads();
    #pragma unroll
    for (int mi = 0; mi < 4; mi++) {
        #pragma unroll
        for (int ni = 0; ni < 8; ni++) {
            int row0 = bm + (wm << 6) + (mi << 4) + (lane >> 2);
            int col  = bn + (wn << 6) + (ni << 3) + ((lane & 3) << 1);
            float b0 = __ldg(bias + col), b1 = __ldg(bias + col + 1);
            #pragma unroll
            for (int hf = 0; hf < 2; hf++) {
                int row = row0 + hf * 8;
                float v0 = acc[mi][ni][hf * 2 + 0] + b0;
                float v1 = acc[mi][ni][hf * 2 + 1] + b1;
                size_t oi = (size_t)row * N + col;
                if (EPI == 2) {
                    float2 rv = *(const float2*)(res + oi);
                    float2 ov; ov.x = v0 + rv.x; ov.y = v1 + rv.y;
                    *(float2*)(Cf + oi) = ov;
                } else {
                    float a0 = (EPI == 1) ? gelu_f(v0) : v0;
                    float a1 = (EPI == 1) ? gelu_f(v1) : v1;
                    *(__half2*)(Ch + oi) = __floats2half2_rn(a0, a1);
                }
            }
        }
    }
}

// fp16 flash attention: BQ=128 (8 warps x 16 rows), BK=64, hd=64
// 2 CTAs/SM (smem 55KB, regs capped at 128) for cross-CTA latency hiding.
#define AQ_STRIDE 144
#define SM_Q   0
#define SM_KV0 18432
#define KV_STG 18432
#define VOFF   9216
#define ATT_SMEM (SM_KV0 + 2 * KV_STG)   // 55296

__device__ __forceinline__ void att_load_kv(
    uint32_t base, const __half* __restrict__ qv, size_t kvrow0, int tid)
{
    const size_t TD3 = 3 * DDIM;
    #pragma unroll
    for (int i = 0; i < 4; i++) {
        int e = tid + (i << 8);
        int t = e >> 9;               // 0 K, 1 V
        int rem = e & 511;
        int r = rem >> 3, c = rem & 7;
        size_t off = (kvrow0 + r) * TD3 + (t ? 2 * DDIM : DDIM) + (c << 3);
        cp16(base + (t ? (uint32_t)VOFF : 0u) + r * AQ_STRIDE + (c << 4), qv + off);
    }
}

__global__ void __launch_bounds__(256, 2) attn_tc(
    const __half* __restrict__ qv, __half* __restrict__ o16)
{
    extern __shared__ __align__(1024) char smem[];
    uint32_t sb = s2u(smem);
    int qt = (int)gridDim.x - 1 - (int)blockIdx.x;
    int b  = blockIdx.y >> 4;
    int h  = blockIdx.y & 15;
    int tid = threadIdx.x, wid = tid >> 5, lane = tid & 31;
    const size_t TD3 = 3 * DDIM;
    size_t qrow0 = (size_t)b * TTOK + (size_t)qt * 128;
    const __half* qv_head = qv + h * HDIM;
    const float L2E = 1.4426950408889634f;

    #pragma unroll
    for (int i = 0; i < 4; i++) {
        int e = tid + (i << 8);
        int r = e >> 3, c = e & 7;
        cp16(sb + SM_Q + r * AQ_STRIDE + (c << 4),
             qv_head + (qrow0 + r) * TD3 + (c << 3));
    }
    att_load_kv(sb + SM_KV0, qv_head, (size_t)b * TTOK, tid);
    CP_COMMIT();

    uint32_t qf[4][4];
    float O[8][4];
    #pragma unroll
    for (int n = 0; n < 8; n++)
        #pragma unroll
        for (int e = 0; e < 4; e++) O[n][e] = 0.f;
    float m0 = -1e30f, m1 = -1e30f, l0 = 0.f, l1 = 0.f;

    int bg = lane >> 3, brow = lane & 7;
    int ntiles = 2 * qt + 2;
    bool qloaded = false;

    for (int j = 0; j < ntiles; j++) {
        CP_WAIT0();
        __syncthreads();
        if (j + 1 < ntiles) {
            att_load_kv(sb + SM_KV0 + (uint32_t)((j + 1) & 1) * KV_STG,
                        qv_head, (size_t)b * TTOK + (size_t)(j + 1) * 64, tid);
            CP_COMMIT();
        }
        if (!qloaded) {
            qloaded = true;
            #pragma unroll
            for (int kc = 0; kc < 4; kc++) {
                uint32_t aoff = (uint32_t)((wid * 16 + (lane & 15)) * AQ_STRIDE
                                           + ((kc << 4) + ((lane >> 4) << 3)) * 2);
                ldsm4(qf[kc], sb + SM_Q + aoff);
            }
        }

        uint32_t kb = sb + SM_KV0 + (uint32_t)(j & 1) * KV_STG;

        // ---- S = Q K^T ----
        float S[8][4];
        #pragma unroll
        for (int n = 0; n < 8; n++)
            #pragma unroll
            for (int e = 0; e < 4; e++) S[n][e] = 0.f;
        #pragma unroll
        for (int p = 0; p < 4; p++) {
            #pragma unroll
            for (int kc = 0; kc < 4; kc++) {
                uint32_t koff = (uint32_t)(((p << 4) + ((bg >> 1) << 3) + brow) * AQ_STRIDE
                                           + ((kc << 4) + ((bg & 1) << 3)) * 2);
                uint32_t rh[4];
                ldsm4(rh, kb + koff);
                mma_f16(S[2*p],   qf[kc], rh[0], rh[1]);
                mma_f16(S[2*p+1], qf[kc], rh[2], rh[3]);
            }
        }

        // ---- scale + causal mask ----
        int row0 = qt * 128 + wid * 16 + (lane >> 2);
        int row1 = row0 + 8;
        int cbase = j * 64 + ((lane & 3) << 1);
        bool need_mask = (j >= 2 * qt);
        #pragma unroll
        for (int n = 0; n < 8; n++) {
            #pragma unroll
            for (int e = 0; e < 4; e++) S[n][e] *= 0.125f;
            if (need_mask) {
                int c0 = cbase + n * 8;
                if (c0     > row0) S[n][0] = -1e30f;
                if (c0 + 1 > row0) S[n][1] = -1e30f;
                if (c0     > row1) S[n][2] = -1e30f;
                if (c0 + 1 > row1) S[n][3] = -1e30f;
            }
        }

        // ---- online max + alpha ----
        float mr0 = -1e30f, mr1 = -1e30f;
        #pragma unroll
        for (int n = 0; n < 8; n++) {
            mr0 = fmaxf(mr0, fmaxf(S[n][0], S[n][1]));
            mr1 = fmaxf(mr1, fmaxf(S[n][2], S[n][3]));
        }
        mr0 = fmaxf(mr0, __shfl_xor_sync(0xffffffffu, mr0, 1));
        mr0 = fmaxf(mr0, __shfl_xor_sync(0xffffffffu, mr0, 2));
        mr1 = fmaxf(mr1, __shfl_xor_sync(0xffffffffu, mr1, 1));
        mr1 = fmaxf(mr1, __shfl_xor_sync(0xffffffffu, mr1, 2));
        float mn0 = fmaxf(m0, mr0), mn1 = fmaxf(m1, mr1);
        float alpha0 = __expf(m0 - mn0), alpha1 = __expf(m1 - mn1);
        m0 = mn0; m1 = mn1;
        #pragma unroll
        for (int n = 0; n < 8; n++) {
            O[n][0] *= alpha0; O[n][1] *= alpha0;
            O[n][2] *= alpha1; O[n][3] *= alpha1;
        }

        // ---- P = exp(S - m) via ex2.f16x2, fused with PV MMA; row sums on the fly ----
        float sum0 = 0.f, sum1 = 0.f;
        #pragma unroll
        for (int kc = 0; kc < 4; kc++) {
            uint32_t pf[4];
            pf[0] = ex2_h2((S[2*kc][0]   - mn0) * L2E, (S[2*kc][1]   - mn0) * L2E);
            pf[1] = ex2_h2((S[2*kc][2]   - mn1) * L2E, (S[2*kc][3]   - mn1) * L2E);
            pf[2] = ex2_h2((S[2*kc+1][0] - mn0) * L2E, (S[2*kc+1][1] - mn0) * L2E);
            pf[3] = ex2_h2((S[2*kc+1][2] - mn1) * L2E, (S[2*kc+1][3] - mn1) * L2E);
            float2 f0 = __half22float2(*(__half2*)&pf[0]);
            float2 f1 = __half22float2(*(__half2*)&pf[1]);
            float2 f2 = __half22float2(*(__half2*)&pf[2]);
            float2 f3 = __half22float2(*(__half2*)&pf[3]);
            sum0 += f0.x + f0.y + f2.x + f2.y;
            sum1 += f1.x + f1.y + f3.x + f3.y;
            #pragma unroll
            for (int np = 0; np < 4; np++) {
                uint32_t voff = (uint32_t)(((kc << 4) + ((bg & 1) << 3) + brow) * AQ_STRIDE
                                           + ((np << 4) + ((bg >> 1) << 3)) * 2);
                uint32_t rv[4];
                ldsm4t(rv, kb + VOFF + voff);
                mma_f16(O[2*np],   pf, rv[0], rv[1]);
                mma_f16(O[2*np+1], pf, rv[2], rv[3]);
            }
        }
        sum0 += __shfl_xor_sync(0xffffffffu, sum0, 1);
        sum0 += __shfl_xor_sync(0xffffffffu, sum0, 2);
        sum1 += __shfl_xor_sync(0xffffffffu, sum1, 1);
        sum1 += __shfl_xor_sync(0xffffffffu, sum1, 2);
        l0 = l0 * alpha0 + sum0;
        l1 = l1 * alpha1 + sum1;
    }

    float inv0 = 1.0f / l0, inv1 = 1.0f / l1;
    size_t row0g = qrow0 + wid * 16 + (lane >> 2);
    int colb = h * HDIM + ((lane & 3) << 1);
    #pragma unroll
    for (int n = 0; n < 8; n++) {
        int col = colb + n * 8;
        *(__half2*)(o16 + row0g * DDIM + col) =
            __floats2half2_rn(O[n][0] * inv0, O[n][1] * inv0);
        *(__half2*)(o16 + (row0g + 8) * DDIM + col) =
            __floats2half2_rn(O[n][2] * inv1, O[n][3] * inv1);
    }
}

extern "C" void kernel_launch(void* const* d_in, const int* in_sizes, int n_in,
                              void* d_out, int out_size) {
    const float* x      = (const float*)d_in[0];
    const float* ln1_g  = (const float*)d_in[1];
    const float* ln1_b  = (const float*)d_in[2];
    const float* ln2_g  = (const float*)d_in[3];
    const float* ln2_b  = (const float*)d_in[4];
    const float* w_qkv  = (const float*)d_in[5];
    const float* b_qkv  = (const float*)d_in[6];
    const float* w_o    = (const float*)d_in[7];
    const float* b_o    = (const float*)d_in[8];
    const float* w_fc1  = (const float*)d_in[9];
    const float* b_fc1  = (const float*)d_in[10];
    const float* w_fc2  = (const float*)d_in[11];
    const float* b_fc2  = (const float*)d_in[12];
    float* out = (float*)d_out;

    float* p_x1;
    __half *p_a16, *p_qv16, *p_h16, *p_wq, *p_wo, *p_w1, *p_w2;
    cudaGetSymbolAddress((void**)&p_x1,   g_x1);
    cudaGetSymbolAddress((void**)&p_a16,  g_a16);
    cudaGetSymbolAddress((void**)&p_qv16, g_qv16);
    cudaGetSymbolAddress((void**)&p_h16,  g_h16);
    cudaGetSymbolAddress((void**)&p_wq,   g_wq16);
    cudaGetSymbolAddress((void**)&p_wo,   g_wo16);
    cudaGetSymbolAddress((void**)&p_w1,   g_w116);
    cudaGetSymbolAddress((void**)&p_w2,   g_w216);

    cudaFuncSetAttribute(attn_tc, cudaFuncAttributeMaxDynamicSharedMemorySize, ATT_SMEM);
    cudaFuncSetAttribute(hmma_gemm<1>, cudaFuncAttributeMaxDynamicSharedMemorySize, GEMM_SMEM);
    cudaFuncSetAttribute(hmma_gemm<2>, cudaFuncAttributeMaxDynamicSharedMemorySize, GEMM_SMEM);
    cudaFuncSetAttribute(hmma_gemm<3>, cudaFuncAttributeMaxDynamicSharedMemorySize, GEMM_SMEM);

    static cudaStream_t s_side = nullptr;
    static cudaEvent_t ev_fork = nullptr, ev_ln = nullptr, ev_join = nullptr;
    if (s_side == nullptr) {
        cudaStreamCreateWithFlags(&s_side, cudaStreamNonBlocking);
        cudaEventCreateWithFlags(&ev_fork, cudaEventDisableTiming);
        cudaEventCreateWithFlags(&ev_ln,   cudaEventDisableTiming);
        cudaEventCreateWithFlags(&ev_join, cudaEventDisableTiming);
    }

    // fork: side stream does ln1 then wo/w1/w2 converts
    cudaEventRecord(ev_fork, (cudaStream_t)0);
    cudaStreamWaitEvent(s_side, ev_fork, 0);
    ln_h<<<BT, 256, 0, s_side>>>(x, ln1_g, ln1_b, p_a16);
    cudaEventRecord(ev_ln, s_side);
    wconv16<<<(DDIM * DDIM / 8 + 255) / 256, 256, 0, s_side>>>(w_o, p_wo, DDIM * DDIM / 8);
    wconv16<<<(4 * DDIM * DDIM / 8 + 255) / 256, 256, 0, s_side>>>(w_fc1, p_w1, 4 * DDIM * DDIM / 8);
    wconv16<<<(4 * DDIM * DDIM / 8 + 255) / 256, 256, 0, s_side>>>(w_fc2, p_w2, 4 * DDIM * DDIM / 8);
    cudaEventRecord(ev_join, s_side);

    // main stream
    wconv16<<<(3 * DDIM * DDIM / 8 + 255) / 256, 256>>>(w_qkv, p_wq, 3 * DDIM * DDIM / 8);
    cudaStreamWaitEvent((cudaStream_t)0, ev_ln, 0);
    hmma_gemm<3><<<dim3(3 * DDIM / 256, BT / 128), 256, GEMM_SMEM>>>(
        p_a16, p_wq, b_qkv, nullptr, nullptr, p_qv16, 3 * DDIM, DDIM);
    attn_tc<<<dim3(TTOK / 128, BB * NH), 256, ATT_SMEM>>>(p_qv16, p_a16);
    cudaStreamWaitEvent((cudaStream_t)0, ev_join, 0);
    hmma_gemm<2><<<dim3(DDIM / 256, BT / 128), 256, GEMM_SMEM>>>(
        p_a16, p_wo, b_o, x, p_x1, nullptr, DDIM, DDIM);
    ln_h<<<BT, 256>>>(p_x1, ln2_g, ln2_b, p_a16);
    hmma_gemm<1><<<dim3(4 * DDIM / 256, BT / 128), 256, GEMM_SMEM>>>(
        p_a16, p_w1, b_fc1, nullptr, nullptr, p_h16, 4 * DDIM, DDIM);
    hmma_gemm<2><<<dim3(DDIM / 256, BT / 128), 256, GEMM_SMEM>>>(
        p_h16, p_w2, b_fc2, p_x1, out, nullptr, DDIM, 4 * DDIM);
}